// round 9
// baseline (speedup 1.0000x reference)
#include <cuda_runtime.h>
#include <cuda_bf16.h>
#include <math_constants.h>
#include <cstdint>

// Problem constants (fixed by the reference setup)
#define NN  50000
#define DD  512
#define HH  512
#define OC  256
#define EE  150000

// ---------------- scratch (no allocation allowed -> __device__ globals) ----------------
__device__ float g_hsrc[(size_t)NN * HH];   // GEMM outputs (layer1 512 / layer2 256 cols)
__device__ float g_asrc[NN];
__device__ float g_adst[NN];
__device__ float g_s[4][NN];                // per-layer, per-list softmax sums
__device__ float g_wa[2][DD];
__device__ float g_wb[2][DD];

// bf16 hi/lo intermediate activations (producer-split)
__device__ __nv_bfloat16 g_agghi[(size_t)NN * HH];
__device__ __nv_bfloat16 g_agglo[(size_t)NN * HH];
__device__ __nv_bfloat16 g_hmhi[(size_t)NN * HH];
__device__ __nv_bfloat16 g_hmlo[(size_t)NN * HH];

// CSR structures (built once per launch; shared by both layers)
__device__ int   g_rowptr[2][NN + 1];
__device__ int   g_pos[2][NN];              // histogram, then fill cursor
__device__ int   g_perm[2][EE];             // edge -> csr slot
__device__ int   g_csrc[2][EE];             // csr: source node per slot
__device__ float g_cw[2][EE];               // csr: exp(e) per slot (per layer)
__device__ int   g_bsum[2][128];
__device__ int   g_boff[2][128];

// pre-split weights, [K,N] fp32 layout -> bf16 hi/lo (same layout)
#define WO1 0
#define WO2 262144
#define WO3 524288
#define WO4 655360
#define WTOT 720896
__device__ __nv_bfloat16 g_whi[WTOT];
__device__ __nv_bfloat16 g_wlo[WTOT];

// ==================== weight bf16 hi/lo split (elementwise, float4) ====================
__global__ void wsplit_kernel(const float* __restrict__ W,
                              __nv_bfloat16* __restrict__ hi, __nv_bfloat16* __restrict__ lo,
                              int total4)
{
    int i = blockIdx.x * blockDim.x + threadIdx.x;
    if (i >= total4) return;
    float4 v = ((const float4*)W)[i];
    __nv_bfloat162 h0 = __floats2bfloat162_rn(v.x, v.y);
    float2 f0 = __bfloat1622float2(h0);
    __nv_bfloat162 l0 = __floats2bfloat162_rn(v.x - f0.x, v.y - f0.y);
    __nv_bfloat162 h1 = __floats2bfloat162_rn(v.z, v.w);
    float2 f1 = __bfloat1622float2(h1);
    __nv_bfloat162 l1 = __floats2bfloat162_rn(v.z - f1.x, v.w - f1.y);
    uint2 hh, ll;
    hh.x = reinterpret_cast<uint32_t&>(h0); hh.y = reinterpret_cast<uint32_t&>(h1);
    ll.x = reinterpret_cast<uint32_t&>(l0); ll.y = reinterpret_cast<uint32_t&>(l1);
    ((uint2*)hi)[i] = hh;
    ((uint2*)lo)[i] = ll;
}

// ==================== tensor-core GEMM (mma.sync, 3-term bf16 split) ====================
#define LDM4(r0,r1,r2,r3,addr) \
    asm volatile("ldmatrix.sync.aligned.m8n8.x4.shared.b16 {%0,%1,%2,%3}, [%4];" \
                 : "=r"(r0),"=r"(r1),"=r"(r2),"=r"(r3) : "r"(addr))
#define LDM4T(r0,r1,r2,r3,addr) \
    asm volatile("ldmatrix.sync.aligned.m8n8.x4.trans.shared.b16 {%0,%1,%2,%3}, [%4];" \
                 : "=r"(r0),"=r"(r1),"=r"(r2),"=r"(r3) : "r"(addr))
#define MMA16816(d, a, b) \
    asm volatile("mma.sync.aligned.m16n8k16.row.col.f32.bf16.bf16.f32 " \
                 "{%0,%1,%2,%3},{%4,%5,%6,%7},{%8,%9},{%0,%1,%2,%3};" \
                 : "+f"(d[0]),"+f"(d[1]),"+f"(d[2]),"+f"(d[3]) \
                 : "r"(a[0]),"r"(a[1]),"r"(a[2]),"r"(a[3]),"r"(b[0]),"r"(b[1]))

__device__ __forceinline__ uint32_t smem_u32(const void* p)
{
    return (uint32_t)__cvta_generic_to_shared(p);
}

__device__ __forceinline__ void split2(__nv_bfloat16* hp, __nv_bfloat16* lp, float x, float y)
{
    __nv_bfloat162 h = __floats2bfloat162_rn(x, y);
    float2 hf = __bfloat1622float2(h);
    __nv_bfloat162 l = __floats2bfloat162_rn(x - hf.x, y - hf.y);
    *(__nv_bfloat162*)hp = h;
    *(__nv_bfloat162*)lp = l;
}

// C = A @ B (+bias)(+relu). A either fp32 (split on the fly) or pre-split bf16 hi/lo.
// C either fp32 or pre-split bf16 hi/lo.
template<bool ASPLIT, bool BIAS, bool RELU, bool CSPLIT>
__global__ __launch_bounds__(256)
void mma_gemm_kernel(const float* __restrict__ A,
                     const __nv_bfloat16* __restrict__ Ahi,
                     const __nv_bfloat16* __restrict__ Alo,
                     const __nv_bfloat16* __restrict__ Bhi,
                     const __nv_bfloat16* __restrict__ Blo,
                     const float* __restrict__ bias,
                     float* __restrict__ C,
                     __nv_bfloat16* __restrict__ Chi,
                     __nv_bfloat16* __restrict__ Clo,
                     int M, int N, int K)
{
    const int BM = 128, BN = 128, BK = 32;
    const int APAD = 8, BPAD = 8;
    __shared__ __align__(16) __nv_bfloat16 sAhi[BM][BK + APAD];
    __shared__ __align__(16) __nv_bfloat16 sAlo[BM][BK + APAD];
    __shared__ __align__(16) __nv_bfloat16 sBhi[BK][BN + BPAD];
    __shared__ __align__(16) __nv_bfloat16 sBlo[BK][BN + BPAD];

    int tid = threadIdx.x;
    int lane = tid & 31;
    int w = tid >> 5;
    int wm = w & 3;
    int wn = w >> 2;

    int blockM = blockIdx.y * BM;
    int blockN = blockIdx.x * BN;

    // fp32-A mapping
    int aRow0 = tid >> 3;          // + 32*i
    int aCol  = (tid & 7) * 4;
    // split-A mapping: 128x32 bf16 = 512 uint4-groups; 2 per thread
    int sR[2], sC_[2];
    #pragma unroll
    for (int i = 0; i < 2; i++) {
        int g = tid + 256 * i;
        sR[i] = g >> 2;            // 0..127
        sC_[i] = (g & 3) * 8;      // 0,8,16,24
    }
    // B tile: 32x128 bf16 = 512 uint4-groups; 2 per thread
    int bR[2], bC[2];
    #pragma unroll
    for (int i = 0; i < 2; i++) {
        int g = tid + 256 * i;
        bR[i] = g >> 4;            // 0..31
        bC[i] = (g & 15) * 8;      // 0..120
    }

    const float4 z4 = make_float4(0.f, 0.f, 0.f, 0.f);
    const uint4 zu4 = make_uint4(0, 0, 0, 0);
    float4 pa[4];
    uint4 pah[2], pal[2];
    uint4 pbh[2], pbl[2];

    float acc[2][8][4];
    #pragma unroll
    for (int mt = 0; mt < 2; mt++)
        #pragma unroll
        for (int nt = 0; nt < 8; nt++)
            #pragma unroll
            for (int q = 0; q < 4; q++) acc[mt][nt][q] = 0.f;

    uint32_t baseAhi = smem_u32(&sAhi[0][0]);
    uint32_t baseAlo = smem_u32(&sAlo[0][0]);
    uint32_t baseBhi = smem_u32(&sBhi[0][0]);
    uint32_t baseBlo = smem_u32(&sBlo[0][0]);

    // ---- prologue: tile 0 ----
    if constexpr (ASPLIT) {
        #pragma unroll
        for (int i = 0; i < 2; i++) {
            int gr = blockM + sR[i];
            if (gr < M) {
                size_t go = (size_t)gr * K + sC_[i];
                pah[i] = *(const uint4*)(Ahi + go);
                pal[i] = *(const uint4*)(Alo + go);
            } else { pah[i] = zu4; pal[i] = zu4; }
        }
    } else {
        #pragma unroll
        for (int i = 0; i < 4; i++) {
            int r = blockM + aRow0 + 32 * i;
            pa[i] = (r < M) ? *(const float4*)(A + (size_t)r * K + aCol) : z4;
        }
    }
    #pragma unroll
    for (int i = 0; i < 2; i++) {
        size_t go = (size_t)bR[i] * N + blockN + bC[i];
        pbh[i] = *(const uint4*)(Bhi + go);
        pbl[i] = *(const uint4*)(Blo + go);
    }
    if constexpr (ASPLIT) {
        #pragma unroll
        for (int i = 0; i < 2; i++) {
            *(uint4*)&sAhi[sR[i]][sC_[i]] = pah[i];
            *(uint4*)&sAlo[sR[i]][sC_[i]] = pal[i];
        }
    } else {
        #pragma unroll
        for (int i = 0; i < 4; i++) {
            int r = aRow0 + 32 * i;
            split2(&sAhi[r][aCol],     &sAlo[r][aCol],     pa[i].x, pa[i].y);
            split2(&sAhi[r][aCol + 2], &sAlo[r][aCol + 2], pa[i].z, pa[i].w);
        }
    }
    #pragma unroll
    for (int i = 0; i < 2; i++) {
        *(uint4*)&sBhi[bR[i]][bC[i]] = pbh[i];
        *(uint4*)&sBlo[bR[i]][bC[i]] = pbl[i];
    }
    __syncthreads();

    int nT = K / BK;
    for (int kt = 0; kt < nT; kt++) {
        // prefetch next tile to registers
        if (kt + 1 < nT) {
            if constexpr (ASPLIT) {
                #pragma unroll
                for (int i = 0; i < 2; i++) {
                    int gr = blockM + sR[i];
                    if (gr < M) {
                        size_t go = (size_t)gr * K + (kt + 1) * BK + sC_[i];
                        pah[i] = *(const uint4*)(Ahi + go);
                        pal[i] = *(const uint4*)(Alo + go);
                    } else { pah[i] = zu4; pal[i] = zu4; }
                }
            } else {
                #pragma unroll
                for (int i = 0; i < 4; i++) {
                    int r = blockM + aRow0 + 32 * i;
                    pa[i] = (r < M) ? *(const float4*)(A + (size_t)r * K + (kt + 1) * BK + aCol) : z4;
                }
            }
            #pragma unroll
            for (int i = 0; i < 2; i++) {
                size_t go = (size_t)((kt + 1) * BK + bR[i]) * N + blockN + bC[i];
                pbh[i] = *(const uint4*)(Bhi + go);
                pbl[i] = *(const uint4*)(Blo + go);
            }
        }

        #pragma unroll
        for (int ks = 0; ks < 2; ks++) {
            uint32_t ah[2][4], al[2][4];
            #pragma unroll
            for (int mt = 0; mt < 2; mt++) {
                uint32_t off = (uint32_t)((wm * 32 + mt * 16 + (lane & 15)) * (BK + APAD)
                                          + (lane >> 4) * 8 + ks * 16) * 2u;
                LDM4(ah[mt][0], ah[mt][1], ah[mt][2], ah[mt][3], baseAhi + off);
                LDM4(al[mt][0], al[mt][1], al[mt][2], al[mt][3], baseAlo + off);
            }
            uint32_t bh[8][2], bl[8][2];
            #pragma unroll
            for (int p = 0; p < 4; p++) {
                uint32_t off = (uint32_t)((ks * 16 + (lane & 15)) * (BN + BPAD)
                                          + wn * 64 + p * 16 + ((lane & 16) >> 1)) * 2u;
                uint32_t r0, r1, r2, r3;
                LDM4T(r0, r1, r2, r3, baseBhi + off);
                bh[2 * p][0] = r0; bh[2 * p][1] = r1;
                bh[2 * p + 1][0] = r2; bh[2 * p + 1][1] = r3;
                LDM4T(r0, r1, r2, r3, baseBlo + off);
                bl[2 * p][0] = r0; bl[2 * p][1] = r1;
                bl[2 * p + 1][0] = r2; bl[2 * p + 1][1] = r3;
            }
            #pragma unroll
            for (int mt = 0; mt < 2; mt++)
                #pragma unroll
                for (int nt = 0; nt < 8; nt++) {
                    MMA16816(acc[mt][nt], ah[mt], bh[nt]);
                    MMA16816(acc[mt][nt], ah[mt], bl[nt]);
                    MMA16816(acc[mt][nt], al[mt], bh[nt]);
                }
        }
        __syncthreads();

        if (kt + 1 < nT) {
            if constexpr (ASPLIT) {
                #pragma unroll
                for (int i = 0; i < 2; i++) {
                    *(uint4*)&sAhi[sR[i]][sC_[i]] = pah[i];
                    *(uint4*)&sAlo[sR[i]][sC_[i]] = pal[i];
                }
            } else {
                #pragma unroll
                for (int i = 0; i < 4; i++) {
                    int r = aRow0 + 32 * i;
                    split2(&sAhi[r][aCol],     &sAlo[r][aCol],     pa[i].x, pa[i].y);
                    split2(&sAhi[r][aCol + 2], &sAlo[r][aCol + 2], pa[i].z, pa[i].w);
                }
            }
            #pragma unroll
            for (int i = 0; i < 2; i++) {
                *(uint4*)&sBhi[bR[i]][bC[i]] = pbh[i];
                *(uint4*)&sBlo[bR[i]][bC[i]] = pbl[i];
            }
            __syncthreads();
        }
    }

    // ---- epilogue ----
    #pragma unroll
    for (int mt = 0; mt < 2; mt++) {
        #pragma unroll
        for (int nt = 0; nt < 8; nt++) {
            int row = blockM + wm * 32 + mt * 16 + (lane >> 2);
            int col = blockN + wn * 64 + nt * 8 + (lane & 3) * 2;
            float2 v0 = make_float2(acc[mt][nt][0], acc[mt][nt][1]);
            float2 v1 = make_float2(acc[mt][nt][2], acc[mt][nt][3]);
            if (BIAS) {
                float2 bv = *(const float2*)(bias + col);
                v0.x += bv.x; v0.y += bv.y;
                v1.x += bv.x; v1.y += bv.y;
            }
            if (RELU) {
                v0.x = fmaxf(v0.x, 0.f); v0.y = fmaxf(v0.y, 0.f);
                v1.x = fmaxf(v1.x, 0.f); v1.y = fmaxf(v1.y, 0.f);
            }
            if constexpr (CSPLIT) {
                if (row < M)
                    split2(Chi + (size_t)row * N + col, Clo + (size_t)row * N + col, v0.x, v0.y);
                if (row + 8 < M)
                    split2(Chi + (size_t)(row + 8) * N + col, Clo + (size_t)(row + 8) * N + col, v1.x, v1.y);
            } else {
                if (row < M)     *(float2*)(C + (size_t)row * N + col) = v0;
                if (row + 8 < M) *(float2*)(C + (size_t)(row + 8) * N + col) = v1;
            }
        }
    }
}

// ---------------- GEMV kernels ----------------
__global__ void gemv_kernel(const float* __restrict__ A, const float* __restrict__ v,
                            float* __restrict__ out, int M, int K)
{
    int row = blockIdx.x * (blockDim.x >> 5) + (threadIdx.x >> 5);
    int lane = threadIdx.x & 31;
    if (row >= M) return;
    const float4* a4 = (const float4*)(A + (size_t)row * K);
    const float4* v4 = (const float4*)v;
    int K4 = K >> 2;
    float sum = 0.f;
    for (int k = lane; k < K4; k += 32) {
        float4 a = a4[k], b = v4[k];
        sum += a.x * b.x + a.y * b.y + a.z * b.z + a.w * b.w;
    }
    #pragma unroll
    for (int o = 16; o; o >>= 1) sum += __shfl_down_sync(0xffffffffu, sum, o);
    if (lane == 0) out[row] = sum;
}

// dual GEMV on fp32 A
__global__ void gemv2_kernel(const float* __restrict__ A,
                             const float* __restrict__ va, const float* __restrict__ vb,
                             float* __restrict__ oa, float* __restrict__ ob, int M, int K)
{
    int row = blockIdx.x * (blockDim.x >> 5) + (threadIdx.x >> 5);
    int lane = threadIdx.x & 31;
    if (row >= M) return;
    const float4* a4 = (const float4*)(A + (size_t)row * K);
    const float4* va4 = (const float4*)va;
    const float4* vb4 = (const float4*)vb;
    int K4 = K >> 2;
    float sa = 0.f, sb = 0.f;
    for (int k = lane; k < K4; k += 32) {
        float4 a = a4[k], u = va4[k], t = vb4[k];
        sa += a.x * u.x + a.y * u.y + a.z * u.z + a.w * u.w;
        sb += a.x * t.x + a.y * t.y + a.z * t.z + a.w * t.w;
    }
    #pragma unroll
    for (int o = 16; o; o >>= 1) {
        sa += __shfl_down_sync(0xffffffffu, sa, o);
        sb += __shfl_down_sync(0xffffffffu, sb, o);
    }
    if (lane == 0) { oa[row] = sa; ob[row] = sb; }
}

// dual GEMV on split bf16 A (a = hi + lo)
__global__ void gemv2s_kernel(const __nv_bfloat16* __restrict__ Ahi,
                              const __nv_bfloat16* __restrict__ Alo,
                              const float* __restrict__ va, const float* __restrict__ vb,
                              float* __restrict__ oa, float* __restrict__ ob, int M, int K)
{
    int row = blockIdx.x * (blockDim.x >> 5) + (threadIdx.x >> 5);
    int lane = threadIdx.x & 31;
    if (row >= M) return;
    const __nv_bfloat162* h2 = (const __nv_bfloat162*)(Ahi + (size_t)row * K);
    const __nv_bfloat162* l2 = (const __nv_bfloat162*)(Alo + (size_t)row * K);
    const float2* va2 = (const float2*)va;
    const float2* vb2 = (const float2*)vb;
    int K2 = K >> 1;
    float sa = 0.f, sb = 0.f;
    for (int k = lane; k < K2; k += 32) {
        float2 hf = __bfloat1622float2(h2[k]);
        float2 lf = __bfloat1622float2(l2[k]);
        float a0 = hf.x + lf.x, a1 = hf.y + lf.y;
        float2 u = va2[k], t = vb2[k];
        sa += a0 * u.x + a1 * u.y;
        sb += a0 * t.x + a1 * t.y;
    }
    #pragma unroll
    for (int o = 16; o; o >>= 1) {
        sa += __shfl_down_sync(0xffffffffu, sa, o);
        sb += __shfl_down_sync(0xffffffffu, sb, o);
    }
    if (lane == 0) { oa[row] = sa; ob[row] = sb; }
}

// ---------------- CSR build kernels ----------------
__global__ void zero_int_kernel(int* __restrict__ p, int n)
{
    int i = blockIdx.x * blockDim.x + threadIdx.x;
    if (i < n) p[i] = 0;
}
__global__ void zero_f_kernel(float* __restrict__ p, int n)
{
    int i = blockIdx.x * blockDim.x + threadIdx.x;
    if (i < n) p[i] = 0.f;
}
__global__ void hist_kernel(const int* __restrict__ dst, int* __restrict__ cnt, int E)
{
    int i = blockIdx.x * blockDim.x + threadIdx.x;
    if (i < E) atomicAdd(&cnt[dst[i]], 1);
}
__global__ void scan1_kernel(const int* __restrict__ cnt, int* __restrict__ rowptr,
                             int* __restrict__ bsum, int n)
{
    __shared__ int sm[512];
    int t = threadIdx.x;
    int idx = blockIdx.x * 512 + t;
    int v = (idx < n) ? cnt[idx] : 0;
    sm[t] = v;
    __syncthreads();
    for (int o = 1; o < 512; o <<= 1) {
        int a = (t >= o) ? sm[t - o] : 0;
        __syncthreads();
        sm[t] += a;
        __syncthreads();
    }
    if (idx < n) rowptr[idx + 1] = sm[t];
    if (t == 511) bsum[blockIdx.x] = sm[511];
}
__global__ void scan2_kernel(const int* __restrict__ bsum, int* __restrict__ boff, int nb)
{
    __shared__ int sm[128];
    int t = threadIdx.x;
    int v = (t < nb) ? bsum[t] : 0;
    sm[t] = v;
    __syncthreads();
    for (int o = 1; o < 128; o <<= 1) {
        int a = (t >= o) ? sm[t - o] : 0;
        __syncthreads();
        sm[t] += a;
        __syncthreads();
    }
    boff[t] = sm[t] - v;     // exclusive
}
__global__ void scan3_kernel(int* __restrict__ rowptr, const int* __restrict__ boff, int n)
{
    int idx = blockIdx.x * 512 + threadIdx.x;
    if (idx < n) rowptr[idx + 1] += boff[blockIdx.x];
    if (idx == 0) rowptr[0] = 0;
}
__global__ void copy_int_kernel(int* __restrict__ d, const int* __restrict__ s, int n)
{
    int i = blockIdx.x * blockDim.x + threadIdx.x;
    if (i < n) d[i] = s[i];
}
__global__ void fill_kernel(const int* __restrict__ src, const int* __restrict__ dst,
                            int* __restrict__ pos, int* __restrict__ perm,
                            int* __restrict__ csrc, int E)
{
    int i = blockIdx.x * blockDim.x + threadIdx.x;
    if (i >= E) return;
    int slot = atomicAdd(&pos[dst[i]], 1);
    perm[i] = slot;
    csrc[slot] = src[i];
}

// ---------------- edge alpha, both lists in one kernel ----------------
__global__ void alpha_both_kernel(const int* __restrict__ src1, const int* __restrict__ dst1,
                                  const int* __restrict__ src2, const int* __restrict__ dst2,
                                  const float* __restrict__ as_, const float* __restrict__ ad_,
                                  const int* __restrict__ perm, float* __restrict__ cw,
                                  float* __restrict__ s, int E)
{
    int i = blockIdx.x * blockDim.x + threadIdx.x;
    if (i >= 2 * E) return;
    int l = (i >= E) ? 1 : 0;
    int j = i - l * E;
    const int* sp = l ? src2 : src1;
    const int* dp = l ? dst2 : dst1;
    int sn = sp[j], dn = dp[j];
    float v = as_[sn] + ad_[dn];
    v = v > 0.f ? v : 0.2f * v;          // leaky_relu, slope 0.2
    float ex = expf(v);
    cw[(size_t)l * EE + perm[(size_t)l * EE + j]] = ex;
    atomicAdd(&s[(size_t)l * NN + dn], ex);
}

// ---------------- per-node CSR aggregation; writes bf16 hi/lo split output ----------------
template<int C>
__global__ void agg_kernel(const int* __restrict__ rp1, const int* __restrict__ cs1,
                           const float* __restrict__ cw1, const float* __restrict__ s1,
                           const int* __restrict__ rp2, const int* __restrict__ cs2,
                           const float* __restrict__ cw2, const float* __restrict__ s2,
                           const float* __restrict__ h, const float* __restrict__ bias,
                           __nv_bfloat16* __restrict__ ohi, __nv_bfloat16* __restrict__ olo)
{
    int n = blockIdx.x;
    int c = threadIdx.x * 4;
    float4 b4 = *(const float4*)(bias + c);
    float4 acc = make_float4(2.f * b4.x, 2.f * b4.y, 2.f * b4.z, 2.f * b4.w);

    int st = rp1[n], en = rp1[n + 1];
    float inv = 1.f / (s1[n] + 1e-16f);
    for (int j = st; j < en; j++) {
        float wv = cw1[j] * inv;
        float4 hv = *(const float4*)(h + (size_t)cs1[j] * C + c);
        acc.x += wv * hv.x; acc.y += wv * hv.y;
        acc.z += wv * hv.z; acc.w += wv * hv.w;
    }
    st = rp2[n]; en = rp2[n + 1];
    inv = 1.f / (s2[n] + 1e-16f);
    for (int j = st; j < en; j++) {
        float wv = cw2[j] * inv;
        float4 hv = *(const float4*)(h + (size_t)cs2[j] * C + c);
        acc.x += wv * hv.x; acc.y += wv * hv.y;
        acc.z += wv * hv.z; acc.w += wv * hv.w;
    }
    size_t idx = (size_t)n * C + c;
    split2(&ohi[idx],     &olo[idx],     acc.x, acc.y);
    split2(&ohi[idx + 2], &olo[idx + 2], acc.z, acc.w);
}

// ---------------- host orchestration ----------------
static void* symaddr(const void* s)
{
    void* p = nullptr;
    cudaGetSymbolAddress(&p, s);
    return p;
}

extern "C" void kernel_launch(void* const* d_in, const int* in_sizes, int n_in,
                              void* d_out, int out_size)
{
    (void)n_in; (void)out_size;
    const float* x   = (const float*)d_in[0];
    const int*   ei1 = (const int*)d_in[1];
    const int*   ei2 = (const int*)d_in[2];
    const float* W1s = (const float*)d_in[3];
    const float* W1d = (const float*)d_in[4];
    const float* a1s = (const float*)d_in[5];
    const float* a1d = (const float*)d_in[6];
    const float* b1  = (const float*)d_in[7];
    const float* Wl1 = (const float*)d_in[8];
    const float* bl1 = (const float*)d_in[9];
    const float* W2s = (const float*)d_in[10];
    const float* W2d = (const float*)d_in[11];
    const float* a2s = (const float*)d_in[12];
    const float* a2d = (const float*)d_in[13];
    const float* b2  = (const float*)d_in[14];
    const float* Wl2 = (const float*)d_in[15];
    const float* bl2 = (const float*)d_in[16];
    float* out = (float*)d_out;

    const int N = in_sizes[0] / DD;       // 50000
    const int E = in_sizes[1] / 2;        // 150000

    float* hsrc = (float*)symaddr(g_hsrc);
    float* asrc = (float*)symaddr(g_asrc);
    float* adst = (float*)symaddr(g_adst);
    float* sbuf = (float*)symaddr(g_s);          // [4][NN]
    float* wa   = (float*)symaddr(g_wa);         // [2][DD]
    float* wb   = (float*)symaddr(g_wb);         // [2][DD]
    int* rowptr = (int*)symaddr(g_rowptr);
    int* pos    = (int*)symaddr(g_pos);
    int* perm   = (int*)symaddr(g_perm);
    int* csrc   = (int*)symaddr(g_csrc);
    float* cw   = (float*)symaddr(g_cw);
    int* bsum   = (int*)symaddr(g_bsum);
    int* boff   = (int*)symaddr(g_boff);
    __nv_bfloat16* whi   = (__nv_bfloat16*)symaddr(g_whi);
    __nv_bfloat16* wlo   = (__nv_bfloat16*)symaddr(g_wlo);
    __nv_bfloat16* agghi = (__nv_bfloat16*)symaddr(g_agghi);
    __nv_bfloat16* agglo = (__nv_bfloat16*)symaddr(g_agglo);
    __nv_bfloat16* hmhi  = (__nv_bfloat16*)symaddr(g_hmhi);
    __nv_bfloat16* hmlo  = (__nv_bfloat16*)symaddr(g_hmlo);

    const int NB = (NN + 511) / 512;
    const int* srcp1 = ei1;            const int* dstp1 = ei1 + E;
    const int* srcp2 = ei2;            const int* dstp2 = ei2 + E;

    static cudaStream_t sB = nullptr, sC = nullptr;
    static cudaEvent_t ev0, evB, evC1, ev1, evC2;
    if (!sB) {
        cudaStreamCreateWithFlags(&sB, cudaStreamNonBlocking);
        cudaStreamCreateWithFlags(&sC, cudaStreamNonBlocking);
        cudaEventCreateWithFlags(&ev0, cudaEventDisableTiming);
        cudaEventCreateWithFlags(&evB, cudaEventDisableTiming);
        cudaEventCreateWithFlags(&evC1, cudaEventDisableTiming);
        cudaEventCreateWithFlags(&ev1, cudaEventDisableTiming);
        cudaEventCreateWithFlags(&evC2, cudaEventDisableTiming);
    }

    dim3 gH(HH / 128, (N + 127) / 128);
    dim3 gO(OC / 128, (N + 127) / 128);

    // ===== fork =====
    cudaEventRecord(ev0, 0);
    cudaStreamWaitEvent(sB, ev0, 0);
    cudaStreamWaitEvent(sC, ev0, 0);

    // launches 0..4 (so GEMM1 is submission #5 -> ncu -s 5 profiles it)
    wsplit_kernel<<<(DD * HH / 4 + 255) / 256, 256>>>(W1s, whi + WO1, wlo + WO1, DD * HH / 4);          // 0 (default)
    wsplit_kernel<<<(HH * HH / 4 + 255) / 256, 256, 0, sB>>>(Wl1, whi + WO2, wlo + WO2, HH * HH / 4);   // 1
    wsplit_kernel<<<(HH * OC / 4 + 255) / 256, 256, 0, sB>>>(W2s, whi + WO3, wlo + WO3, HH * OC / 4);   // 2
    wsplit_kernel<<<(OC * OC / 4 + 255) / 256, 256, 0, sB>>>(Wl2, whi + WO4, wlo + WO4, OC * OC / 4);   // 3
    gemv_kernel<<<(HH + 7) / 8, 256, 0, sB>>>(W2s, a2s, wa + DD, HH, OC);                               // 4

    // 5: GEMM1 = x @ W1s -> hsrc (fp32 A path)
    mma_gemm_kernel<false, false, false, false><<<gH, 256>>>(
        x, nullptr, nullptr, whi + WO1, wlo + WO1, nullptr, hsrc, nullptr, nullptr, N, HH, DD);

    // ----- stream B: rest of off-chain setup -----
    gemv_kernel<<<(HH + 7) / 8, 256, 0, sB>>>(W2d, a2d, wb + DD, HH, OC);
    zero_f_kernel<<<(4 * NN + 255) / 256, 256, 0, sB>>>(sbuf, 4 * NN);
    zero_int_kernel<<<(2 * NN + 255) / 256, 256, 0, sB>>>(pos, 2 * NN);
    for (int l = 0; l < 2; l++) {
        const int* dstp = l ? dstp2 : dstp1;
        const int* srcp = l ? srcp2 : srcp1;
        int* cnt_l = pos + l * NN;
        int* rp_l  = rowptr + l * (NN + 1);
        hist_kernel<<<(E + 255) / 256, 256, 0, sB>>>(dstp, cnt_l, E);
        scan1_kernel<<<NB, 512, 0, sB>>>(cnt_l, rp_l, bsum + l * 128, N);
        scan2_kernel<<<1, 128, 0, sB>>>(bsum + l * 128, boff + l * 128, NB);
        scan3_kernel<<<NB, 512, 0, sB>>>(rp_l, boff + l * 128, N);
        copy_int_kernel<<<(NN + 255) / 256, 256, 0, sB>>>(cnt_l, rp_l, N);
        fill_kernel<<<(E + 255) / 256, 256, 0, sB>>>(srcp, dstp, cnt_l, perm + l * EE, csrc + l * EE, E);
    }
    cudaEventRecord(evB, sB);

    // ----- stream C: L1 weight gemvs + node alphas + edge alphas (all overlap GEMM1) -----
    gemv_kernel<<<(DD + 7) / 8, 256, 0, sC>>>(W1s, a1s, wa, DD, HH);
    gemv_kernel<<<(DD + 7) / 8, 256, 0, sC>>>(W1d, a1d, wb, DD, HH);
    gemv2_kernel<<<(N + 7) / 8, 256, 0, sC>>>(x, wa, wb, asrc, adst, N, DD);
    cudaStreamWaitEvent(sC, evB, 0);
    alpha_both_kernel<<<(2 * E + 255) / 256, 256, 0, sC>>>(srcp1, dstp1, srcp2, dstp2,
                                                           asrc, adst, perm, cw, sbuf, E);
    cudaEventRecord(evC1, sC);

    // ----- default stream: critical chain -----
    cudaStreamWaitEvent(0, evC1, 0);
    agg_kernel<HH><<<N, HH / 4>>>(rowptr, csrc, cw, sbuf,
                                  rowptr + (NN + 1), csrc + EE, cw + EE, sbuf + NN,
                                  hsrc, b1, agghi, agglo);
    // lin1: A = agg (split), C = hmid (split), bias+relu
    mma_gemm_kernel<true, true, true, true><<<gH, 256>>>(
        nullptr, agghi, agglo, whi + WO2, wlo + WO2, bl1, nullptr, hmhi, hmlo, N, HH, HH);

    // fork: layer-2 node/edge alphas overlap GEMM2
    cudaEventRecord(ev1, 0);
    cudaStreamWaitEvent(sC, ev1, 0);
    gemv2s_kernel<<<(N + 7) / 8, 256, 0, sC>>>(hmhi, hmlo, wa + DD, wb + DD, asrc, adst, N, HH);
    alpha_both_kernel<<<(2 * E + 255) / 256, 256, 0, sC>>>(srcp1, dstp1, srcp2, dstp2,
                                                           asrc, adst, perm, cw, sbuf + 2 * NN, E);
    cudaEventRecord(evC2, sC);

    // GEMM2: A = hmid (split) -> hsrc fp32
    mma_gemm_kernel<true, false, false, false><<<gO, 256>>>(
        nullptr, hmhi, hmlo, whi + WO3, wlo + WO3, nullptr, hsrc, nullptr, nullptr, N, OC, HH);

    cudaStreamWaitEvent(0, evC2, 0);
    agg_kernel<OC><<<N, OC / 4>>>(rowptr, csrc, cw, sbuf + 2 * NN,
                                  rowptr + (NN + 1), csrc + EE, cw + EE, sbuf + 3 * NN,
                                  hsrc, b2, agghi, agglo);
    // lin2: A = agg2 (split) -> out fp32, +bias
    mma_gemm_kernel<true, true, false, false><<<gO, 256>>>(
        nullptr, agghi, agglo, whi + WO4, wlo + WO4, bl2, out, nullptr, nullptr, N, OC, OC);
}

// round 12
// speedup vs baseline: 1.5619x; 1.5619x over previous
#include <cuda_runtime.h>
#include <cuda_bf16.h>
#include <math_constants.h>
#include <cstdint>

// Problem constants (fixed by the reference setup)
#define NN  50000
#define DD  512
#define HH  512
#define OC  256
#define EE  150000

// ---------------- scratch (no allocation allowed -> __device__ globals) ----------------
__device__ float g_hsrc[(size_t)NN * HH];   // layer1: [N,512]; layer2 reuse: [N,256]
__device__ float g_agg [(size_t)NN * HH];   // conv accumulator
__device__ float g_hmid[(size_t)NN * HH];   // after lin1
__device__ float g_asrc[NN];
__device__ float g_adst[NN];
__device__ float g_s[4][NN];                // per-layer, per-list softmax sums
__device__ float g_wa[2][DD];
__device__ float g_wb[2][DD];

// CSR structures (built once per launch; shared by both layers)
__device__ int   g_rowptr[2][NN + 1];
__device__ int   g_pos[2][NN];              // histogram, then fill cursor
__device__ int   g_perm[2][EE];             // edge -> csr slot
__device__ int   g_csrc[2][EE];             // csr: source node per slot
__device__ float g_cw[2][EE];               // csr: exp(e) per slot (per layer)
__device__ int   g_bsum[2][128];
__device__ int   g_boff[2][128];

// pre-split weights, [K,N] fp32 layout -> bf16 hi/lo (same layout)
#define WO1 0
#define WO2 262144
#define WO3 524288
#define WO4 655360
#define WTOT 720896
__device__ __nv_bfloat16 g_whi[WTOT];
__device__ __nv_bfloat16 g_wlo[WTOT];

// ==================== weight bf16 hi/lo split (elementwise, float4) ====================
__global__ void wsplit_kernel(const float* __restrict__ W,
                              __nv_bfloat16* __restrict__ hi, __nv_bfloat16* __restrict__ lo,
                              int total4)
{
    int i = blockIdx.x * blockDim.x + threadIdx.x;
    if (i >= total4) return;
    float4 v = ((const float4*)W)[i];
    __nv_bfloat162 h0 = __floats2bfloat162_rn(v.x, v.y);
    float2 f0 = __bfloat1622float2(h0);
    __nv_bfloat162 l0 = __floats2bfloat162_rn(v.x - f0.x, v.y - f0.y);
    __nv_bfloat162 h1 = __floats2bfloat162_rn(v.z, v.w);
    float2 f1 = __bfloat1622float2(h1);
    __nv_bfloat162 l1 = __floats2bfloat162_rn(v.z - f1.x, v.w - f1.y);
    uint2 hh, ll;
    hh.x = reinterpret_cast<uint32_t&>(h0); hh.y = reinterpret_cast<uint32_t&>(h1);
    ll.x = reinterpret_cast<uint32_t&>(l0); ll.y = reinterpret_cast<uint32_t&>(l1);
    ((uint2*)hi)[i] = hh;
    ((uint2*)lo)[i] = ll;
}

// ==================== tensor-core GEMM (mma.sync, 3-term bf16 split) ====================
#define LDM4(r0,r1,r2,r3,addr) \
    asm volatile("ldmatrix.sync.aligned.m8n8.x4.shared.b16 {%0,%1,%2,%3}, [%4];" \
                 : "=r"(r0),"=r"(r1),"=r"(r2),"=r"(r3) : "r"(addr))
#define LDM4T(r0,r1,r2,r3,addr) \
    asm volatile("ldmatrix.sync.aligned.m8n8.x4.trans.shared.b16 {%0,%1,%2,%3}, [%4];" \
                 : "=r"(r0),"=r"(r1),"=r"(r2),"=r"(r3) : "r"(addr))
#define MMA16816(d, a, b) \
    asm volatile("mma.sync.aligned.m16n8k16.row.col.f32.bf16.bf16.f32 " \
                 "{%0,%1,%2,%3},{%4,%5,%6,%7},{%8,%9},{%0,%1,%2,%3};" \
                 : "+f"(d[0]),"+f"(d[1]),"+f"(d[2]),"+f"(d[3]) \
                 : "r"(a[0]),"r"(a[1]),"r"(a[2]),"r"(a[3]),"r"(b[0]),"r"(b[1]))

__device__ __forceinline__ uint32_t smem_u32(const void* p)
{
    return (uint32_t)__cvta_generic_to_shared(p);
}

__device__ __forceinline__ void split2(__nv_bfloat16* hp, __nv_bfloat16* lp, float x, float y)
{
    __nv_bfloat162 h = __floats2bfloat162_rn(x, y);
    float2 hf = __bfloat1622float2(h);
    __nv_bfloat162 l = __floats2bfloat162_rn(x - hf.x, y - hf.y);
    *(__nv_bfloat162*)hp = h;
    *(__nv_bfloat162*)lp = l;
}

// C = A[MxK](fp32, split on the fly) @ B[KxN](pre-split bf16 hi/lo) (+bias)(+relu)
template<bool BIAS, bool RELU>
__global__ __launch_bounds__(256)
void mma_gemm_kernel(const float* __restrict__ A,
                     const __nv_bfloat16* __restrict__ Bhi,
                     const __nv_bfloat16* __restrict__ Blo,
                     const float* __restrict__ bias, float* __restrict__ C,
                     int M, int N, int K)
{
    const int BM = 128, BN = 128, BK = 32;
    const int APAD = 8, BPAD = 8;
    __shared__ __align__(16) __nv_bfloat16 sAhi[BM][BK + APAD];
    __shared__ __align__(16) __nv_bfloat16 sAlo[BM][BK + APAD];
    __shared__ __align__(16) __nv_bfloat16 sBhi[BK][BN + BPAD];
    __shared__ __align__(16) __nv_bfloat16 sBlo[BK][BN + BPAD];

    int tid = threadIdx.x;
    int lane = tid & 31;
    int w = tid >> 5;
    int wm = w & 3;
    int wn = w >> 2;

    int blockM = blockIdx.y * BM;
    int blockN = blockIdx.x * BN;

    int aRow0 = tid >> 3;          // + 32*i
    int aCol  = (tid & 7) * 4;
    // B tile: 32 rows x 128 cols = 512 uint4-groups of 8 bf16; 2 groups per thread
    int bR[2], bC[2];
    #pragma unroll
    for (int i = 0; i < 2; i++) {
        int g = tid + 256 * i;
        bR[i] = g >> 4;            // 0..31
        bC[i] = (g & 15) * 8;      // 0..120
    }

    const float4 z4 = make_float4(0.f, 0.f, 0.f, 0.f);
    float4 pa[4];
    uint4 pbh[2], pbl[2];

    float acc[2][8][4];
    #pragma unroll
    for (int mt = 0; mt < 2; mt++)
        #pragma unroll
        for (int nt = 0; nt < 8; nt++)
            #pragma unroll
            for (int q = 0; q < 4; q++) acc[mt][nt][q] = 0.f;

    uint32_t baseAhi = smem_u32(&sAhi[0][0]);
    uint32_t baseAlo = smem_u32(&sAlo[0][0]);
    uint32_t baseBhi = smem_u32(&sBhi[0][0]);
    uint32_t baseBlo = smem_u32(&sBlo[0][0]);

    // prologue: tile 0
    #pragma unroll
    for (int i = 0; i < 4; i++) {
        int r = blockM + aRow0 + 32 * i;
        pa[i] = (r < M) ? *(const float4*)(A + (size_t)r * K + aCol) : z4;
    }
    #pragma unroll
    for (int i = 0; i < 2; i++) {
        size_t go = (size_t)bR[i] * N + blockN + bC[i];
        pbh[i] = *(const uint4*)(Bhi + go);
        pbl[i] = *(const uint4*)(Blo + go);
    }
    #pragma unroll
    for (int i = 0; i < 4; i++) {
        int r = aRow0 + 32 * i;
        split2(&sAhi[r][aCol],     &sAlo[r][aCol],     pa[i].x, pa[i].y);
        split2(&sAhi[r][aCol + 2], &sAlo[r][aCol + 2], pa[i].z, pa[i].w);
    }
    #pragma unroll
    for (int i = 0; i < 2; i++) {
        *(uint4*)&sBhi[bR[i]][bC[i]] = pbh[i];
        *(uint4*)&sBlo[bR[i]][bC[i]] = pbl[i];
    }
    __syncthreads();

    int nT = K / BK;
    for (int kt = 0; kt < nT; kt++) {
        // prefetch next tile to registers
        if (kt + 1 < nT) {
            #pragma unroll
            for (int i = 0; i < 4; i++) {
                int r = blockM + aRow0 + 32 * i;
                pa[i] = (r < M) ? *(const float4*)(A + (size_t)r * K + (kt + 1) * BK + aCol) : z4;
            }
            #pragma unroll
            for (int i = 0; i < 2; i++) {
                size_t go = (size_t)((kt + 1) * BK + bR[i]) * N + blockN + bC[i];
                pbh[i] = *(const uint4*)(Bhi + go);
                pbl[i] = *(const uint4*)(Blo + go);
            }
        }

        #pragma unroll
        for (int ks = 0; ks < 2; ks++) {
            uint32_t ah[2][4], al[2][4];
            #pragma unroll
            for (int mt = 0; mt < 2; mt++) {
                uint32_t off = (uint32_t)((wm * 32 + mt * 16 + (lane & 15)) * (BK + APAD)
                                          + (lane >> 4) * 8 + ks * 16) * 2u;
                LDM4(ah[mt][0], ah[mt][1], ah[mt][2], ah[mt][3], baseAhi + off);
                LDM4(al[mt][0], al[mt][1], al[mt][2], al[mt][3], baseAlo + off);
            }
            uint32_t bh[8][2], bl[8][2];
            #pragma unroll
            for (int p = 0; p < 4; p++) {
                uint32_t off = (uint32_t)((ks * 16 + (lane & 15)) * (BN + BPAD)
                                          + wn * 64 + p * 16 + ((lane & 16) >> 1)) * 2u;
                uint32_t r0, r1, r2, r3;
                LDM4T(r0, r1, r2, r3, baseBhi + off);
                bh[2 * p][0] = r0; bh[2 * p][1] = r1;
                bh[2 * p + 1][0] = r2; bh[2 * p + 1][1] = r3;
                LDM4T(r0, r1, r2, r3, baseBlo + off);
                bl[2 * p][0] = r0; bl[2 * p][1] = r1;
                bl[2 * p + 1][0] = r2; bl[2 * p + 1][1] = r3;
            }
            #pragma unroll
            for (int mt = 0; mt < 2; mt++)
                #pragma unroll
                for (int nt = 0; nt < 8; nt++) {
                    MMA16816(acc[mt][nt], ah[mt], bh[nt]);
                    MMA16816(acc[mt][nt], ah[mt], bl[nt]);
                    MMA16816(acc[mt][nt], al[mt], bh[nt]);
                }
        }
        __syncthreads();

        if (kt + 1 < nT) {
            #pragma unroll
            for (int i = 0; i < 4; i++) {
                int r = aRow0 + 32 * i;
                split2(&sAhi[r][aCol],     &sAlo[r][aCol],     pa[i].x, pa[i].y);
                split2(&sAhi[r][aCol + 2], &sAlo[r][aCol + 2], pa[i].z, pa[i].w);
            }
            #pragma unroll
            for (int i = 0; i < 2; i++) {
                *(uint4*)&sBhi[bR[i]][bC[i]] = pbh[i];
                *(uint4*)&sBlo[bR[i]][bC[i]] = pbl[i];
            }
            __syncthreads();
        }
    }

    // epilogue
    #pragma unroll
    for (int mt = 0; mt < 2; mt++) {
        #pragma unroll
        for (int nt = 0; nt < 8; nt++) {
            int row = blockM + wm * 32 + mt * 16 + (lane >> 2);
            int col = blockN + wn * 64 + nt * 8 + (lane & 3) * 2;
            float2 v0 = make_float2(acc[mt][nt][0], acc[mt][nt][1]);
            float2 v1 = make_float2(acc[mt][nt][2], acc[mt][nt][3]);
            if (BIAS) {
                float2 bv = *(const float2*)(bias + col);
                v0.x += bv.x; v0.y += bv.y;
                v1.x += bv.x; v1.y += bv.y;
            }
            if (RELU) {
                v0.x = fmaxf(v0.x, 0.f); v0.y = fmaxf(v0.y, 0.f);
                v1.x = fmaxf(v1.x, 0.f); v1.y = fmaxf(v1.y, 0.f);
            }
            if (row < M)     *(float2*)(C + (size_t)row * N + col) = v0;
            if (row + 8 < M) *(float2*)(C + (size_t)(row + 8) * N + col) = v1;
        }
    }
}

// ---------------- GEMV kernels ----------------
__global__ void gemv_kernel(const float* __restrict__ A, const float* __restrict__ v,
                            float* __restrict__ out, int M, int K)
{
    int row = blockIdx.x * (blockDim.x >> 5) + (threadIdx.x >> 5);
    int lane = threadIdx.x & 31;
    if (row >= M) return;
    const float4* a4 = (const float4*)(A + (size_t)row * K);
    const float4* v4 = (const float4*)v;
    int K4 = K >> 2;
    float sum = 0.f;
    for (int k = lane; k < K4; k += 32) {
        float4 a = a4[k], b = v4[k];
        sum += a.x * b.x + a.y * b.y + a.z * b.z + a.w * b.w;
    }
    #pragma unroll
    for (int o = 16; o; o >>= 1) sum += __shfl_down_sync(0xffffffffu, sum, o);
    if (lane == 0) out[row] = sum;
}

__global__ void gemv2_kernel(const float* __restrict__ A,
                             const float* __restrict__ va, const float* __restrict__ vb,
                             float* __restrict__ oa, float* __restrict__ ob, int M, int K)
{
    int row = blockIdx.x * (blockDim.x >> 5) + (threadIdx.x >> 5);
    int lane = threadIdx.x & 31;
    if (row >= M) return;
    const float4* a4 = (const float4*)(A + (size_t)row * K);
    const float4* va4 = (const float4*)va;
    const float4* vb4 = (const float4*)vb;
    int K4 = K >> 2;
    float sa = 0.f, sb = 0.f;
    for (int k = lane; k < K4; k += 32) {
        float4 a = a4[k], u = va4[k], t = vb4[k];
        sa += a.x * u.x + a.y * u.y + a.z * u.z + a.w * u.w;
        sb += a.x * t.x + a.y * t.y + a.z * t.z + a.w * t.w;
    }
    #pragma unroll
    for (int o = 16; o; o >>= 1) {
        sa += __shfl_down_sync(0xffffffffu, sa, o);
        sb += __shfl_down_sync(0xffffffffu, sb, o);
    }
    if (lane == 0) { oa[row] = sa; ob[row] = sb; }
}

// ---------------- CSR build kernels ----------------
__global__ void zero_int_kernel(int* __restrict__ p, int n)
{
    int i = blockIdx.x * blockDim.x + threadIdx.x;
    if (i < n) p[i] = 0;
}
__global__ void zero_f_kernel(float* __restrict__ p, int n)
{
    int i = blockIdx.x * blockDim.x + threadIdx.x;
    if (i < n) p[i] = 0.f;
}
__global__ void hist_kernel(const int* __restrict__ dst, int* __restrict__ cnt, int E)
{
    int i = blockIdx.x * blockDim.x + threadIdx.x;
    if (i < E) atomicAdd(&cnt[dst[i]], 1);
}
__global__ void scan1_kernel(const int* __restrict__ cnt, int* __restrict__ rowptr,
                             int* __restrict__ bsum, int n)
{
    __shared__ int sm[512];
    int t = threadIdx.x;
    int idx = blockIdx.x * 512 + t;
    int v = (idx < n) ? cnt[idx] : 0;
    sm[t] = v;
    __syncthreads();
    for (int o = 1; o < 512; o <<= 1) {
        int a = (t >= o) ? sm[t - o] : 0;
        __syncthreads();
        sm[t] += a;
        __syncthreads();
    }
    if (idx < n) rowptr[idx + 1] = sm[t];
    if (t == 511) bsum[blockIdx.x] = sm[511];
}
__global__ void scan2_kernel(const int* __restrict__ bsum, int* __restrict__ boff, int nb)
{
    __shared__ int sm[128];
    int t = threadIdx.x;
    int v = (t < nb) ? bsum[t] : 0;
    sm[t] = v;
    __syncthreads();
    for (int o = 1; o < 128; o <<= 1) {
        int a = (t >= o) ? sm[t - o] : 0;
        __syncthreads();
        sm[t] += a;
        __syncthreads();
    }
    boff[t] = sm[t] - v;     // exclusive
}
__global__ void scan3_kernel(int* __restrict__ rowptr, const int* __restrict__ boff, int n)
{
    int idx = blockIdx.x * 512 + threadIdx.x;
    if (idx < n) rowptr[idx + 1] += boff[blockIdx.x];
    if (idx == 0) rowptr[0] = 0;
}
__global__ void copy_int_kernel(int* __restrict__ d, const int* __restrict__ s, int n)
{
    int i = blockIdx.x * blockDim.x + threadIdx.x;
    if (i < n) d[i] = s[i];
}
__global__ void fill_kernel(const int* __restrict__ src, const int* __restrict__ dst,
                            int* __restrict__ pos, int* __restrict__ perm,
                            int* __restrict__ csrc, int E)
{
    int i = blockIdx.x * blockDim.x + threadIdx.x;
    if (i >= E) return;
    int slot = atomicAdd(&pos[dst[i]], 1);
    perm[i] = slot;
    csrc[slot] = src[i];
}

// ---------------- edge alpha, both lists in one kernel ----------------
__global__ void alpha_both_kernel(const int* __restrict__ src1, const int* __restrict__ dst1,
                                  const int* __restrict__ src2, const int* __restrict__ dst2,
                                  const float* __restrict__ as_, const float* __restrict__ ad_,
                                  const int* __restrict__ perm, float* __restrict__ cw,
                                  float* __restrict__ s, int E)
{
    int i = blockIdx.x * blockDim.x + threadIdx.x;
    if (i >= 2 * E) return;
    int l = (i >= E) ? 1 : 0;
    int j = i - l * E;
    const int* sp = l ? src2 : src1;
    const int* dp = l ? dst2 : dst1;
    int sn = sp[j], dn = dp[j];
    float v = as_[sn] + ad_[dn];
    v = v > 0.f ? v : 0.2f * v;          // leaky_relu, slope 0.2
    float ex = expf(v);
    cw[(size_t)l * EE + perm[(size_t)l * EE + j]] = ex;
    atomicAdd(&s[(size_t)l * NN + dn], ex);
}

// ---------------- per-node CSR aggregation (both lists), out = 2*bias + sums ----------------
template<int C>
__global__ void agg_kernel(const int* __restrict__ rp1, const int* __restrict__ cs1,
                           const float* __restrict__ cw1, const float* __restrict__ s1,
                           const int* __restrict__ rp2, const int* __restrict__ cs2,
                           const float* __restrict__ cw2, const float* __restrict__ s2,
                           const float* __restrict__ h, const float* __restrict__ bias,
                           float* __restrict__ out)
{
    int n = blockIdx.x;
    int c = threadIdx.x * 4;
    float4 b4 = *(const float4*)(bias + c);
    float4 acc = make_float4(2.f * b4.x, 2.f * b4.y, 2.f * b4.z, 2.f * b4.w);

    int st = rp1[n], en = rp1[n + 1];
    float inv = 1.f / (s1[n] + 1e-16f);
    for (int j = st; j < en; j++) {
        float wv = cw1[j] * inv;
        float4 hv = *(const float4*)(h + (size_t)cs1[j] * C + c);
        acc.x += wv * hv.x; acc.y += wv * hv.y;
        acc.z += wv * hv.z; acc.w += wv * hv.w;
    }
    st = rp2[n]; en = rp2[n + 1];
    inv = 1.f / (s2[n] + 1e-16f);
    for (int j = st; j < en; j++) {
        float wv = cw2[j] * inv;
        float4 hv = *(const float4*)(h + (size_t)cs2[j] * C + c);
        acc.x += wv * hv.x; acc.y += wv * hv.y;
        acc.z += wv * hv.z; acc.w += wv * hv.w;
    }
    *(float4*)(out + (size_t)n * C + c) = acc;
}

// ---------------- host orchestration ----------------
static void* symaddr(const void* s)
{
    void* p = nullptr;
    cudaGetSymbolAddress(&p, s);
    return p;
}

extern "C" void kernel_launch(void* const* d_in, const int* in_sizes, int n_in,
                              void* d_out, int out_size)
{
    (void)n_in; (void)out_size;
    const float* x   = (const float*)d_in[0];
    const int*   ei1 = (const int*)d_in[1];
    const int*   ei2 = (const int*)d_in[2];
    const float* W1s = (const float*)d_in[3];
    const float* W1d = (const float*)d_in[4];
    const float* a1s = (const float*)d_in[5];
    const float* a1d = (const float*)d_in[6];
    const float* b1  = (const float*)d_in[7];
    const float* Wl1 = (const float*)d_in[8];
    const float* bl1 = (const float*)d_in[9];
    const float* W2s = (const float*)d_in[10];
    const float* W2d = (const float*)d_in[11];
    const float* a2s = (const float*)d_in[12];
    const float* a2d = (const float*)d_in[13];
    const float* b2  = (const float*)d_in[14];
    const float* Wl2 = (const float*)d_in[15];
    const float* bl2 = (const float*)d_in[16];
    float* out = (float*)d_out;

    const int N = in_sizes[0] / DD;       // 50000
    const int E = in_sizes[1] / 2;        // 150000

    float* hsrc = (float*)symaddr(g_hsrc);
    float* agg  = (float*)symaddr(g_agg);
    float* hmid = (float*)symaddr(g_hmid);
    float* asrc = (float*)symaddr(g_asrc);
    float* adst = (float*)symaddr(g_adst);
    float* sbuf = (float*)symaddr(g_s);          // [4][NN]
    float* wa   = (float*)symaddr(g_wa);         // [2][DD]
    float* wb   = (float*)symaddr(g_wb);         // [2][DD]
    int* rowptr = (int*)symaddr(g_rowptr);
    int* pos    = (int*)symaddr(g_pos);
    int* perm   = (int*)symaddr(g_perm);
    int* csrc   = (int*)symaddr(g_csrc);
    float* cw   = (float*)symaddr(g_cw);
    int* bsum   = (int*)symaddr(g_bsum);
    int* boff   = (int*)symaddr(g_boff);
    __nv_bfloat16* whi = (__nv_bfloat16*)symaddr(g_whi);
    __nv_bfloat16* wlo = (__nv_bfloat16*)symaddr(g_wlo);

    const int NB = (NN + 511) / 512;
    const int* srcp1 = ei1;            const int* dstp1 = ei1 + E;
    const int* srcp2 = ei2;            const int* dstp2 = ei2 + E;

    static cudaStream_t sB = nullptr, sC = nullptr;
    static cudaEvent_t ev0, evB, evC1, ev1, evC2;
    if (!sB) {
        cudaStreamCreateWithFlags(&sB, cudaStreamNonBlocking);
        cudaStreamCreateWithFlags(&sC, cudaStreamNonBlocking);
        cudaEventCreateWithFlags(&ev0, cudaEventDisableTiming);
        cudaEventCreateWithFlags(&evB, cudaEventDisableTiming);
        cudaEventCreateWithFlags(&evC1, cudaEventDisableTiming);
        cudaEventCreateWithFlags(&ev1, cudaEventDisableTiming);
        cudaEventCreateWithFlags(&evC2, cudaEventDisableTiming);
    }

    dim3 gH(HH / 128, (N + 127) / 128);
    dim3 gO(OC / 128, (N + 127) / 128);

    // ===== fork =====
    cudaEventRecord(ev0, 0);
    cudaStreamWaitEvent(sB, ev0, 0);
    cudaStreamWaitEvent(sC, ev0, 0);

    // ----- stream B: weight splits (except W1s), L2 weight gemvs, CSR build, sum zeroing -----
    wsplit_kernel<<<(HH * HH / 4 + 255) / 256, 256, 0, sB>>>(Wl1, whi + WO2, wlo + WO2, HH * HH / 4);
    wsplit_kernel<<<(HH * OC / 4 + 255) / 256, 256, 0, sB>>>(W2s, whi + WO3, wlo + WO3, HH * OC / 4);
    wsplit_kernel<<<(OC * OC / 4 + 255) / 256, 256, 0, sB>>>(Wl2, whi + WO4, wlo + WO4, OC * OC / 4);
    gemv_kernel<<<(HH + 7) / 8, 256, 0, sB>>>(W2s, a2s, wa + DD, HH, OC);
    gemv_kernel<<<(HH + 7) / 8, 256, 0, sB>>>(W2d, a2d, wb + DD, HH, OC);
    zero_f_kernel<<<(4 * NN + 255) / 256, 256, 0, sB>>>(sbuf, 4 * NN);
    zero_int_kernel<<<(2 * NN + 255) / 256, 256, 0, sB>>>(pos, 2 * NN);
    for (int l = 0; l < 2; l++) {
        const int* dstp = l ? dstp2 : dstp1;
        const int* srcp = l ? srcp2 : srcp1;
        int* cnt_l = pos + l * NN;
        int* rp_l  = rowptr + l * (NN + 1);
        hist_kernel<<<(E + 255) / 256, 256, 0, sB>>>(dstp, cnt_l, E);
        scan1_kernel<<<NB, 512, 0, sB>>>(cnt_l, rp_l, bsum + l * 128, N);
        scan2_kernel<<<1, 128, 0, sB>>>(bsum + l * 128, boff + l * 128, NB);
        scan3_kernel<<<NB, 512, 0, sB>>>(rp_l, boff + l * 128, N);
        copy_int_kernel<<<(NN + 255) / 256, 256, 0, sB>>>(cnt_l, rp_l, N);
        fill_kernel<<<(E + 255) / 256, 256, 0, sB>>>(srcp, dstp, cnt_l, perm + l * EE, csrc + l * EE, E);
    }
    cudaEventRecord(evB, sB);

    // ----- stream C: L1 weight gemvs + node alphas from x + L1 edge alphas -----
    // (edge alphas depend only on CSR (evB) + node alphas -> overlap GEMM1)
    gemv_kernel<<<(DD + 7) / 8, 256, 0, sC>>>(W1s, a1s, wa, DD, HH);
    gemv_kernel<<<(DD + 7) / 8, 256, 0, sC>>>(W1d, a1d, wb, DD, HH);
    gemv2_kernel<<<(N + 7) / 8, 256, 0, sC>>>(x, wa, wb, asrc, adst, N, DD);
    cudaStreamWaitEvent(sC, evB, 0);
    alpha_both_kernel<<<(2 * E + 255) / 256, 256, 0, sC>>>(srcp1, dstp1, srcp2, dstp2,
                                                           asrc, adst, perm, cw, sbuf, E);
    cudaEventRecord(evC1, sC);

    // ----- default stream: critical chain -----
    wsplit_kernel<<<(DD * HH / 4 + 255) / 256, 256>>>(W1s, whi + WO1, wlo + WO1, DD * HH / 4);
    mma_gemm_kernel<false, false><<<gH, 256>>>(x, whi + WO1, wlo + WO1, nullptr, hsrc, N, HH, DD);

    cudaStreamWaitEvent(0, evC1, 0);
    agg_kernel<HH><<<N, HH / 4>>>(rowptr, csrc, cw, sbuf,
                                  rowptr + (NN + 1), csrc + EE, cw + EE, sbuf + NN,
                                  hsrc, b1, agg);
    mma_gemm_kernel<true, true><<<gH, 256>>>(agg, whi + WO2, wlo + WO2, bl1, hmid, N, HH, HH);

    // fork: layer-2 node/edge alphas overlap GEMM2
    cudaEventRecord(ev1, 0);
    cudaStreamWaitEvent(sC, ev1, 0);
    gemv2_kernel<<<(N + 7) / 8, 256, 0, sC>>>(hmid, wa + DD, wb + DD, asrc, adst, N, HH);
    alpha_both_kernel<<<(2 * E + 255) / 256, 256, 0, sC>>>(srcp1, dstp1, srcp2, dstp2,
                                                           asrc, adst, perm, cw, sbuf + 2 * NN, E);
    cudaEventRecord(evC2, sC);

    mma_gemm_kernel<false, false><<<gO, 256>>>(hmid, whi + WO3, wlo + WO3, nullptr, hsrc, N, OC, HH);

    cudaStreamWaitEvent(0, evC2, 0);
    agg_kernel<OC><<<N, OC / 4>>>(rowptr, csrc, cw, sbuf + 2 * NN,
                                  rowptr + (NN + 1), csrc + EE, cw + EE, sbuf + 3 * NN,
                                  hsrc, b2, agg);
    mma_gemm_kernel<true, false><<<gO, 256>>>(agg, whi + WO4, wlo + WO4, bl2, out, N, OC, OC);
}

// round 13
// speedup vs baseline: 1.6326x; 1.0453x over previous
#include <cuda_runtime.h>
#include <cuda_bf16.h>
#include <math_constants.h>
#include <cstdint>

// Problem constants (fixed by the reference setup)
#define NN  50000
#define DD  512
#define HH  512
#define OC  256
#define EE  150000

// ---------------- scratch (no allocation allowed -> __device__ globals) ----------------
__device__ float g_hsrc[(size_t)NN * HH];   // layer1: [N,512]; layer2 reuse: [N,256]
__device__ float g_agg [(size_t)NN * HH];   // conv accumulator
__device__ float g_hmid[(size_t)NN * HH];   // after lin1
__device__ float g_asrc[NN];
__device__ float g_adst[NN];
__device__ float g_s[4][NN];                // per-layer, per-list softmax sums
__device__ float g_wa[2][DD];
__device__ float g_wb[2][DD];

// CSR structures (built once per launch; shared by both layers)
__device__ int   g_rowptr[2][NN + 1];
__device__ int   g_pos[2][NN];              // histogram, then fill cursor
__device__ int   g_perm[2][EE];             // edge -> csr slot
__device__ int   g_csrc[2][EE];             // csr: source node per slot
__device__ float g_cw[2][EE];               // csr: exp(e) per slot (per layer)
__device__ int   g_bsum[2][128];
__device__ int   g_boff[2][128];

// pre-split weights, [K,N] fp32 layout -> bf16 hi/lo (same layout)
#define WO1 0
#define WO2 262144
#define WO3 524288
#define WO4 655360
#define WTOT 720896
__device__ __nv_bfloat16 g_whi[WTOT];
__device__ __nv_bfloat16 g_wlo[WTOT];

// ==================== weight bf16 hi/lo split (elementwise, float4) ====================
__global__ void wsplit_kernel(const float* __restrict__ W,
                              __nv_bfloat16* __restrict__ hi, __nv_bfloat16* __restrict__ lo,
                              int total4)
{
    int i = blockIdx.x * blockDim.x + threadIdx.x;
    if (i >= total4) return;
    float4 v = ((const float4*)W)[i];
    __nv_bfloat162 h0 = __floats2bfloat162_rn(v.x, v.y);
    float2 f0 = __bfloat1622float2(h0);
    __nv_bfloat162 l0 = __floats2bfloat162_rn(v.x - f0.x, v.y - f0.y);
    __nv_bfloat162 h1 = __floats2bfloat162_rn(v.z, v.w);
    float2 f1 = __bfloat1622float2(h1);
    __nv_bfloat162 l1 = __floats2bfloat162_rn(v.z - f1.x, v.w - f1.y);
    uint2 hh, ll;
    hh.x = reinterpret_cast<uint32_t&>(h0); hh.y = reinterpret_cast<uint32_t&>(h1);
    ll.x = reinterpret_cast<uint32_t&>(l0); ll.y = reinterpret_cast<uint32_t&>(l1);
    ((uint2*)hi)[i] = hh;
    ((uint2*)lo)[i] = ll;
}

// ==================== tensor-core GEMM (mma.sync, 3-term bf16 split) ====================
#define LDM4(r0,r1,r2,r3,addr) \
    asm volatile("ldmatrix.sync.aligned.m8n8.x4.shared.b16 {%0,%1,%2,%3}, [%4];" \
                 : "=r"(r0),"=r"(r1),"=r"(r2),"=r"(r3) : "r"(addr))
#define LDM4T(r0,r1,r2,r3,addr) \
    asm volatile("ldmatrix.sync.aligned.m8n8.x4.trans.shared.b16 {%0,%1,%2,%3}, [%4];" \
                 : "=r"(r0),"=r"(r1),"=r"(r2),"=r"(r3) : "r"(addr))
#define MMA16816(d, a, b) \
    asm volatile("mma.sync.aligned.m16n8k16.row.col.f32.bf16.bf16.f32 " \
                 "{%0,%1,%2,%3},{%4,%5,%6,%7},{%8,%9},{%0,%1,%2,%3};" \
                 : "+f"(d[0]),"+f"(d[1]),"+f"(d[2]),"+f"(d[3]) \
                 : "r"(a[0]),"r"(a[1]),"r"(a[2]),"r"(a[3]),"r"(b[0]),"r"(b[1]))
#define CP_ASYNC16(dst, src) \
    asm volatile("cp.async.ca.shared.global [%0], [%1], 16;" :: "r"(dst), "l"(src) : "memory")
#define CP_COMMIT()  asm volatile("cp.async.commit_group;" ::: "memory")
#define CP_WAIT0()   asm volatile("cp.async.wait_group 0;" ::: "memory")

__device__ __forceinline__ uint32_t smem_u32(const void* p)
{
    return (uint32_t)__cvta_generic_to_shared(p);
}

__device__ __forceinline__ void split2(__nv_bfloat16* hp, __nv_bfloat16* lp, float x, float y)
{
    __nv_bfloat162 h = __floats2bfloat162_rn(x, y);
    float2 hf = __bfloat1622float2(h);
    __nv_bfloat162 l = __floats2bfloat162_rn(x - hf.x, y - hf.y);
    *(__nv_bfloat162*)hp = h;
    *(__nv_bfloat162*)lp = l;
}

// dynamic-smem stage layout (bytes)
#define GA_HI 0
#define GA_LO 10240
#define GB_HI 20480
#define GB_LO 29184
#define GSTAGE 37888
#define GDSM (2 * GSTAGE)

// C = A[MxK](fp32, split on the fly) @ B[KxN](pre-split bf16 hi/lo) (+bias)(+relu)
// Double-buffered SMEM: B via cp.async, A via register prefetch; 1 sync per K-tile.
template<bool BIAS, bool RELU>
__global__ __launch_bounds__(256)
void mma_gemm_kernel(const float* __restrict__ A,
                     const __nv_bfloat16* __restrict__ Bhi,
                     const __nv_bfloat16* __restrict__ Blo,
                     const float* __restrict__ bias, float* __restrict__ C,
                     int M, int N, int K)
{
    const int BM = 128, BN = 128, BK = 32;
    const int ASTR = 40;      // A row stride (elements): BK + 8 pad
    const int BSTR = 136;     // B row stride (elements): BN + 8 pad
    extern __shared__ __align__(16) char dsm[];

    int tid = threadIdx.x;
    int lane = tid & 31;
    int w = tid >> 5;
    int wm = w & 3;
    int wn = w >> 2;

    int blockM = blockIdx.y * BM;
    int blockN = blockIdx.x * BN;

    int aRow0 = tid >> 3;          // + 32*i
    int aCol  = (tid & 7) * 4;
    // B tile: 32 rows x 128 cols = 512 uint4-groups of 8 bf16; 2 groups per thread
    int bR[2], bC[2];
    #pragma unroll
    for (int i = 0; i < 2; i++) {
        int g = tid + 256 * i;
        bR[i] = g >> 4;            // 0..31
        bC[i] = (g & 15) * 8;      // 0..120
    }

    const float4 z4 = make_float4(0.f, 0.f, 0.f, 0.f);
    float4 pa[4];

    float acc[2][8][4];
    #pragma unroll
    for (int mt = 0; mt < 2; mt++)
        #pragma unroll
        for (int nt = 0; nt < 8; nt++)
            #pragma unroll
            for (int q = 0; q < 4; q++) acc[mt][nt][q] = 0.f;

    const uint32_t smBase = smem_u32(dsm);

    // ---- prologue: tile 0 into stage 0 ----
    #pragma unroll
    for (int i = 0; i < 2; i++) {
        uint32_t so = (uint32_t)(bR[i] * BSTR + bC[i]) * 2u;
        size_t go = (size_t)bR[i] * N + blockN + bC[i];
        CP_ASYNC16(smBase + GB_HI + so, Bhi + go);
        CP_ASYNC16(smBase + GB_LO + so, Blo + go);
    }
    CP_COMMIT();
    #pragma unroll
    for (int i = 0; i < 4; i++) {
        int r = blockM + aRow0 + 32 * i;
        pa[i] = (r < M) ? *(const float4*)(A + (size_t)r * K + aCol) : z4;
    }
    #pragma unroll
    for (int i = 0; i < 4; i++) {
        int r = aRow0 + 32 * i;
        __nv_bfloat16* hp = (__nv_bfloat16*)(dsm + GA_HI + (r * ASTR + aCol) * 2);
        __nv_bfloat16* lp = (__nv_bfloat16*)(dsm + GA_LO + (r * ASTR + aCol) * 2);
        split2(hp,     lp,     pa[i].x, pa[i].y);
        split2(hp + 2, lp + 2, pa[i].z, pa[i].w);
    }
    CP_WAIT0();
    __syncthreads();

    int nT = K / BK;
    for (int kt = 0; kt < nT; kt++) {
        uint32_t cur = (uint32_t)(kt & 1) * GSTAGE;
        uint32_t nxt = cur ^ GSTAGE;

        // prefetch next tile: B via cp.async into nxt, A into registers
        if (kt + 1 < nT) {
            #pragma unroll
            for (int i = 0; i < 2; i++) {
                uint32_t so = (uint32_t)(bR[i] * BSTR + bC[i]) * 2u;
                size_t go = (size_t)((kt + 1) * BK + bR[i]) * N + blockN + bC[i];
                CP_ASYNC16(smBase + nxt + GB_HI + so, Bhi + go);
                CP_ASYNC16(smBase + nxt + GB_LO + so, Blo + go);
            }
            CP_COMMIT();
            #pragma unroll
            for (int i = 0; i < 4; i++) {
                int r = blockM + aRow0 + 32 * i;
                pa[i] = (r < M) ? *(const float4*)(A + (size_t)r * K + (kt + 1) * BK + aCol) : z4;
            }
        }

        // compute on cur
        #pragma unroll
        for (int ks = 0; ks < 2; ks++) {
            uint32_t ah[2][4], al[2][4];
            #pragma unroll
            for (int mt = 0; mt < 2; mt++) {
                uint32_t off = (uint32_t)((wm * 32 + mt * 16 + (lane & 15)) * ASTR
                                          + (lane >> 4) * 8 + ks * 16) * 2u;
                LDM4(ah[mt][0], ah[mt][1], ah[mt][2], ah[mt][3], smBase + cur + GA_HI + off);
                LDM4(al[mt][0], al[mt][1], al[mt][2], al[mt][3], smBase + cur + GA_LO + off);
            }
            uint32_t bh[8][2], bl[8][2];
            #pragma unroll
            for (int p = 0; p < 4; p++) {
                uint32_t off = (uint32_t)((ks * 16 + (lane & 15)) * BSTR
                                          + wn * 64 + p * 16 + ((lane & 16) >> 1)) * 2u;
                uint32_t r0, r1, r2, r3;
                LDM4T(r0, r1, r2, r3, smBase + cur + GB_HI + off);
                bh[2 * p][0] = r0; bh[2 * p][1] = r1;
                bh[2 * p + 1][0] = r2; bh[2 * p + 1][1] = r3;
                LDM4T(r0, r1, r2, r3, smBase + cur + GB_LO + off);
                bl[2 * p][0] = r0; bl[2 * p][1] = r1;
                bl[2 * p + 1][0] = r2; bl[2 * p + 1][1] = r3;
            }
            #pragma unroll
            for (int mt = 0; mt < 2; mt++)
                #pragma unroll
                for (int nt = 0; nt < 8; nt++) {
                    MMA16816(acc[mt][nt], ah[mt], bh[nt]);
                    MMA16816(acc[mt][nt], ah[mt], bl[nt]);
                    MMA16816(acc[mt][nt], al[mt], bh[nt]);
                }
        }

        if (kt + 1 < nT) {
            // split-store A into nxt, then drain cp.async before the sync
            #pragma unroll
            for (int i = 0; i < 4; i++) {
                int r = aRow0 + 32 * i;
                __nv_bfloat16* hp = (__nv_bfloat16*)(dsm + nxt + GA_HI + (r * ASTR + aCol) * 2);
                __nv_bfloat16* lp = (__nv_bfloat16*)(dsm + nxt + GA_LO + (r * ASTR + aCol) * 2);
                split2(hp,     lp,     pa[i].x, pa[i].y);
                split2(hp + 2, lp + 2, pa[i].z, pa[i].w);
            }
            CP_WAIT0();
        }
        __syncthreads();
    }

    // epilogue
    #pragma unroll
    for (int mt = 0; mt < 2; mt++) {
        #pragma unroll
        for (int nt = 0; nt < 8; nt++) {
            int row = blockM + wm * 32 + mt * 16 + (lane >> 2);
            int col = blockN + wn * 64 + nt * 8 + (lane & 3) * 2;
            float2 v0 = make_float2(acc[mt][nt][0], acc[mt][nt][1]);
            float2 v1 = make_float2(acc[mt][nt][2], acc[mt][nt][3]);
            if (BIAS) {
                float2 bv = *(const float2*)(bias + col);
                v0.x += bv.x; v0.y += bv.y;
                v1.x += bv.x; v1.y += bv.y;
            }
            if (RELU) {
                v0.x = fmaxf(v0.x, 0.f); v0.y = fmaxf(v0.y, 0.f);
                v1.x = fmaxf(v1.x, 0.f); v1.y = fmaxf(v1.y, 0.f);
            }
            if (row < M)     *(float2*)(C + (size_t)row * N + col) = v0;
            if (row + 8 < M) *(float2*)(C + (size_t)(row + 8) * N + col) = v1;
        }
    }
}

// ---------------- GEMV kernels ----------------
__global__ void gemv_kernel(const float* __restrict__ A, const float* __restrict__ v,
                            float* __restrict__ out, int M, int K)
{
    int row = blockIdx.x * (blockDim.x >> 5) + (threadIdx.x >> 5);
    int lane = threadIdx.x & 31;
    if (row >= M) return;
    const float4* a4 = (const float4*)(A + (size_t)row * K);
    const float4* v4 = (const float4*)v;
    int K4 = K >> 2;
    float sum = 0.f;
    for (int k = lane; k < K4; k += 32) {
        float4 a = a4[k], b = v4[k];
        sum += a.x * b.x + a.y * b.y + a.z * b.z + a.w * b.w;
    }
    #pragma unroll
    for (int o = 16; o; o >>= 1) sum += __shfl_down_sync(0xffffffffu, sum, o);
    if (lane == 0) out[row] = sum;
}

__global__ void gemv2_kernel(const float* __restrict__ A,
                             const float* __restrict__ va, const float* __restrict__ vb,
                             float* __restrict__ oa, float* __restrict__ ob, int M, int K)
{
    int row = blockIdx.x * (blockDim.x >> 5) + (threadIdx.x >> 5);
    int lane = threadIdx.x & 31;
    if (row >= M) return;
    const float4* a4 = (const float4*)(A + (size_t)row * K);
    const float4* va4 = (const float4*)va;
    const float4* vb4 = (const float4*)vb;
    int K4 = K >> 2;
    float sa = 0.f, sb = 0.f;
    for (int k = lane; k < K4; k += 32) {
        float4 a = a4[k], u = va4[k], t = vb4[k];
        sa += a.x * u.x + a.y * u.y + a.z * u.z + a.w * u.w;
        sb += a.x * t.x + a.y * t.y + a.z * t.z + a.w * t.w;
    }
    #pragma unroll
    for (int o = 16; o; o >>= 1) {
        sa += __shfl_down_sync(0xffffffffu, sa, o);
        sb += __shfl_down_sync(0xffffffffu, sb, o);
    }
    if (lane == 0) { oa[row] = sa; ob[row] = sb; }
}

// ---------------- CSR build kernels ----------------
__global__ void zero_int_kernel(int* __restrict__ p, int n)
{
    int i = blockIdx.x * blockDim.x + threadIdx.x;
    if (i < n) p[i] = 0;
}
__global__ void zero_f_kernel(float* __restrict__ p, int n)
{
    int i = blockIdx.x * blockDim.x + threadIdx.x;
    if (i < n) p[i] = 0.f;
}
__global__ void hist_kernel(const int* __restrict__ dst, int* __restrict__ cnt, int E)
{
    int i = blockIdx.x * blockDim.x + threadIdx.x;
    if (i < E) atomicAdd(&cnt[dst[i]], 1);
}
__global__ void scan1_kernel(const int* __restrict__ cnt, int* __restrict__ rowptr,
                             int* __restrict__ bsum, int n)
{
    __shared__ int sm[512];
    int t = threadIdx.x;
    int idx = blockIdx.x * 512 + t;
    int v = (idx < n) ? cnt[idx] : 0;
    sm[t] = v;
    __syncthreads();
    for (int o = 1; o < 512; o <<= 1) {
        int a = (t >= o) ? sm[t - o] : 0;
        __syncthreads();
        sm[t] += a;
        __syncthreads();
    }
    if (idx < n) rowptr[idx + 1] = sm[t];
    if (t == 511) bsum[blockIdx.x] = sm[511];
}
__global__ void scan2_kernel(const int* __restrict__ bsum, int* __restrict__ boff, int nb)
{
    __shared__ int sm[128];
    int t = threadIdx.x;
    int v = (t < nb) ? bsum[t] : 0;
    sm[t] = v;
    __syncthreads();
    for (int o = 1; o < 128; o <<= 1) {
        int a = (t >= o) ? sm[t - o] : 0;
        __syncthreads();
        sm[t] += a;
        __syncthreads();
    }
    boff[t] = sm[t] - v;     // exclusive
}
__global__ void scan3_kernel(int* __restrict__ rowptr, const int* __restrict__ boff, int n)
{
    int idx = blockIdx.x * 512 + threadIdx.x;
    if (idx < n) rowptr[idx + 1] += boff[blockIdx.x];
    if (idx == 0) rowptr[0] = 0;
}
__global__ void copy_int_kernel(int* __restrict__ d, const int* __restrict__ s, int n)
{
    int i = blockIdx.x * blockDim.x + threadIdx.x;
    if (i < n) d[i] = s[i];
}
__global__ void fill_kernel(const int* __restrict__ src, const int* __restrict__ dst,
                            int* __restrict__ pos, int* __restrict__ perm,
                            int* __restrict__ csrc, int E)
{
    int i = blockIdx.x * blockDim.x + threadIdx.x;
    if (i >= E) return;
    int slot = atomicAdd(&pos[dst[i]], 1);
    perm[i] = slot;
    csrc[slot] = src[i];
}

// ---------------- edge alpha, both lists in one kernel ----------------
__global__ void alpha_both_kernel(const int* __restrict__ src1, const int* __restrict__ dst1,
                                  const int* __restrict__ src2, const int* __restrict__ dst2,
                                  const float* __restrict__ as_, const float* __restrict__ ad_,
                                  const int* __restrict__ perm, float* __restrict__ cw,
                                  float* __restrict__ s, int E)
{
    int i = blockIdx.x * blockDim.x + threadIdx.x;
    if (i >= 2 * E) return;
    int l = (i >= E) ? 1 : 0;
    int j = i - l * E;
    const int* sp = l ? src2 : src1;
    const int* dp = l ? dst2 : dst1;
    int sn = sp[j], dn = dp[j];
    float v = as_[sn] + ad_[dn];
    v = v > 0.f ? v : 0.2f * v;          // leaky_relu, slope 0.2
    float ex = expf(v);
    cw[(size_t)l * EE + perm[(size_t)l * EE + j]] = ex;
    atomicAdd(&s[(size_t)l * NN + dn], ex);
}

// ---------------- per-node CSR aggregation (both lists), out = 2*bias + sums ----------------
template<int C>
__global__ void agg_kernel(const int* __restrict__ rp1, const int* __restrict__ cs1,
                           const float* __restrict__ cw1, const float* __restrict__ s1,
                           const int* __restrict__ rp2, const int* __restrict__ cs2,
                           const float* __restrict__ cw2, const float* __restrict__ s2,
                           const float* __restrict__ h, const float* __restrict__ bias,
                           float* __restrict__ out)
{
    int n = blockIdx.x;
    int c = threadIdx.x * 4;
    float4 b4 = *(const float4*)(bias + c);
    float4 acc = make_float4(2.f * b4.x, 2.f * b4.y, 2.f * b4.z, 2.f * b4.w);

    int st = rp1[n], en = rp1[n + 1];
    float inv = 1.f / (s1[n] + 1e-16f);
    for (int j = st; j < en; j++) {
        float wv = cw1[j] * inv;
        float4 hv = *(const float4*)(h + (size_t)cs1[j] * C + c);
        acc.x += wv * hv.x; acc.y += wv * hv.y;
        acc.z += wv * hv.z; acc.w += wv * hv.w;
    }
    st = rp2[n]; en = rp2[n + 1];
    inv = 1.f / (s2[n] + 1e-16f);
    for (int j = st; j < en; j++) {
        float wv = cw2[j] * inv;
        float4 hv = *(const float4*)(h + (size_t)cs2[j] * C + c);
        acc.x += wv * hv.x; acc.y += wv * hv.y;
        acc.z += wv * hv.z; acc.w += wv * hv.w;
    }
    *(float4*)(out + (size_t)n * C + c) = acc;
}

// ---------------- host orchestration ----------------
static void* symaddr(const void* s)
{
    void* p = nullptr;
    cudaGetSymbolAddress(&p, s);
    return p;
}

extern "C" void kernel_launch(void* const* d_in, const int* in_sizes, int n_in,
                              void* d_out, int out_size)
{
    (void)n_in; (void)out_size;
    const float* x   = (const float*)d_in[0];
    const int*   ei1 = (const int*)d_in[1];
    const int*   ei2 = (const int*)d_in[2];
    const float* W1s = (const float*)d_in[3];
    const float* W1d = (const float*)d_in[4];
    const float* a1s = (const float*)d_in[5];
    const float* a1d = (const float*)d_in[6];
    const float* b1  = (const float*)d_in[7];
    const float* Wl1 = (const float*)d_in[8];
    const float* bl1 = (const float*)d_in[9];
    const float* W2s = (const float*)d_in[10];
    const float* W2d = (const float*)d_in[11];
    const float* a2s = (const float*)d_in[12];
    const float* a2d = (const float*)d_in[13];
    const float* b2  = (const float*)d_in[14];
    const float* Wl2 = (const float*)d_in[15];
    const float* bl2 = (const float*)d_in[16];
    float* out = (float*)d_out;

    const int N = in_sizes[0] / DD;       // 50000
    const int E = in_sizes[1] / 2;        // 150000

    float* hsrc = (float*)symaddr(g_hsrc);
    float* agg  = (float*)symaddr(g_agg);
    float* hmid = (float*)symaddr(g_hmid);
    float* asrc = (float*)symaddr(g_asrc);
    float* adst = (float*)symaddr(g_adst);
    float* sbuf = (float*)symaddr(g_s);          // [4][NN]
    float* wa   = (float*)symaddr(g_wa);         // [2][DD]
    float* wb   = (float*)symaddr(g_wb);         // [2][DD]
    int* rowptr = (int*)symaddr(g_rowptr);
    int* pos    = (int*)symaddr(g_pos);
    int* perm   = (int*)symaddr(g_perm);
    int* csrc   = (int*)symaddr(g_csrc);
    float* cw   = (float*)symaddr(g_cw);
    int* bsum   = (int*)symaddr(g_bsum);
    int* boff   = (int*)symaddr(g_boff);
    __nv_bfloat16* whi = (__nv_bfloat16*)symaddr(g_whi);
    __nv_bfloat16* wlo = (__nv_bfloat16*)symaddr(g_wlo);

    const int NB = (NN + 511) / 512;
    const int* srcp1 = ei1;            const int* dstp1 = ei1 + E;
    const int* srcp2 = ei2;            const int* dstp2 = ei2 + E;

    static cudaStream_t sB = nullptr, sC = nullptr;
    static cudaEvent_t ev0, evB, evC1, ev1, evC2;
    if (!sB) {
        cudaStreamCreateWithFlags(&sB, cudaStreamNonBlocking);
        cudaStreamCreateWithFlags(&sC, cudaStreamNonBlocking);
        cudaEventCreateWithFlags(&ev0, cudaEventDisableTiming);
        cudaEventCreateWithFlags(&evB, cudaEventDisableTiming);
        cudaEventCreateWithFlags(&evC1, cudaEventDisableTiming);
        cudaEventCreateWithFlags(&ev1, cudaEventDisableTiming);
        cudaEventCreateWithFlags(&evC2, cudaEventDisableTiming);
        cudaFuncSetAttribute(mma_gemm_kernel<false, false>,
                             cudaFuncAttributeMaxDynamicSharedMemorySize, GDSM);
        cudaFuncSetAttribute(mma_gemm_kernel<true, true>,
                             cudaFuncAttributeMaxDynamicSharedMemorySize, GDSM);
        cudaFuncSetAttribute(mma_gemm_kernel<true, false>,
                             cudaFuncAttributeMaxDynamicSharedMemorySize, GDSM);
    }

    dim3 gH(HH / 128, (N + 127) / 128);
    dim3 gO(OC / 128, (N + 127) / 128);

    // ===== fork =====
    cudaEventRecord(ev0, 0);
    cudaStreamWaitEvent(sB, ev0, 0);
    cudaStreamWaitEvent(sC, ev0, 0);

    // ----- stream B: weight splits (except W1s), L2 weight gemvs, CSR build, sum zeroing -----
    wsplit_kernel<<<(HH * HH / 4 + 255) / 256, 256, 0, sB>>>(Wl1, whi + WO2, wlo + WO2, HH * HH / 4);
    wsplit_kernel<<<(HH * OC / 4 + 255) / 256, 256, 0, sB>>>(W2s, whi + WO3, wlo + WO3, HH * OC / 4);
    wsplit_kernel<<<(OC * OC / 4 + 255) / 256, 256, 0, sB>>>(Wl2, whi + WO4, wlo + WO4, OC * OC / 4);
    gemv_kernel<<<(HH + 7) / 8, 256, 0, sB>>>(W2s, a2s, wa + DD, HH, OC);
    gemv_kernel<<<(HH + 7) / 8, 256, 0, sB>>>(W2d, a2d, wb + DD, HH, OC);
    zero_f_kernel<<<(4 * NN + 255) / 256, 256, 0, sB>>>(sbuf, 4 * NN);
    zero_int_kernel<<<(2 * NN + 255) / 256, 256, 0, sB>>>(pos, 2 * NN);
    for (int l = 0; l < 2; l++) {
        const int* dstp = l ? dstp2 : dstp1;
        const int* srcp = l ? srcp2 : srcp1;
        int* cnt_l = pos + l * NN;
        int* rp_l  = rowptr + l * (NN + 1);
        hist_kernel<<<(E + 255) / 256, 256, 0, sB>>>(dstp, cnt_l, E);
        scan1_kernel<<<NB, 512, 0, sB>>>(cnt_l, rp_l, bsum + l * 128, N);
        scan2_kernel<<<1, 128, 0, sB>>>(bsum + l * 128, boff + l * 128, NB);
        scan3_kernel<<<NB, 512, 0, sB>>>(rp_l, boff + l * 128, N);
        copy_int_kernel<<<(NN + 255) / 256, 256, 0, sB>>>(cnt_l, rp_l, N);
        fill_kernel<<<(E + 255) / 256, 256, 0, sB>>>(srcp, dstp, cnt_l, perm + l * EE, csrc + l * EE, E);
    }
    cudaEventRecord(evB, sB);

    // ----- stream C: L1 weight gemvs + node alphas from x + L1 edge alphas -----
    gemv_kernel<<<(DD + 7) / 8, 256, 0, sC>>>(W1s, a1s, wa, DD, HH);
    gemv_kernel<<<(DD + 7) / 8, 256, 0, sC>>>(W1d, a1d, wb, DD, HH);
    gemv2_kernel<<<(N + 7) / 8, 256, 0, sC>>>(x, wa, wb, asrc, adst, N, DD);
    cudaStreamWaitEvent(sC, evB, 0);
    alpha_both_kernel<<<(2 * E + 255) / 256, 256, 0, sC>>>(srcp1, dstp1, srcp2, dstp2,
                                                           asrc, adst, perm, cw, sbuf, E);
    cudaEventRecord(evC1, sC);

    // ----- default stream: critical chain -----
    wsplit_kernel<<<(DD * HH / 4 + 255) / 256, 256>>>(W1s, whi + WO1, wlo + WO1, DD * HH / 4);
    mma_gemm_kernel<false, false><<<gH, 256, GDSM>>>(x, whi + WO1, wlo + WO1, nullptr, hsrc, N, HH, DD);

    cudaStreamWaitEvent(0, evC1, 0);
    agg_kernel<HH><<<N, HH / 4>>>(rowptr, csrc, cw, sbuf,
                                  rowptr + (NN + 1), csrc + EE, cw + EE, sbuf + NN,
                                  hsrc, b1, agg);
    mma_gemm_kernel<true, true><<<gH, 256, GDSM>>>(agg, whi + WO2, wlo + WO2, bl1, hmid, N, HH, HH);

    // fork: layer-2 node/edge alphas overlap GEMM2
    cudaEventRecord(ev1, 0);
    cudaStreamWaitEvent(sC, ev1, 0);
    gemv2_kernel<<<(N + 7) / 8, 256, 0, sC>>>(hmid, wa + DD, wb + DD, asrc, adst, N, HH);
    alpha_both_kernel<<<(2 * E + 255) / 256, 256, 0, sC>>>(srcp1, dstp1, srcp2, dstp2,
                                                           asrc, adst, perm, cw, sbuf + 2 * NN, E);
    cudaEventRecord(evC2, sC);

    mma_gemm_kernel<false, false><<<gO, 256, GDSM>>>(hmid, whi + WO3, wlo + WO3, nullptr, hsrc, N, OC, HH);

    cudaStreamWaitEvent(0, evC2, 0);
    agg_kernel<OC><<<N, OC / 4>>>(rowptr, csrc, cw, sbuf + 2 * NN,
                                  rowptr + (NN + 1), csrc + EE, cw + EE, sbuf + 3 * NN,
                                  hsrc, b2, agg);
    mma_gemm_kernel<true, false><<<gO, 256, GDSM>>>(agg, whi + WO4, wlo + WO4, bl2, out, N, OC, OC);
}

// round 14
// speedup vs baseline: 1.6552x; 1.0139x over previous
#include <cuda_runtime.h>
#include <cuda_bf16.h>
#include <math_constants.h>
#include <cstdint>

// Problem constants (fixed by the reference setup)
#define NN  50000
#define DD  512
#define HH  512
#define OC  256
#define EE  150000

// ---------------- scratch (no allocation allowed -> __device__ globals) ----------------
__device__ float g_hsrc[(size_t)NN * HH];   // layer1: [N,512]; layer2 reuse: [N,256]
__device__ float g_agg [(size_t)NN * HH];   // conv accumulator
__device__ float g_hmid[(size_t)NN * HH];   // after lin1
__device__ float g_asrc[NN];
__device__ float g_adst[NN];
__device__ float g_s[4][NN];                // per-layer, per-list softmax sums
__device__ float g_wa[2][DD];
__device__ float g_wb[2][DD];

// CSR structures (built once per launch; shared by both layers)
__device__ int   g_rowptr[2][NN + 1];
__device__ int   g_pos[2][NN];              // histogram, then fill cursor
__device__ int   g_perm[2][EE];             // edge -> csr slot
__device__ int   g_csrc[2][EE];             // csr: source node per slot
__device__ float g_cw[2][EE];               // csr: exp(e) per slot (per layer)
__device__ int   g_bsum[2][128];
__device__ int   g_boff[2][128];

// pre-split weights, [K,N] fp32 layout -> bf16 hi/lo (same layout)
#define WO1 0
#define WO2 262144
#define WO3 524288
#define WO4 655360
#define WTOT 720896
__device__ __nv_bfloat16 g_whi[WTOT];
__device__ __nv_bfloat16 g_wlo[WTOT];

// ==================== weight bf16 hi/lo split (elementwise, float4) ====================
__global__ void wsplit_kernel(const float* __restrict__ W,
                              __nv_bfloat16* __restrict__ hi, __nv_bfloat16* __restrict__ lo,
                              int total4)
{
    int i = blockIdx.x * blockDim.x + threadIdx.x;
    if (i >= total4) return;
    float4 v = ((const float4*)W)[i];
    __nv_bfloat162 h0 = __floats2bfloat162_rn(v.x, v.y);
    float2 f0 = __bfloat1622float2(h0);
    __nv_bfloat162 l0 = __floats2bfloat162_rn(v.x - f0.x, v.y - f0.y);
    __nv_bfloat162 h1 = __floats2bfloat162_rn(v.z, v.w);
    float2 f1 = __bfloat1622float2(h1);
    __nv_bfloat162 l1 = __floats2bfloat162_rn(v.z - f1.x, v.w - f1.y);
    uint2 hh, ll;
    hh.x = reinterpret_cast<uint32_t&>(h0); hh.y = reinterpret_cast<uint32_t&>(h1);
    ll.x = reinterpret_cast<uint32_t&>(l0); ll.y = reinterpret_cast<uint32_t&>(l1);
    ((uint2*)hi)[i] = hh;
    ((uint2*)lo)[i] = ll;
}

// ==================== tensor-core GEMM (mma.sync, 3-term bf16 split) ====================
#define LDM4(r0,r1,r2,r3,addr) \
    asm volatile("ldmatrix.sync.aligned.m8n8.x4.shared.b16 {%0,%1,%2,%3}, [%4];" \
                 : "=r"(r0),"=r"(r1),"=r"(r2),"=r"(r3) : "r"(addr))
#define LDM4T(r0,r1,r2,r3,addr) \
    asm volatile("ldmatrix.sync.aligned.m8n8.x4.trans.shared.b16 {%0,%1,%2,%3}, [%4];" \
                 : "=r"(r0),"=r"(r1),"=r"(r2),"=r"(r3) : "r"(addr))
#define MMA16816(d, a, b) \
    asm volatile("mma.sync.aligned.m16n8k16.row.col.f32.bf16.bf16.f32 " \
                 "{%0,%1,%2,%3},{%4,%5,%6,%7},{%8,%9},{%0,%1,%2,%3};" \
                 : "+f"(d[0]),"+f"(d[1]),"+f"(d[2]),"+f"(d[3]) \
                 : "r"(a[0]),"r"(a[1]),"r"(a[2]),"r"(a[3]),"r"(b[0]),"r"(b[1]))
#define CP_ASYNC16(dst, src) \
    asm volatile("cp.async.ca.shared.global [%0], [%1], 16;" :: "r"(dst), "l"(src) : "memory")
#define CP_COMMIT()  asm volatile("cp.async.commit_group;" ::: "memory")
#define CP_WAIT0()   asm volatile("cp.async.wait_group 0;" ::: "memory")

__device__ __forceinline__ uint32_t smem_u32(const void* p)
{
    return (uint32_t)__cvta_generic_to_shared(p);
}

__device__ __forceinline__ void split2(__nv_bfloat16* hp, __nv_bfloat16* lp, float x, float y)
{
    __nv_bfloat162 h = __floats2bfloat162_rn(x, y);
    float2 hf = __bfloat1622float2(h);
    __nv_bfloat162 l = __floats2bfloat162_rn(x - hf.x, y - hf.y);
    *(__nv_bfloat162*)hp = h;
    *(__nv_bfloat162*)lp = l;
}

// dynamic-smem stage layout (bytes)
#define GA_HI 0
#define GA_LO 10240
#define GB_HI 20480
#define GB_LO 29184
#define GSTAGE 37888
#define GDSM (2 * GSTAGE)

// C = A[MxK](fp32, split on the fly) @ B[KxN](pre-split bf16 hi/lo) (+bias)(+relu)
// Double-buffered SMEM: B via cp.async, A via register prefetch; 1 sync per K-tile.
template<bool BIAS, bool RELU>
__global__ __launch_bounds__(256)
void mma_gemm_kernel(const float* __restrict__ A,
                     const __nv_bfloat16* __restrict__ Bhi,
                     const __nv_bfloat16* __restrict__ Blo,
                     const float* __restrict__ bias, float* __restrict__ C,
                     int M, int N, int K)
{
    const int BM = 128, BN = 128, BK = 32;
    const int ASTR = 40;      // A row stride (elements): BK + 8 pad
    const int BSTR = 136;     // B row stride (elements): BN + 8 pad
    extern __shared__ __align__(16) char dsm[];

    int tid = threadIdx.x;
    int lane = tid & 31;
    int w = tid >> 5;
    int wm = w & 3;
    int wn = w >> 2;

    int blockM = blockIdx.y * BM;
    int blockN = blockIdx.x * BN;

    int aRow0 = tid >> 3;          // + 32*i
    int aCol  = (tid & 7) * 4;
    // B tile: 32 rows x 128 cols = 512 uint4-groups of 8 bf16; 2 groups per thread
    int bR[2], bC[2];
    #pragma unroll
    for (int i = 0; i < 2; i++) {
        int g = tid + 256 * i;
        bR[i] = g >> 4;            // 0..31
        bC[i] = (g & 15) * 8;      // 0..120
    }

    const float4 z4 = make_float4(0.f, 0.f, 0.f, 0.f);
    float4 pa[4];

    float acc[2][8][4];
    #pragma unroll
    for (int mt = 0; mt < 2; mt++)
        #pragma unroll
        for (int nt = 0; nt < 8; nt++)
            #pragma unroll
            for (int q = 0; q < 4; q++) acc[mt][nt][q] = 0.f;

    const uint32_t smBase = smem_u32(dsm);

    // ---- prologue: tile 0 into stage 0 ----
    #pragma unroll
    for (int i = 0; i < 2; i++) {
        uint32_t so = (uint32_t)(bR[i] * BSTR + bC[i]) * 2u;
        size_t go = (size_t)bR[i] * N + blockN + bC[i];
        CP_ASYNC16(smBase + GB_HI + so, Bhi + go);
        CP_ASYNC16(smBase + GB_LO + so, Blo + go);
    }
    CP_COMMIT();
    #pragma unroll
    for (int i = 0; i < 4; i++) {
        int r = blockM + aRow0 + 32 * i;
        pa[i] = (r < M) ? *(const float4*)(A + (size_t)r * K + aCol) : z4;
    }
    #pragma unroll
    for (int i = 0; i < 4; i++) {
        int r = aRow0 + 32 * i;
        __nv_bfloat16* hp = (__nv_bfloat16*)(dsm + GA_HI + (r * ASTR + aCol) * 2);
        __nv_bfloat16* lp = (__nv_bfloat16*)(dsm + GA_LO + (r * ASTR + aCol) * 2);
        split2(hp,     lp,     pa[i].x, pa[i].y);
        split2(hp + 2, lp + 2, pa[i].z, pa[i].w);
    }
    CP_WAIT0();
    __syncthreads();

    int nT = K / BK;
    for (int kt = 0; kt < nT; kt++) {
        uint32_t cur = (uint32_t)(kt & 1) * GSTAGE;
        uint32_t nxt = cur ^ GSTAGE;

        // prefetch next tile: B via cp.async into nxt, A into registers
        if (kt + 1 < nT) {
            #pragma unroll
            for (int i = 0; i < 2; i++) {
                uint32_t so = (uint32_t)(bR[i] * BSTR + bC[i]) * 2u;
                size_t go = (size_t)((kt + 1) * BK + bR[i]) * N + blockN + bC[i];
                CP_ASYNC16(smBase + nxt + GB_HI + so, Bhi + go);
                CP_ASYNC16(smBase + nxt + GB_LO + so, Blo + go);
            }
            CP_COMMIT();
            #pragma unroll
            for (int i = 0; i < 4; i++) {
                int r = blockM + aRow0 + 32 * i;
                pa[i] = (r < M) ? *(const float4*)(A + (size_t)r * K + (kt + 1) * BK + aCol) : z4;
            }
        }

        // compute on cur
        #pragma unroll
        for (int ks = 0; ks < 2; ks++) {
            uint32_t ah[2][4], al[2][4];
            #pragma unroll
            for (int mt = 0; mt < 2; mt++) {
                uint32_t off = (uint32_t)((wm * 32 + mt * 16 + (lane & 15)) * ASTR
                                          + (lane >> 4) * 8 + ks * 16) * 2u;
                LDM4(ah[mt][0], ah[mt][1], ah[mt][2], ah[mt][3], smBase + cur + GA_HI + off);
                LDM4(al[mt][0], al[mt][1], al[mt][2], al[mt][3], smBase + cur + GA_LO + off);
            }
            uint32_t bh[8][2], bl[8][2];
            #pragma unroll
            for (int p = 0; p < 4; p++) {
                uint32_t off = (uint32_t)((ks * 16 + (lane & 15)) * BSTR
                                          + wn * 64 + p * 16 + ((lane & 16) >> 1)) * 2u;
                uint32_t r0, r1, r2, r3;
                LDM4T(r0, r1, r2, r3, smBase + cur + GB_HI + off);
                bh[2 * p][0] = r0; bh[2 * p][1] = r1;
                bh[2 * p + 1][0] = r2; bh[2 * p + 1][1] = r3;
                LDM4T(r0, r1, r2, r3, smBase + cur + GB_LO + off);
                bl[2 * p][0] = r0; bl[2 * p][1] = r1;
                bl[2 * p + 1][0] = r2; bl[2 * p + 1][1] = r3;
            }
            #pragma unroll
            for (int mt = 0; mt < 2; mt++)
                #pragma unroll
                for (int nt = 0; nt < 8; nt++) {
                    MMA16816(acc[mt][nt], ah[mt], bh[nt]);
                    MMA16816(acc[mt][nt], ah[mt], bl[nt]);
                    MMA16816(acc[mt][nt], al[mt], bh[nt]);
                }
        }

        if (kt + 1 < nT) {
            // split-store A into nxt, then drain cp.async before the sync
            #pragma unroll
            for (int i = 0; i < 4; i++) {
                int r = aRow0 + 32 * i;
                __nv_bfloat16* hp = (__nv_bfloat16*)(dsm + nxt + GA_HI + (r * ASTR + aCol) * 2);
                __nv_bfloat16* lp = (__nv_bfloat16*)(dsm + nxt + GA_LO + (r * ASTR + aCol) * 2);
                split2(hp,     lp,     pa[i].x, pa[i].y);
                split2(hp + 2, lp + 2, pa[i].z, pa[i].w);
            }
            CP_WAIT0();
        }
        __syncthreads();
    }

    // epilogue
    #pragma unroll
    for (int mt = 0; mt < 2; mt++) {
        #pragma unroll
        for (int nt = 0; nt < 8; nt++) {
            int row = blockM + wm * 32 + mt * 16 + (lane >> 2);
            int col = blockN + wn * 64 + nt * 8 + (lane & 3) * 2;
            float2 v0 = make_float2(acc[mt][nt][0], acc[mt][nt][1]);
            float2 v1 = make_float2(acc[mt][nt][2], acc[mt][nt][3]);
            if (BIAS) {
                float2 bv = *(const float2*)(bias + col);
                v0.x += bv.x; v0.y += bv.y;
                v1.x += bv.x; v1.y += bv.y;
            }
            if (RELU) {
                v0.x = fmaxf(v0.x, 0.f); v0.y = fmaxf(v0.y, 0.f);
                v1.x = fmaxf(v1.x, 0.f); v1.y = fmaxf(v1.y, 0.f);
            }
            if (row < M)     *(float2*)(C + (size_t)row * N + col) = v0;
            if (row + 8 < M) *(float2*)(C + (size_t)(row + 8) * N + col) = v1;
        }
    }
}

// ---------------- GEMV kernels ----------------
__global__ void gemv_kernel(const float* __restrict__ A, const float* __restrict__ v,
                            float* __restrict__ out, int M, int K)
{
    int row = blockIdx.x * (blockDim.x >> 5) + (threadIdx.x >> 5);
    int lane = threadIdx.x & 31;
    if (row >= M) return;
    const float4* a4 = (const float4*)(A + (size_t)row * K);
    const float4* v4 = (const float4*)v;
    int K4 = K >> 2;
    float sum = 0.f;
    for (int k = lane; k < K4; k += 32) {
        float4 a = a4[k], b = v4[k];
        sum += a.x * b.x + a.y * b.y + a.z * b.z + a.w * b.w;
    }
    #pragma unroll
    for (int o = 16; o; o >>= 1) sum += __shfl_down_sync(0xffffffffu, sum, o);
    if (lane == 0) out[row] = sum;
}

__global__ void gemv2_kernel(const float* __restrict__ A,
                             const float* __restrict__ va, const float* __restrict__ vb,
                             float* __restrict__ oa, float* __restrict__ ob, int M, int K)
{
    int row = blockIdx.x * (blockDim.x >> 5) + (threadIdx.x >> 5);
    int lane = threadIdx.x & 31;
    if (row >= M) return;
    const float4* a4 = (const float4*)(A + (size_t)row * K);
    const float4* va4 = (const float4*)va;
    const float4* vb4 = (const float4*)vb;
    int K4 = K >> 2;
    float sa = 0.f, sb = 0.f;
    for (int k = lane; k < K4; k += 32) {
        float4 a = a4[k], u = va4[k], t = vb4[k];
        sa += a.x * u.x + a.y * u.y + a.z * u.z + a.w * u.w;
        sb += a.x * t.x + a.y * t.y + a.z * t.z + a.w * t.w;
    }
    #pragma unroll
    for (int o = 16; o; o >>= 1) {
        sa += __shfl_down_sync(0xffffffffu, sa, o);
        sb += __shfl_down_sync(0xffffffffu, sb, o);
    }
    if (lane == 0) { oa[row] = sa; ob[row] = sb; }
}

// ---------------- CSR build kernels ----------------
__global__ void zero_int_kernel(int* __restrict__ p, int n)
{
    int i = blockIdx.x * blockDim.x + threadIdx.x;
    if (i < n) p[i] = 0;
}
__global__ void zero_f_kernel(float* __restrict__ p, int n)
{
    int i = blockIdx.x * blockDim.x + threadIdx.x;
    if (i < n) p[i] = 0.f;
}
__global__ void hist_kernel(const int* __restrict__ dst, int* __restrict__ cnt, int E)
{
    int i = blockIdx.x * blockDim.x + threadIdx.x;
    if (i < E) atomicAdd(&cnt[dst[i]], 1);
}
__global__ void scan1_kernel(const int* __restrict__ cnt, int* __restrict__ rowptr,
                             int* __restrict__ bsum, int n)
{
    __shared__ int sm[512];
    int t = threadIdx.x;
    int idx = blockIdx.x * 512 + t;
    int v = (idx < n) ? cnt[idx] : 0;
    sm[t] = v;
    __syncthreads();
    for (int o = 1; o < 512; o <<= 1) {
        int a = (t >= o) ? sm[t - o] : 0;
        __syncthreads();
        sm[t] += a;
        __syncthreads();
    }
    if (idx < n) rowptr[idx + 1] = sm[t];
    if (t == 511) bsum[blockIdx.x] = sm[511];
}
__global__ void scan2_kernel(const int* __restrict__ bsum, int* __restrict__ boff, int nb)
{
    __shared__ int sm[128];
    int t = threadIdx.x;
    int v = (t < nb) ? bsum[t] : 0;
    sm[t] = v;
    __syncthreads();
    for (int o = 1; o < 128; o <<= 1) {
        int a = (t >= o) ? sm[t - o] : 0;
        __syncthreads();
        sm[t] += a;
        __syncthreads();
    }
    boff[t] = sm[t] - v;     // exclusive
}
__global__ void scan3_kernel(int* __restrict__ rowptr, const int* __restrict__ boff, int n)
{
    int idx = blockIdx.x * 512 + threadIdx.x;
    if (idx < n) rowptr[idx + 1] += boff[blockIdx.x];
    if (idx == 0) rowptr[0] = 0;
}
__global__ void copy_int_kernel(int* __restrict__ d, const int* __restrict__ s, int n)
{
    int i = blockIdx.x * blockDim.x + threadIdx.x;
    if (i < n) d[i] = s[i];
}
__global__ void fill_kernel(const int* __restrict__ src, const int* __restrict__ dst,
                            int* __restrict__ pos, int* __restrict__ perm,
                            int* __restrict__ csrc, int E)
{
    int i = blockIdx.x * blockDim.x + threadIdx.x;
    if (i >= E) return;
    int slot = atomicAdd(&pos[dst[i]], 1);
    perm[i] = slot;
    csrc[slot] = src[i];
}

// ---------------- edge alpha, both lists in one kernel ----------------
__global__ void alpha_both_kernel(const int* __restrict__ src1, const int* __restrict__ dst1,
                                  const int* __restrict__ src2, const int* __restrict__ dst2,
                                  const float* __restrict__ as_, const float* __restrict__ ad_,
                                  const int* __restrict__ perm, float* __restrict__ cw,
                                  float* __restrict__ s, int E)
{
    int i = blockIdx.x * blockDim.x + threadIdx.x;
    if (i >= 2 * E) return;
    int l = (i >= E) ? 1 : 0;
    int j = i - l * E;
    const int* sp = l ? src2 : src1;
    const int* dp = l ? dst2 : dst1;
    int sn = sp[j], dn = dp[j];
    float v = as_[sn] + ad_[dn];
    v = v > 0.f ? v : 0.2f * v;          // leaky_relu, slope 0.2
    float ex = expf(v);
    cw[(size_t)l * EE + perm[(size_t)l * EE + j]] = ex;
    atomicAdd(&s[(size_t)l * NN + dn], ex);
}

// ---------------- per-node CSR aggregation (both lists), out = 2*bias + sums ----------------
// 4-way neighbor batching: issue 4 independent gathers before accumulating (MLP).
template<int C>
__global__ void agg_kernel(const int* __restrict__ rp1, const int* __restrict__ cs1,
                           const float* __restrict__ cw1, const float* __restrict__ s1,
                           const int* __restrict__ rp2, const int* __restrict__ cs2,
                           const float* __restrict__ cw2, const float* __restrict__ s2,
                           const float* __restrict__ h, const float* __restrict__ bias,
                           float* __restrict__ out)
{
    int n = blockIdx.x;
    int c = threadIdx.x * 4;
    float4 b4 = *(const float4*)(bias + c);
    float4 acc = make_float4(2.f * b4.x, 2.f * b4.y, 2.f * b4.z, 2.f * b4.w);

    #pragma unroll
    for (int li = 0; li < 2; li++) {
        const int* rp = li ? rp2 : rp1;
        const int* cs = li ? cs2 : cs1;
        const float* cwp = li ? cw2 : cw1;
        const float* sp = li ? s2 : s1;

        int st = rp[n], en = rp[n + 1];
        float inv = 1.f / (sp[n] + 1e-16f);
        int j = st;
        for (; j + 4 <= en; j += 4) {
            int i0 = cs[j], i1 = cs[j + 1], i2 = cs[j + 2], i3 = cs[j + 3];
            float w0 = cwp[j] * inv, w1 = cwp[j + 1] * inv;
            float w2 = cwp[j + 2] * inv, w3 = cwp[j + 3] * inv;
            float4 h0 = *(const float4*)(h + (size_t)i0 * C + c);
            float4 h1 = *(const float4*)(h + (size_t)i1 * C + c);
            float4 h2 = *(const float4*)(h + (size_t)i2 * C + c);
            float4 h3 = *(const float4*)(h + (size_t)i3 * C + c);
            acc.x += w0 * h0.x + w1 * h1.x + w2 * h2.x + w3 * h3.x;
            acc.y += w0 * h0.y + w1 * h1.y + w2 * h2.y + w3 * h3.y;
            acc.z += w0 * h0.z + w1 * h1.z + w2 * h2.z + w3 * h3.z;
            acc.w += w0 * h0.w + w1 * h1.w + w2 * h2.w + w3 * h3.w;
        }
        for (; j < en; j++) {
            float wv = cwp[j] * inv;
            float4 hv = *(const float4*)(h + (size_t)cs[j] * C + c);
            acc.x += wv * hv.x; acc.y += wv * hv.y;
            acc.z += wv * hv.z; acc.w += wv * hv.w;
        }
    }
    *(float4*)(out + (size_t)n * C + c) = acc;
}

// ---------------- host orchestration ----------------
static void* symaddr(const void* s)
{
    void* p = nullptr;
    cudaGetSymbolAddress(&p, s);
    return p;
}

extern "C" void kernel_launch(void* const* d_in, const int* in_sizes, int n_in,
                              void* d_out, int out_size)
{
    (void)n_in; (void)out_size;
    const float* x   = (const float*)d_in[0];
    const int*   ei1 = (const int*)d_in[1];
    const int*   ei2 = (const int*)d_in[2];
    const float* W1s = (const float*)d_in[3];
    const float* W1d = (const float*)d_in[4];
    const float* a1s = (const float*)d_in[5];
    const float* a1d = (const float*)d_in[6];
    const float* b1  = (const float*)d_in[7];
    const float* Wl1 = (const float*)d_in[8];
    const float* bl1 = (const float*)d_in[9];
    const float* W2s = (const float*)d_in[10];
    const float* W2d = (const float*)d_in[11];
    const float* a2s = (const float*)d_in[12];
    const float* a2d = (const float*)d_in[13];
    const float* b2  = (const float*)d_in[14];
    const float* Wl2 = (const float*)d_in[15];
    const float* bl2 = (const float*)d_in[16];
    float* out = (float*)d_out;

    const int N = in_sizes[0] / DD;       // 50000
    const int E = in_sizes[1] / 2;        // 150000

    float* hsrc = (float*)symaddr(g_hsrc);
    float* agg  = (float*)symaddr(g_agg);
    float* hmid = (float*)symaddr(g_hmid);
    float* asrc = (float*)symaddr(g_asrc);
    float* adst = (float*)symaddr(g_adst);
    float* sbuf = (float*)symaddr(g_s);          // [4][NN]
    float* wa   = (float*)symaddr(g_wa);         // [2][DD]
    float* wb   = (float*)symaddr(g_wb);         // [2][DD]
    int* rowptr = (int*)symaddr(g_rowptr);
    int* pos    = (int*)symaddr(g_pos);
    int* perm   = (int*)symaddr(g_perm);
    int* csrc   = (int*)symaddr(g_csrc);
    float* cw   = (float*)symaddr(g_cw);
    int* bsum   = (int*)symaddr(g_bsum);
    int* boff   = (int*)symaddr(g_boff);
    __nv_bfloat16* whi = (__nv_bfloat16*)symaddr(g_whi);
    __nv_bfloat16* wlo = (__nv_bfloat16*)symaddr(g_wlo);

    const int NB = (NN + 511) / 512;
    const int* srcp1 = ei1;            const int* dstp1 = ei1 + E;
    const int* srcp2 = ei2;            const int* dstp2 = ei2 + E;

    static cudaStream_t sB = nullptr, sC = nullptr;
    static cudaEvent_t ev0, evB, evC1, ev1, evC2;
    if (!sB) {
        cudaStreamCreateWithFlags(&sB, cudaStreamNonBlocking);
        cudaStreamCreateWithFlags(&sC, cudaStreamNonBlocking);
        cudaEventCreateWithFlags(&ev0, cudaEventDisableTiming);
        cudaEventCreateWithFlags(&evB, cudaEventDisableTiming);
        cudaEventCreateWithFlags(&evC1, cudaEventDisableTiming);
        cudaEventCreateWithFlags(&ev1, cudaEventDisableTiming);
        cudaEventCreateWithFlags(&evC2, cudaEventDisableTiming);
        cudaFuncSetAttribute(mma_gemm_kernel<false, false>,
                             cudaFuncAttributeMaxDynamicSharedMemorySize, GDSM);
        cudaFuncSetAttribute(mma_gemm_kernel<true, true>,
                             cudaFuncAttributeMaxDynamicSharedMemorySize, GDSM);
        cudaFuncSetAttribute(mma_gemm_kernel<true, false>,
                             cudaFuncAttributeMaxDynamicSharedMemorySize, GDSM);
    }

    dim3 gH(HH / 128, (N + 127) / 128);
    dim3 gO(OC / 128, (N + 127) / 128);

    // ===== fork =====
    cudaEventRecord(ev0, 0);
    cudaStreamWaitEvent(sB, ev0, 0);
    cudaStreamWaitEvent(sC, ev0, 0);

    // Submissions 1-3, then GEMM1 as the 4th launch (ncu profile targeting).
    wsplit_kernel<<<(DD * HH / 4 + 255) / 256, 256>>>(W1s, whi + WO1, wlo + WO1, DD * HH / 4);          // 1 (default)
    wsplit_kernel<<<(HH * HH / 4 + 255) / 256, 256, 0, sB>>>(Wl1, whi + WO2, wlo + WO2, HH * HH / 4);   // 2
    wsplit_kernel<<<(HH * OC / 4 + 255) / 256, 256, 0, sB>>>(W2s, whi + WO3, wlo + WO3, HH * OC / 4);   // 3
    mma_gemm_kernel<false, false><<<gH, 256, GDSM>>>(x, whi + WO1, wlo + WO1, nullptr, hsrc, N, HH, DD); // 4 <- profile target

    // ----- stream B: remaining setup (CSR build etc.) -----
    wsplit_kernel<<<(OC * OC / 4 + 255) / 256, 256, 0, sB>>>(Wl2, whi + WO4, wlo + WO4, OC * OC / 4);
    gemv_kernel<<<(HH + 7) / 8, 256, 0, sB>>>(W2s, a2s, wa + DD, HH, OC);
    gemv_kernel<<<(HH + 7) / 8, 256, 0, sB>>>(W2d, a2d, wb + DD, HH, OC);
    zero_f_kernel<<<(4 * NN + 255) / 256, 256, 0, sB>>>(sbuf, 4 * NN);
    zero_int_kernel<<<(2 * NN + 255) / 256, 256, 0, sB>>>(pos, 2 * NN);
    for (int l = 0; l < 2; l++) {
        const int* dstp = l ? dstp2 : dstp1;
        const int* srcp = l ? srcp2 : srcp1;
        int* cnt_l = pos + l * NN;
        int* rp_l  = rowptr + l * (NN + 1);
        hist_kernel<<<(E + 255) / 256, 256, 0, sB>>>(dstp, cnt_l, E);
        scan1_kernel<<<NB, 512, 0, sB>>>(cnt_l, rp_l, bsum + l * 128, N);
        scan2_kernel<<<1, 128, 0, sB>>>(bsum + l * 128, boff + l * 128, NB);
        scan3_kernel<<<NB, 512, 0, sB>>>(rp_l, boff + l * 128, N);
        copy_int_kernel<<<(NN + 255) / 256, 256, 0, sB>>>(cnt_l, rp_l, N);
        fill_kernel<<<(E + 255) / 256, 256, 0, sB>>>(srcp, dstp, cnt_l, perm + l * EE, csrc + l * EE, E);
    }
    cudaEventRecord(evB, sB);

    // ----- stream C: L1 weight gemvs + node alphas from x + L1 edge alphas -----
    gemv_kernel<<<(DD + 7) / 8, 256, 0, sC>>>(W1s, a1s, wa, DD, HH);
    gemv_kernel<<<(DD + 7) / 8, 256, 0, sC>>>(W1d, a1d, wb, DD, HH);
    gemv2_kernel<<<(N + 7) / 8, 256, 0, sC>>>(x, wa, wb, asrc, adst, N, DD);
    cudaStreamWaitEvent(sC, evB, 0);
    alpha_both_kernel<<<(2 * E + 255) / 256, 256, 0, sC>>>(srcp1, dstp1, srcp2, dstp2,
                                                           asrc, adst, perm, cw, sbuf, E);
    cudaEventRecord(evC1, sC);

    // ----- default stream: critical chain -----
    cudaStreamWaitEvent(0, evC1, 0);
    agg_kernel<HH><<<N, HH / 4>>>(rowptr, csrc, cw, sbuf,
                                  rowptr + (NN + 1), csrc + EE, cw + EE, sbuf + NN,
                                  hsrc, b1, agg);
    mma_gemm_kernel<true, true><<<gH, 256, GDSM>>>(agg, whi + WO2, wlo + WO2, bl1, hmid, N, HH, HH);

    // fork: layer-2 node/edge alphas overlap GEMM2
    cudaEventRecord(ev1, 0);
    cudaStreamWaitEvent(sC, ev1, 0);
    gemv2_kernel<<<(N + 7) / 8, 256, 0, sC>>>(hmid, wa + DD, wb + DD, asrc, adst, N, HH);
    alpha_both_kernel<<<(2 * E + 255) / 256, 256, 0, sC>>>(srcp1, dstp1, srcp2, dstp2,
                                                           asrc, adst, perm, cw, sbuf + 2 * NN, E);
    cudaEventRecord(evC2, sC);

    mma_gemm_kernel<false, false><<<gO, 256, GDSM>>>(hmid, whi + WO3, wlo + WO3, nullptr, hsrc, N, OC, HH);

    cudaStreamWaitEvent(0, evC2, 0);
    agg_kernel<OC><<<N, OC / 4>>>(rowptr, csrc, cw, sbuf + 2 * NN,
                                  rowptr + (NN + 1), csrc + EE, cw + EE, sbuf + 3 * NN,
                                  hsrc, b2, agg);
    mma_gemm_kernel<true, false><<<gO, 256, GDSM>>>(agg, whi + WO4, wlo + WO4, bl2, out, N, OC, OC);
}

// round 15
// speedup vs baseline: 1.8832x; 1.1377x over previous
#include <cuda_runtime.h>
#include <cuda_bf16.h>
#include <math_constants.h>
#include <cstdint>

// Problem constants (fixed by the reference setup)
#define NN  50000
#define DD  512
#define HH  512
#define OC  256
#define EE  150000

// ---------------- scratch (no allocation allowed -> __device__ globals) ----------------
__device__ float g_hsrc[(size_t)NN * HH];   // layer1: [N,512]; layer2 reuse: [N,256]
__device__ float g_agg [(size_t)NN * HH];   // conv accumulator
__device__ float g_hmid[(size_t)NN * HH];   // after lin1
__device__ float g_asrc[NN];
__device__ float g_adst[NN];
__device__ float g_s[4][NN];                // per-layer, per-list softmax sums
__device__ float g_wa[2][DD];
__device__ float g_wb[2][DD];

// CSR structures (built once per launch; shared by both layers)
__device__ int   g_rowptr[2][NN + 1];
__device__ int   g_pos[2][NN];              // histogram, then fill cursor
__device__ int   g_perm[2][EE];             // edge -> csr slot
__device__ int   g_csrc[2][EE];             // csr: source node per slot
__device__ float g_cw[2][EE];               // csr: exp(e) per slot (per layer)
__device__ int   g_bsum[2][128];
__device__ int   g_boff[2][128];

// pre-split weights, [K,N] fp32 layout -> bf16 hi/lo (same layout)
#define WO1 0
#define WO2 262144
#define WO3 524288
#define WO4 655360
#define WTOT 720896
__device__ __nv_bfloat16 g_whi[WTOT];
__device__ __nv_bfloat16 g_wlo[WTOT];

// ==================== weight bf16 hi/lo split (elementwise, float4) ====================
__global__ void wsplit_kernel(const float* __restrict__ W,
                              __nv_bfloat16* __restrict__ hi, __nv_bfloat16* __restrict__ lo,
                              int total4)
{
    int i = blockIdx.x * blockDim.x + threadIdx.x;
    if (i >= total4) return;
    float4 v = ((const float4*)W)[i];
    __nv_bfloat162 h0 = __floats2bfloat162_rn(v.x, v.y);
    float2 f0 = __bfloat1622float2(h0);
    __nv_bfloat162 l0 = __floats2bfloat162_rn(v.x - f0.x, v.y - f0.y);
    __nv_bfloat162 h1 = __floats2bfloat162_rn(v.z, v.w);
    float2 f1 = __bfloat1622float2(h1);
    __nv_bfloat162 l1 = __floats2bfloat162_rn(v.z - f1.x, v.w - f1.y);
    uint2 hh, ll;
    hh.x = reinterpret_cast<uint32_t&>(h0); hh.y = reinterpret_cast<uint32_t&>(h1);
    ll.x = reinterpret_cast<uint32_t&>(l0); ll.y = reinterpret_cast<uint32_t&>(l1);
    ((uint2*)hi)[i] = hh;
    ((uint2*)lo)[i] = ll;
}

// ==================== tensor-core GEMM (mma.sync, 3-term bf16 split) ====================
#define LDM4(r0,r1,r2,r3,addr) \
    asm volatile("ldmatrix.sync.aligned.m8n8.x4.shared.b16 {%0,%1,%2,%3}, [%4];" \
                 : "=r"(r0),"=r"(r1),"=r"(r2),"=r"(r3) : "r"(addr))
#define LDM4T(r0,r1,r2,r3,addr) \
    asm volatile("ldmatrix.sync.aligned.m8n8.x4.trans.shared.b16 {%0,%1,%2,%3}, [%4];" \
                 : "=r"(r0),"=r"(r1),"=r"(r2),"=r"(r3) : "r"(addr))
#define MMA16816(d, a, b) \
    asm volatile("mma.sync.aligned.m16n8k16.row.col.f32.bf16.bf16.f32 " \
                 "{%0,%1,%2,%3},{%4,%5,%6,%7},{%8,%9},{%0,%1,%2,%3};" \
                 : "+f"(d[0]),"+f"(d[1]),"+f"(d[2]),"+f"(d[3]) \
                 : "r"(a[0]),"r"(a[1]),"r"(a[2]),"r"(a[3]),"r"(b[0]),"r"(b[1]))
#define CP_ASYNC16(dst, src) \
    asm volatile("cp.async.ca.shared.global [%0], [%1], 16;" :: "r"(dst), "l"(src) : "memory")
#define CP_COMMIT()  asm volatile("cp.async.commit_group;" ::: "memory")
#define CP_WAIT0()   asm volatile("cp.async.wait_group 0;" ::: "memory")

__device__ __forceinline__ uint32_t smem_u32(const void* p)
{
    return (uint32_t)__cvta_generic_to_shared(p);
}

__device__ __forceinline__ void split2(__nv_bfloat16* hp, __nv_bfloat16* lp, float x, float y)
{
    __nv_bfloat162 h = __floats2bfloat162_rn(x, y);
    float2 hf = __bfloat1622float2(h);
    __nv_bfloat162 l = __floats2bfloat162_rn(x - hf.x, y - hf.y);
    *(__nv_bfloat162*)hp = h;
    *(__nv_bfloat162*)lp = l;
}

// dynamic-smem stage layout (bytes)
#define GA_HI 0
#define GA_LO 10240
#define GB_HI 20480
#define GB_LO 29184
#define GSTAGE 37888
#define GDSM (2 * GSTAGE)

// C = A[MxK](fp32, split on the fly) @ B[KxN](pre-split bf16 hi/lo) (+bias)(+relu)
// Double-buffered SMEM: B via cp.async, A via register prefetch; 1 sync per K-tile.
// __launch_bounds__(256, 2): cap regs at 128 so 2 CTAs/SM co-reside (R14 ncu: 133 regs -> occ 12.4%).
template<bool BIAS, bool RELU>
__global__ __launch_bounds__(256, 2)
void mma_gemm_kernel(const float* __restrict__ A,
                     const __nv_bfloat16* __restrict__ Bhi,
                     const __nv_bfloat16* __restrict__ Blo,
                     const float* __restrict__ bias, float* __restrict__ C,
                     int M, int N, int K)
{
    const int BM = 128, BN = 128, BK = 32;
    const int ASTR = 40;      // A row stride (elements): BK + 8 pad
    const int BSTR = 136;     // B row stride (elements): BN + 8 pad
    extern __shared__ __align__(16) char dsm[];

    int tid = threadIdx.x;
    int lane = tid & 31;
    int w = tid >> 5;
    int wm = w & 3;
    int wn = w >> 2;

    int blockM = blockIdx.y * BM;
    int blockN = blockIdx.x * BN;

    int aRow0 = tid >> 3;          // + 32*i
    int aCol  = (tid & 7) * 4;
    // B tile: 32 rows x 128 cols = 512 uint4-groups of 8 bf16; 2 groups per thread
    int bR[2], bC[2];
    #pragma unroll
    for (int i = 0; i < 2; i++) {
        int g = tid + 256 * i;
        bR[i] = g >> 4;            // 0..31
        bC[i] = (g & 15) * 8;      // 0..120
    }

    const float4 z4 = make_float4(0.f, 0.f, 0.f, 0.f);
    float4 pa[4];

    float acc[2][8][4];
    #pragma unroll
    for (int mt = 0; mt < 2; mt++)
        #pragma unroll
        for (int nt = 0; nt < 8; nt++)
            #pragma unroll
            for (int q = 0; q < 4; q++) acc[mt][nt][q] = 0.f;

    const uint32_t smBase = smem_u32(dsm);

    // ---- prologue: tile 0 into stage 0 ----
    #pragma unroll
    for (int i = 0; i < 2; i++) {
        uint32_t so = (uint32_t)(bR[i] * BSTR + bC[i]) * 2u;
        size_t go = (size_t)bR[i] * N + blockN + bC[i];
        CP_ASYNC16(smBase + GB_HI + so, Bhi + go);
        CP_ASYNC16(smBase + GB_LO + so, Blo + go);
    }
    CP_COMMIT();
    #pragma unroll
    for (int i = 0; i < 4; i++) {
        int r = blockM + aRow0 + 32 * i;
        pa[i] = (r < M) ? *(const float4*)(A + (size_t)r * K + aCol) : z4;
    }
    #pragma unroll
    for (int i = 0; i < 4; i++) {
        int r = aRow0 + 32 * i;
        __nv_bfloat16* hp = (__nv_bfloat16*)(dsm + GA_HI + (r * ASTR + aCol) * 2);
        __nv_bfloat16* lp = (__nv_bfloat16*)(dsm + GA_LO + (r * ASTR + aCol) * 2);
        split2(hp,     lp,     pa[i].x, pa[i].y);
        split2(hp + 2, lp + 2, pa[i].z, pa[i].w);
    }
    CP_WAIT0();
    __syncthreads();

    int nT = K / BK;
    for (int kt = 0; kt < nT; kt++) {
        uint32_t cur = (uint32_t)(kt & 1) * GSTAGE;
        uint32_t nxt = cur ^ GSTAGE;

        // prefetch next tile: B via cp.async into nxt, A into registers
        if (kt + 1 < nT) {
            #pragma unroll
            for (int i = 0; i < 2; i++) {
                uint32_t so = (uint32_t)(bR[i] * BSTR + bC[i]) * 2u;
                size_t go = (size_t)((kt + 1) * BK + bR[i]) * N + blockN + bC[i];
                CP_ASYNC16(smBase + nxt + GB_HI + so, Bhi + go);
                CP_ASYNC16(smBase + nxt + GB_LO + so, Blo + go);
            }
            CP_COMMIT();
            #pragma unroll
            for (int i = 0; i < 4; i++) {
                int r = blockM + aRow0 + 32 * i;
                pa[i] = (r < M) ? *(const float4*)(A + (size_t)r * K + (kt + 1) * BK + aCol) : z4;
            }
        }

        // compute on cur
        #pragma unroll
        for (int ks = 0; ks < 2; ks++) {
            uint32_t ah[2][4], al[2][4];
            #pragma unroll
            for (int mt = 0; mt < 2; mt++) {
                uint32_t off = (uint32_t)((wm * 32 + mt * 16 + (lane & 15)) * ASTR
                                          + (lane >> 4) * 8 + ks * 16) * 2u;
                LDM4(ah[mt][0], ah[mt][1], ah[mt][2], ah[mt][3], smBase + cur + GA_HI + off);
                LDM4(al[mt][0], al[mt][1], al[mt][2], al[mt][3], smBase + cur + GA_LO + off);
            }
            uint32_t bh[8][2], bl[8][2];
            #pragma unroll
            for (int p = 0; p < 4; p++) {
                uint32_t off = (uint32_t)((ks * 16 + (lane & 15)) * BSTR
                                          + wn * 64 + p * 16 + ((lane & 16) >> 1)) * 2u;
                uint32_t r0, r1, r2, r3;
                LDM4T(r0, r1, r2, r3, smBase + cur + GB_HI + off);
                bh[2 * p][0] = r0; bh[2 * p][1] = r1;
                bh[2 * p + 1][0] = r2; bh[2 * p + 1][1] = r3;
                LDM4T(r0, r1, r2, r3, smBase + cur + GB_LO + off);
                bl[2 * p][0] = r0; bl[2 * p][1] = r1;
                bl[2 * p + 1][0] = r2; bl[2 * p + 1][1] = r3;
            }
            #pragma unroll
            for (int mt = 0; mt < 2; mt++)
                #pragma unroll
                for (int nt = 0; nt < 8; nt++) {
                    MMA16816(acc[mt][nt], ah[mt], bh[nt]);
                    MMA16816(acc[mt][nt], ah[mt], bl[nt]);
                    MMA16816(acc[mt][nt], al[mt], bh[nt]);
                }
        }

        if (kt + 1 < nT) {
            // split-store A into nxt, then drain cp.async before the sync
            #pragma unroll
            for (int i = 0; i < 4; i++) {
                int r = aRow0 + 32 * i;
                __nv_bfloat16* hp = (__nv_bfloat16*)(dsm + nxt + GA_HI + (r * ASTR + aCol) * 2);
                __nv_bfloat16* lp = (__nv_bfloat16*)(dsm + nxt + GA_LO + (r * ASTR + aCol) * 2);
                split2(hp,     lp,     pa[i].x, pa[i].y);
                split2(hp + 2, lp + 2, pa[i].z, pa[i].w);
            }
            CP_WAIT0();
        }
        __syncthreads();
    }

    // epilogue
    #pragma unroll
    for (int mt = 0; mt < 2; mt++) {
        #pragma unroll
        for (int nt = 0; nt < 8; nt++) {
            int row = blockM + wm * 32 + mt * 16 + (lane >> 2);
            int col = blockN + wn * 64 + nt * 8 + (lane & 3) * 2;
            float2 v0 = make_float2(acc[mt][nt][0], acc[mt][nt][1]);
            float2 v1 = make_float2(acc[mt][nt][2], acc[mt][nt][3]);
            if (BIAS) {
                float2 bv = *(const float2*)(bias + col);
                v0.x += bv.x; v0.y += bv.y;
                v1.x += bv.x; v1.y += bv.y;
            }
            if (RELU) {
                v0.x = fmaxf(v0.x, 0.f); v0.y = fmaxf(v0.y, 0.f);
                v1.x = fmaxf(v1.x, 0.f); v1.y = fmaxf(v1.y, 0.f);
            }
            if (row < M)     *(float2*)(C + (size_t)row * N + col) = v0;
            if (row + 8 < M) *(float2*)(C + (size_t)(row + 8) * N + col) = v1;
        }
    }
}

// ---------------- GEMV kernels ----------------
__global__ void gemv_kernel(const float* __restrict__ A, const float* __restrict__ v,
                            float* __restrict__ out, int M, int K)
{
    int row = blockIdx.x * (blockDim.x >> 5) + (threadIdx.x >> 5);
    int lane = threadIdx.x & 31;
    if (row >= M) return;
    const float4* a4 = (const float4*)(A + (size_t)row * K);
    const float4* v4 = (const float4*)v;
    int K4 = K >> 2;
    float sum = 0.f;
    for (int k = lane; k < K4; k += 32) {
        float4 a = a4[k], b = v4[k];
        sum += a.x * b.x + a.y * b.y + a.z * b.z + a.w * b.w;
    }
    #pragma unroll
    for (int o = 16; o; o >>= 1) sum += __shfl_down_sync(0xffffffffu, sum, o);
    if (lane == 0) out[row] = sum;
}

__global__ void gemv2_kernel(const float* __restrict__ A,
                             const float* __restrict__ va, const float* __restrict__ vb,
                             float* __restrict__ oa, float* __restrict__ ob, int M, int K)
{
    int row = blockIdx.x * (blockDim.x >> 5) + (threadIdx.x >> 5);
    int lane = threadIdx.x & 31;
    if (row >= M) return;
    const float4* a4 = (const float4*)(A + (size_t)row * K);
    const float4* va4 = (const float4*)va;
    const float4* vb4 = (const float4*)vb;
    int K4 = K >> 2;
    float sa = 0.f, sb = 0.f;
    for (int k = lane; k < K4; k += 32) {
        float4 a = a4[k], u = va4[k], t = vb4[k];
        sa += a.x * u.x + a.y * u.y + a.z * u.z + a.w * u.w;
        sb += a.x * t.x + a.y * t.y + a.z * t.z + a.w * t.w;
    }
    #pragma unroll
    for (int o = 16; o; o >>= 1) {
        sa += __shfl_down_sync(0xffffffffu, sa, o);
        sb += __shfl_down_sync(0xffffffffu, sb, o);
    }
    if (lane == 0) { oa[row] = sa; ob[row] = sb; }
}

// ---------------- CSR build kernels ----------------
__global__ void zero_int_kernel(int* __restrict__ p, int n)
{
    int i = blockIdx.x * blockDim.x + threadIdx.x;
    if (i < n) p[i] = 0;
}
__global__ void zero_f_kernel(float* __restrict__ p, int n)
{
    int i = blockIdx.x * blockDim.x + threadIdx.x;
    if (i < n) p[i] = 0.f;
}
__global__ void hist_kernel(const int* __restrict__ dst, int* __restrict__ cnt, int E)
{
    int i = blockIdx.x * blockDim.x + threadIdx.x;
    if (i < E) atomicAdd(&cnt[dst[i]], 1);
}
__global__ void scan1_kernel(const int* __restrict__ cnt, int* __restrict__ rowptr,
                             int* __restrict__ bsum, int n)
{
    __shared__ int sm[512];
    int t = threadIdx.x;
    int idx = blockIdx.x * 512 + t;
    int v = (idx < n) ? cnt[idx] : 0;
    sm[t] = v;
    __syncthreads();
    for (int o = 1; o < 512; o <<= 1) {
        int a = (t >= o) ? sm[t - o] : 0;
        __syncthreads();
        sm[t] += a;
        __syncthreads();
    }
    if (idx < n) rowptr[idx + 1] = sm[t];
    if (t == 511) bsum[blockIdx.x] = sm[511];
}
__global__ void scan2_kernel(const int* __restrict__ bsum, int* __restrict__ boff, int nb)
{
    __shared__ int sm[128];
    int t = threadIdx.x;
    int v = (t < nb) ? bsum[t] : 0;
    sm[t] = v;
    __syncthreads();
    for (int o = 1; o < 128; o <<= 1) {
        int a = (t >= o) ? sm[t - o] : 0;
        __syncthreads();
        sm[t] += a;
        __syncthreads();
    }
    boff[t] = sm[t] - v;     // exclusive
}
__global__ void scan3_kernel(int* __restrict__ rowptr, const int* __restrict__ boff, int n)
{
    int idx = blockIdx.x * 512 + threadIdx.x;
    if (idx < n) rowptr[idx + 1] += boff[blockIdx.x];
    if (idx == 0) rowptr[0] = 0;
}
__global__ void copy_int_kernel(int* __restrict__ d, const int* __restrict__ s, int n)
{
    int i = blockIdx.x * blockDim.x + threadIdx.x;
    if (i < n) d[i] = s[i];
}
__global__ void fill_kernel(const int* __restrict__ src, const int* __restrict__ dst,
                            int* __restrict__ pos, int* __restrict__ perm,
                            int* __restrict__ csrc, int E)
{
    int i = blockIdx.x * blockDim.x + threadIdx.x;
    if (i >= E) return;
    int slot = atomicAdd(&pos[dst[i]], 1);
    perm[i] = slot;
    csrc[slot] = src[i];
}

// ---------------- edge alpha, both lists in one kernel ----------------
__global__ void alpha_both_kernel(const int* __restrict__ src1, const int* __restrict__ dst1,
                                  const int* __restrict__ src2, const int* __restrict__ dst2,
                                  const float* __restrict__ as_, const float* __restrict__ ad_,
                                  const int* __restrict__ perm, float* __restrict__ cw,
                                  float* __restrict__ s, int E)
{
    int i = blockIdx.x * blockDim.x + threadIdx.x;
    if (i >= 2 * E) return;
    int l = (i >= E) ? 1 : 0;
    int j = i - l * E;
    const int* sp = l ? src2 : src1;
    const int* dp = l ? dst2 : dst1;
    int sn = sp[j], dn = dp[j];
    float v = as_[sn] + ad_[dn];
    v = v > 0.f ? v : 0.2f * v;          // leaky_relu, slope 0.2
    float ex = expf(v);
    cw[(size_t)l * EE + perm[(size_t)l * EE + j]] = ex;
    atomicAdd(&s[(size_t)l * NN + dn], ex);
}

// ---------------- per-node CSR aggregation (both lists), out = 2*bias + sums ----------------
// 4-way neighbor batching: issue 4 independent gathers before accumulating (MLP).
template<int C>
__global__ void agg_kernel(const int* __restrict__ rp1, const int* __restrict__ cs1,
                           const float* __restrict__ cw1, const float* __restrict__ s1,
                           const int* __restrict__ rp2, const int* __restrict__ cs2,
                           const float* __restrict__ cw2, const float* __restrict__ s2,
                           const float* __restrict__ h, const float* __restrict__ bias,
                           float* __restrict__ out)
{
    int n = blockIdx.x;
    int c = threadIdx.x * 4;
    float4 b4 = *(const float4*)(bias + c);
    float4 acc = make_float4(2.f * b4.x, 2.f * b4.y, 2.f * b4.z, 2.f * b4.w);

    #pragma unroll
    for (int li = 0; li < 2; li++) {
        const int* rp = li ? rp2 : rp1;
        const int* cs = li ? cs2 : cs1;
        const float* cwp = li ? cw2 : cw1;
        const float* sp = li ? s2 : s1;

        int st = rp[n], en = rp[n + 1];
        float inv = 1.f / (sp[n] + 1e-16f);
        int j = st;
        for (; j + 4 <= en; j += 4) {
            int i0 = cs[j], i1 = cs[j + 1], i2 = cs[j + 2], i3 = cs[j + 3];
            float w0 = cwp[j] * inv, w1 = cwp[j + 1] * inv;
            float w2 = cwp[j + 2] * inv, w3 = cwp[j + 3] * inv;
            float4 h0 = *(const float4*)(h + (size_t)i0 * C + c);
            float4 h1 = *(const float4*)(h + (size_t)i1 * C + c);
            float4 h2 = *(const float4*)(h + (size_t)i2 * C + c);
            float4 h3 = *(const float4*)(h + (size_t)i3 * C + c);
            acc.x += w0 * h0.x + w1 * h1.x + w2 * h2.x + w3 * h3.x;
            acc.y += w0 * h0.y + w1 * h1.y + w2 * h2.y + w3 * h3.y;
            acc.z += w0 * h0.z + w1 * h1.z + w2 * h2.z + w3 * h3.z;
            acc.w += w0 * h0.w + w1 * h1.w + w2 * h2.w + w3 * h3.w;
        }
        for (; j < en; j++) {
            float wv = cwp[j] * inv;
            float4 hv = *(const float4*)(h + (size_t)cs[j] * C + c);
            acc.x += wv * hv.x; acc.y += wv * hv.y;
            acc.z += wv * hv.z; acc.w += wv * hv.w;
        }
    }
    *(float4*)(out + (size_t)n * C + c) = acc;
}

// ---------------- host orchestration ----------------
static void* symaddr(const void* s)
{
    void* p = nullptr;
    cudaGetSymbolAddress(&p, s);
    return p;
}

extern "C" void kernel_launch(void* const* d_in, const int* in_sizes, int n_in,
                              void* d_out, int out_size)
{
    (void)n_in; (void)out_size;
    const float* x   = (const float*)d_in[0];
    const int*   ei1 = (const int*)d_in[1];
    const int*   ei2 = (const int*)d_in[2];
    const float* W1s = (const float*)d_in[3];
    const float* W1d = (const float*)d_in[4];
    const float* a1s = (const float*)d_in[5];
    const float* a1d = (const float*)d_in[6];
    const float* b1  = (const float*)d_in[7];
    const float* Wl1 = (const float*)d_in[8];
    const float* bl1 = (const float*)d_in[9];
    const float* W2s = (const float*)d_in[10];
    const float* W2d = (const float*)d_in[11];
    const float* a2s = (const float*)d_in[12];
    const float* a2d = (const float*)d_in[13];
    const float* b2  = (const float*)d_in[14];
    const float* Wl2 = (const float*)d_in[15];
    const float* bl2 = (const float*)d_in[16];
    float* out = (float*)d_out;

    const int N = in_sizes[0] / DD;       // 50000
    const int E = in_sizes[1] / 2;        // 150000

    float* hsrc = (float*)symaddr(g_hsrc);
    float* agg  = (float*)symaddr(g_agg);
    float* hmid = (float*)symaddr(g_hmid);
    float* asrc = (float*)symaddr(g_asrc);
    float* adst = (float*)symaddr(g_adst);
    float* sbuf = (float*)symaddr(g_s);          // [4][NN]
    float* wa   = (float*)symaddr(g_wa);         // [2][DD]
    float* wb   = (float*)symaddr(g_wb);         // [2][DD]
    int* rowptr = (int*)symaddr(g_rowptr);
    int* pos    = (int*)symaddr(g_pos);
    int* perm   = (int*)symaddr(g_perm);
    int* csrc   = (int*)symaddr(g_csrc);
    float* cw   = (float*)symaddr(g_cw);
    int* bsum   = (int*)symaddr(g_bsum);
    int* boff   = (int*)symaddr(g_boff);
    __nv_bfloat16* whi = (__nv_bfloat16*)symaddr(g_whi);
    __nv_bfloat16* wlo = (__nv_bfloat16*)symaddr(g_wlo);

    const int NB = (NN + 511) / 512;
    const int* srcp1 = ei1;            const int* dstp1 = ei1 + E;
    const int* srcp2 = ei2;            const int* dstp2 = ei2 + E;

    static cudaStream_t sB = nullptr, sC = nullptr;
    static cudaEvent_t ev0, evB, evC1, ev1, evC2;
    if (!sB) {
        cudaStreamCreateWithFlags(&sB, cudaStreamNonBlocking);
        cudaStreamCreateWithFlags(&sC, cudaStreamNonBlocking);
        cudaEventCreateWithFlags(&ev0, cudaEventDisableTiming);
        cudaEventCreateWithFlags(&evB, cudaEventDisableTiming);
        cudaEventCreateWithFlags(&evC1, cudaEventDisableTiming);
        cudaEventCreateWithFlags(&ev1, cudaEventDisableTiming);
        cudaEventCreateWithFlags(&evC2, cudaEventDisableTiming);
        cudaFuncSetAttribute(mma_gemm_kernel<false, false>,
                             cudaFuncAttributeMaxDynamicSharedMemorySize, GDSM);
        cudaFuncSetAttribute(mma_gemm_kernel<true, true>,
                             cudaFuncAttributeMaxDynamicSharedMemorySize, GDSM);
        cudaFuncSetAttribute(mma_gemm_kernel<true, false>,
                             cudaFuncAttributeMaxDynamicSharedMemorySize, GDSM);
    }

    dim3 gH(HH / 128, (N + 127) / 128);
    dim3 gO(OC / 128, (N + 127) / 128);

    // ===== fork =====
    cudaEventRecord(ev0, 0);
    cudaStreamWaitEvent(sB, ev0, 0);
    cudaStreamWaitEvent(sC, ev0, 0);

    // Submissions 1-3, then GEMM1 as the 4th launch (ncu profile targeting).
    wsplit_kernel<<<(DD * HH / 4 + 255) / 256, 256>>>(W1s, whi + WO1, wlo + WO1, DD * HH / 4);          // 1 (default)
    wsplit_kernel<<<(HH * HH / 4 + 255) / 256, 256, 0, sB>>>(Wl1, whi + WO2, wlo + WO2, HH * HH / 4);   // 2
    wsplit_kernel<<<(HH * OC / 4 + 255) / 256, 256, 0, sB>>>(W2s, whi + WO3, wlo + WO3, HH * OC / 4);   // 3
    mma_gemm_kernel<false, false><<<gH, 256, GDSM>>>(x, whi + WO1, wlo + WO1, nullptr, hsrc, N, HH, DD); // 4 <- profile target

    // ----- stream B: remaining setup (CSR build etc.) -----
    wsplit_kernel<<<(OC * OC / 4 + 255) / 256, 256, 0, sB>>>(Wl2, whi + WO4, wlo + WO4, OC * OC / 4);
    gemv_kernel<<<(HH + 7) / 8, 256, 0, sB>>>(W2s, a2s, wa + DD, HH, OC);
    gemv_kernel<<<(HH + 7) / 8, 256, 0, sB>>>(W2d, a2d, wb + DD, HH, OC);
    zero_f_kernel<<<(4 * NN + 255) / 256, 256, 0, sB>>>(sbuf, 4 * NN);
    zero_int_kernel<<<(2 * NN + 255) / 256, 256, 0, sB>>>(pos, 2 * NN);
    for (int l = 0; l < 2; l++) {
        const int* dstp = l ? dstp2 : dstp1;
        const int* srcp = l ? srcp2 : srcp1;
        int* cnt_l = pos + l * NN;
        int* rp_l  = rowptr + l * (NN + 1);
        hist_kernel<<<(E + 255) / 256, 256, 0, sB>>>(dstp, cnt_l, E);
        scan1_kernel<<<NB, 512, 0, sB>>>(cnt_l, rp_l, bsum + l * 128, N);
        scan2_kernel<<<1, 128, 0, sB>>>(bsum + l * 128, boff + l * 128, NB);
        scan3_kernel<<<NB, 512, 0, sB>>>(rp_l, boff + l * 128, N);
        copy_int_kernel<<<(NN + 255) / 256, 256, 0, sB>>>(cnt_l, rp_l, N);
        fill_kernel<<<(E + 255) / 256, 256, 0, sB>>>(srcp, dstp, cnt_l, perm + l * EE, csrc + l * EE, E);
    }
    cudaEventRecord(evB, sB);

    // ----- stream C: L1 weight gemvs + node alphas from x + L1 edge alphas -----
    gemv_kernel<<<(DD + 7) / 8, 256, 0, sC>>>(W1s, a1s, wa, DD, HH);
    gemv_kernel<<<(DD + 7) / 8, 256, 0, sC>>>(W1d, a1d, wb, DD, HH);
    gemv2_kernel<<<(N + 7) / 8, 256, 0, sC>>>(x, wa, wb, asrc, adst, N, DD);
    cudaStreamWaitEvent(sC, evB, 0);
    alpha_both_kernel<<<(2 * E + 255) / 256, 256, 0, sC>>>(srcp1, dstp1, srcp2, dstp2,
                                                           asrc, adst, perm, cw, sbuf, E);
    cudaEventRecord(evC1, sC);

    // ----- default stream: critical chain -----
    cudaStreamWaitEvent(0, evC1, 0);
    agg_kernel<HH><<<N, HH / 4>>>(rowptr, csrc, cw, sbuf,
                                  rowptr + (NN + 1), csrc + EE, cw + EE, sbuf + NN,
                                  hsrc, b1, agg);
    mma_gemm_kernel<true, true><<<gH, 256, GDSM>>>(agg, whi + WO2, wlo + WO2, bl1, hmid, N, HH, HH);

    // fork: layer-2 node/edge alphas overlap GEMM2
    cudaEventRecord(ev1, 0);
    cudaStreamWaitEvent(sC, ev1, 0);
    gemv2_kernel<<<(N + 7) / 8, 256, 0, sC>>>(hmid, wa + DD, wb + DD, asrc, adst, N, HH);
    alpha_both_kernel<<<(2 * E + 255) / 256, 256, 0, sC>>>(srcp1, dstp1, srcp2, dstp2,
                                                           asrc, adst, perm, cw, sbuf + 2 * NN, E);
    cudaEventRecord(evC2, sC);

    mma_gemm_kernel<false, false><<<gO, 256, GDSM>>>(hmid, whi + WO3, wlo + WO3, nullptr, hsrc, N, OC, HH);

    cudaStreamWaitEvent(0, evC2, 0);
    agg_kernel<OC><<<N, OC / 4>>>(rowptr, csrc, cw, sbuf + 2 * NN,
                                  rowptr + (NN + 1), csrc + EE, cw + EE, sbuf + 3 * NN,
                                  hsrc, b2, agg);
    mma_gemm_kernel<true, false><<<gO, 256, GDSM>>>(agg, whi + WO4, wlo + WO4, bl2, out, N, OC, OC);
}

// round 16
// speedup vs baseline: 1.9041x; 1.0111x over previous
#include <cuda_runtime.h>
#include <cuda_bf16.h>
#include <math_constants.h>
#include <cstdint>

// Problem constants (fixed by the reference setup)
#define NN  50000
#define DD  512
#define HH  512
#define OC  256
#define EE  150000

// ---------------- scratch (no allocation allowed -> __device__ globals) ----------------
__device__ float g_hsrc[(size_t)NN * HH];   // layer1: [N,512]; layer2 reuse: [N,256]
__device__ float g_agg [(size_t)NN * HH];   // conv accumulator
__device__ float g_hmid[(size_t)NN * HH];   // after lin1
__device__ float g_asrc[NN];
__device__ float g_adst[NN];
__device__ float g_s[4][NN];                // per-layer, per-list softmax sums
__device__ float g_wa[2][DD];
__device__ float g_wb[2][DD];

// CSR structures (built once per launch; shared by both layers)
__device__ int   g_rowptr[2][NN + 1];
__device__ int   g_pos[2][NN];              // histogram, then fill cursor
__device__ int   g_perm[2][EE];             // edge -> csr slot
__device__ int   g_csrc[2][EE];             // csr: source node per slot
__device__ float g_cw[2][EE];               // csr: exp(e) per slot (per layer)
__device__ int   g_bsum[2][128];
__device__ int   g_boff[2][128];

// pre-split weights, [K,N] fp32 layout -> bf16 hi/lo (same layout)
#define WO1 0
#define WO2 262144
#define WO3 524288
#define WO4 655360
#define WTOT 720896
__device__ __nv_bfloat16 g_whi[WTOT];
__device__ __nv_bfloat16 g_wlo[WTOT];

// ==================== weight bf16 hi/lo split (elementwise, float4) ====================
__global__ void wsplit_kernel(const float* __restrict__ W,
                              __nv_bfloat16* __restrict__ hi, __nv_bfloat16* __restrict__ lo,
                              int total4)
{
    int i = blockIdx.x * blockDim.x + threadIdx.x;
    if (i >= total4) return;
    float4 v = ((const float4*)W)[i];
    __nv_bfloat162 h0 = __floats2bfloat162_rn(v.x, v.y);
    float2 f0 = __bfloat1622float2(h0);
    __nv_bfloat162 l0 = __floats2bfloat162_rn(v.x - f0.x, v.y - f0.y);
    __nv_bfloat162 h1 = __floats2bfloat162_rn(v.z, v.w);
    float2 f1 = __bfloat1622float2(h1);
    __nv_bfloat162 l1 = __floats2bfloat162_rn(v.z - f1.x, v.w - f1.y);
    uint2 hh, ll;
    hh.x = reinterpret_cast<uint32_t&>(h0); hh.y = reinterpret_cast<uint32_t&>(h1);
    ll.x = reinterpret_cast<uint32_t&>(l0); ll.y = reinterpret_cast<uint32_t&>(l1);
    ((uint2*)hi)[i] = hh;
    ((uint2*)lo)[i] = ll;
}

// ==================== tensor-core GEMM (mma.sync, 3-term bf16 split) ====================
#define LDM4(r0,r1,r2,r3,addr) \
    asm volatile("ldmatrix.sync.aligned.m8n8.x4.shared.b16 {%0,%1,%2,%3}, [%4];" \
                 : "=r"(r0),"=r"(r1),"=r"(r2),"=r"(r3) : "r"(addr))
#define LDM4T(r0,r1,r2,r3,addr) \
    asm volatile("ldmatrix.sync.aligned.m8n8.x4.trans.shared.b16 {%0,%1,%2,%3}, [%4];" \
                 : "=r"(r0),"=r"(r1),"=r"(r2),"=r"(r3) : "r"(addr))
#define MMA16816(d, a, b) \
    asm volatile("mma.sync.aligned.m16n8k16.row.col.f32.bf16.bf16.f32 " \
                 "{%0,%1,%2,%3},{%4,%5,%6,%7},{%8,%9},{%0,%1,%2,%3};" \
                 : "+f"(d[0]),"+f"(d[1]),"+f"(d[2]),"+f"(d[3]) \
                 : "r"(a[0]),"r"(a[1]),"r"(a[2]),"r"(a[3]),"r"(b[0]),"r"(b[1]))
#define CP_ASYNC16(dst, src) \
    asm volatile("cp.async.ca.shared.global [%0], [%1], 16;" :: "r"(dst), "l"(src) : "memory")
#define CP_COMMIT()  asm volatile("cp.async.commit_group;" ::: "memory")
#define CP_WAIT0()   asm volatile("cp.async.wait_group 0;" ::: "memory")

__device__ __forceinline__ uint32_t smem_u32(const void* p)
{
    return (uint32_t)__cvta_generic_to_shared(p);
}

__device__ __forceinline__ void split2(__nv_bfloat16* hp, __nv_bfloat16* lp, float x, float y)
{
    __nv_bfloat162 h = __floats2bfloat162_rn(x, y);
    float2 hf = __bfloat1622float2(h);
    __nv_bfloat162 l = __floats2bfloat162_rn(x - hf.x, y - hf.y);
    *(__nv_bfloat162*)hp = h;
    *(__nv_bfloat162*)lp = l;
}

// dynamic-smem stage layout (bytes)
#define GA_HI 0
#define GA_LO 10240
#define GB_HI 20480
#define GB_LO 29184
#define GSTAGE 37888
#define GDSM (2 * GSTAGE)

// C = A[MxK](fp32, split on the fly) @ B[KxN](pre-split bf16 hi/lo) (+bias)(+relu)
// Double-buffered SMEM: B via cp.async, A via register prefetch; 1 sync per K-tile.
// N is the row stride of B and C; kernel covers gridDim.x*128 cols at the given
// (possibly column-offset) B/C/bias pointers -> enables column-split launches.
template<bool BIAS, bool RELU>
__global__ __launch_bounds__(256, 2)
void mma_gemm_kernel(const float* __restrict__ A,
                     const __nv_bfloat16* __restrict__ Bhi,
                     const __nv_bfloat16* __restrict__ Blo,
                     const float* __restrict__ bias, float* __restrict__ C,
                     int M, int N, int K)
{
    const int BM = 128, BN = 128, BK = 32;
    const int ASTR = 40;      // A row stride (elements): BK + 8 pad
    const int BSTR = 136;     // B row stride (elements): BN + 8 pad
    extern __shared__ __align__(16) char dsm[];

    int tid = threadIdx.x;
    int lane = tid & 31;
    int w = tid >> 5;
    int wm = w & 3;
    int wn = w >> 2;

    int blockM = blockIdx.y * BM;
    int blockN = blockIdx.x * BN;

    int aRow0 = tid >> 3;          // + 32*i
    int aCol  = (tid & 7) * 4;
    // B tile: 32 rows x 128 cols = 512 uint4-groups of 8 bf16; 2 groups per thread
    int bR[2], bC[2];
    #pragma unroll
    for (int i = 0; i < 2; i++) {
        int g = tid + 256 * i;
        bR[i] = g >> 4;            // 0..31
        bC[i] = (g & 15) * 8;      // 0..120
    }

    const float4 z4 = make_float4(0.f, 0.f, 0.f, 0.f);
    float4 pa[4];

    float acc[2][8][4];
    #pragma unroll
    for (int mt = 0; mt < 2; mt++)
        #pragma unroll
        for (int nt = 0; nt < 8; nt++)
            #pragma unroll
            for (int q = 0; q < 4; q++) acc[mt][nt][q] = 0.f;

    const uint32_t smBase = smem_u32(dsm);

    // ---- prologue: tile 0 into stage 0 ----
    #pragma unroll
    for (int i = 0; i < 2; i++) {
        uint32_t so = (uint32_t)(bR[i] * BSTR + bC[i]) * 2u;
        size_t go = (size_t)bR[i] * N + blockN + bC[i];
        CP_ASYNC16(smBase + GB_HI + so, Bhi + go);
        CP_ASYNC16(smBase + GB_LO + so, Blo + go);
    }
    CP_COMMIT();
    #pragma unroll
    for (int i = 0; i < 4; i++) {
        int r = blockM + aRow0 + 32 * i;
        pa[i] = (r < M) ? *(const float4*)(A + (size_t)r * K + aCol) : z4;
    }
    #pragma unroll
    for (int i = 0; i < 4; i++) {
        int r = aRow0 + 32 * i;
        __nv_bfloat16* hp = (__nv_bfloat16*)(dsm + GA_HI + (r * ASTR + aCol) * 2);
        __nv_bfloat16* lp = (__nv_bfloat16*)(dsm + GA_LO + (r * ASTR + aCol) * 2);
        split2(hp,     lp,     pa[i].x, pa[i].y);
        split2(hp + 2, lp + 2, pa[i].z, pa[i].w);
    }
    CP_WAIT0();
    __syncthreads();

    int nT = K / BK;
    for (int kt = 0; kt < nT; kt++) {
        uint32_t cur = (uint32_t)(kt & 1) * GSTAGE;
        uint32_t nxt = cur ^ GSTAGE;

        // prefetch next tile: B via cp.async into nxt, A into registers
        if (kt + 1 < nT) {
            #pragma unroll
            for (int i = 0; i < 2; i++) {
                uint32_t so = (uint32_t)(bR[i] * BSTR + bC[i]) * 2u;
                size_t go = (size_t)((kt + 1) * BK + bR[i]) * N + blockN + bC[i];
                CP_ASYNC16(smBase + nxt + GB_HI + so, Bhi + go);
                CP_ASYNC16(smBase + nxt + GB_LO + so, Blo + go);
            }
            CP_COMMIT();
            #pragma unroll
            for (int i = 0; i < 4; i++) {
                int r = blockM + aRow0 + 32 * i;
                pa[i] = (r < M) ? *(const float4*)(A + (size_t)r * K + (kt + 1) * BK + aCol) : z4;
            }
        }

        // compute on cur
        #pragma unroll
        for (int ks = 0; ks < 2; ks++) {
            uint32_t ah[2][4], al[2][4];
            #pragma unroll
            for (int mt = 0; mt < 2; mt++) {
                uint32_t off = (uint32_t)((wm * 32 + mt * 16 + (lane & 15)) * ASTR
                                          + (lane >> 4) * 8 + ks * 16) * 2u;
                LDM4(ah[mt][0], ah[mt][1], ah[mt][2], ah[mt][3], smBase + cur + GA_HI + off);
                LDM4(al[mt][0], al[mt][1], al[mt][2], al[mt][3], smBase + cur + GA_LO + off);
            }
            uint32_t bh[8][2], bl[8][2];
            #pragma unroll
            for (int p = 0; p < 4; p++) {
                uint32_t off = (uint32_t)((ks * 16 + (lane & 15)) * BSTR
                                          + wn * 64 + p * 16 + ((lane & 16) >> 1)) * 2u;
                uint32_t r0, r1, r2, r3;
                LDM4T(r0, r1, r2, r3, smBase + cur + GB_HI + off);
                bh[2 * p][0] = r0; bh[2 * p][1] = r1;
                bh[2 * p + 1][0] = r2; bh[2 * p + 1][1] = r3;
                LDM4T(r0, r1, r2, r3, smBase + cur + GB_LO + off);
                bl[2 * p][0] = r0; bl[2 * p][1] = r1;
                bl[2 * p + 1][0] = r2; bl[2 * p + 1][1] = r3;
            }
            #pragma unroll
            for (int mt = 0; mt < 2; mt++)
                #pragma unroll
                for (int nt = 0; nt < 8; nt++) {
                    MMA16816(acc[mt][nt], ah[mt], bh[nt]);
                    MMA16816(acc[mt][nt], ah[mt], bl[nt]);
                    MMA16816(acc[mt][nt], al[mt], bh[nt]);
                }
        }

        if (kt + 1 < nT) {
            // split-store A into nxt, then drain cp.async before the sync
            #pragma unroll
            for (int i = 0; i < 4; i++) {
                int r = aRow0 + 32 * i;
                __nv_bfloat16* hp = (__nv_bfloat16*)(dsm + nxt + GA_HI + (r * ASTR + aCol) * 2);
                __nv_bfloat16* lp = (__nv_bfloat16*)(dsm + nxt + GA_LO + (r * ASTR + aCol) * 2);
                split2(hp,     lp,     pa[i].x, pa[i].y);
                split2(hp + 2, lp + 2, pa[i].z, pa[i].w);
            }
            CP_WAIT0();
        }
        __syncthreads();
    }

    // epilogue
    #pragma unroll
    for (int mt = 0; mt < 2; mt++) {
        #pragma unroll
        for (int nt = 0; nt < 8; nt++) {
            int row = blockM + wm * 32 + mt * 16 + (lane >> 2);
            int col = blockN + wn * 64 + nt * 8 + (lane & 3) * 2;
            float2 v0 = make_float2(acc[mt][nt][0], acc[mt][nt][1]);
            float2 v1 = make_float2(acc[mt][nt][2], acc[mt][nt][3]);
            if (BIAS) {
                float2 bv = *(const float2*)(bias + col);
                v0.x += bv.x; v0.y += bv.y;
                v1.x += bv.x; v1.y += bv.y;
            }
            if (RELU) {
                v0.x = fmaxf(v0.x, 0.f); v0.y = fmaxf(v0.y, 0.f);
                v1.x = fmaxf(v1.x, 0.f); v1.y = fmaxf(v1.y, 0.f);
            }
            if (row < M)     *(float2*)(C + (size_t)row * N + col) = v0;
            if (row + 8 < M) *(float2*)(C + (size_t)(row + 8) * N + col) = v1;
        }
    }
}

// ---------------- GEMV kernels ----------------
__global__ void gemv_kernel(const float* __restrict__ A, const float* __restrict__ v,
                            float* __restrict__ out, int M, int K)
{
    int row = blockIdx.x * (blockDim.x >> 5) + (threadIdx.x >> 5);
    int lane = threadIdx.x & 31;
    if (row >= M) return;
    const float4* a4 = (const float4*)(A + (size_t)row * K);
    const float4* v4 = (const float4*)v;
    int K4 = K >> 2;
    float sum = 0.f;
    for (int k = lane; k < K4; k += 32) {
        float4 a = a4[k], b = v4[k];
        sum += a.x * b.x + a.y * b.y + a.z * b.z + a.w * b.w;
    }
    #pragma unroll
    for (int o = 16; o; o >>= 1) sum += __shfl_down_sync(0xffffffffu, sum, o);
    if (lane == 0) out[row] = sum;
}

__global__ void gemv2_kernel(const float* __restrict__ A,
                             const float* __restrict__ va, const float* __restrict__ vb,
                             float* __restrict__ oa, float* __restrict__ ob, int M, int K)
{
    int row = blockIdx.x * (blockDim.x >> 5) + (threadIdx.x >> 5);
    int lane = threadIdx.x & 31;
    if (row >= M) return;
    const float4* a4 = (const float4*)(A + (size_t)row * K);
    const float4* va4 = (const float4*)va;
    const float4* vb4 = (const float4*)vb;
    int K4 = K >> 2;
    float sa = 0.f, sb = 0.f;
    for (int k = lane; k < K4; k += 32) {
        float4 a = a4[k], u = va4[k], t = vb4[k];
        sa += a.x * u.x + a.y * u.y + a.z * u.z + a.w * u.w;
        sb += a.x * t.x + a.y * t.y + a.z * t.z + a.w * t.w;
    }
    #pragma unroll
    for (int o = 16; o; o >>= 1) {
        sa += __shfl_down_sync(0xffffffffu, sa, o);
        sb += __shfl_down_sync(0xffffffffu, sb, o);
    }
    if (lane == 0) { oa[row] = sa; ob[row] = sb; }
}

// ---------------- CSR build kernels ----------------
__global__ void zero_int_kernel(int* __restrict__ p, int n)
{
    int i = blockIdx.x * blockDim.x + threadIdx.x;
    if (i < n) p[i] = 0;
}
__global__ void zero_f_kernel(float* __restrict__ p, int n)
{
    int i = blockIdx.x * blockDim.x + threadIdx.x;
    if (i < n) p[i] = 0.f;
}
__global__ void hist_kernel(const int* __restrict__ dst, int* __restrict__ cnt, int E)
{
    int i = blockIdx.x * blockDim.x + threadIdx.x;
    if (i < E) atomicAdd(&cnt[dst[i]], 1);
}
__global__ void scan1_kernel(const int* __restrict__ cnt, int* __restrict__ rowptr,
                             int* __restrict__ bsum, int n)
{
    __shared__ int sm[512];
    int t = threadIdx.x;
    int idx = blockIdx.x * 512 + t;
    int v = (idx < n) ? cnt[idx] : 0;
    sm[t] = v;
    __syncthreads();
    for (int o = 1; o < 512; o <<= 1) {
        int a = (t >= o) ? sm[t - o] : 0;
        __syncthreads();
        sm[t] += a;
        __syncthreads();
    }
    if (idx < n) rowptr[idx + 1] = sm[t];
    if (t == 511) bsum[blockIdx.x] = sm[511];
}
__global__ void scan2_kernel(const int* __restrict__ bsum, int* __restrict__ boff, int nb)
{
    __shared__ int sm[128];
    int t = threadIdx.x;
    int v = (t < nb) ? bsum[t] : 0;
    sm[t] = v;
    __syncthreads();
    for (int o = 1; o < 128; o <<= 1) {
        int a = (t >= o) ? sm[t - o] : 0;
        __syncthreads();
        sm[t] += a;
        __syncthreads();
    }
    boff[t] = sm[t] - v;     // exclusive
}
__global__ void scan3_kernel(int* __restrict__ rowptr, const int* __restrict__ boff, int n)
{
    int idx = blockIdx.x * 512 + threadIdx.x;
    if (idx < n) rowptr[idx + 1] += boff[blockIdx.x];
    if (idx == 0) rowptr[0] = 0;
}
__global__ void copy_int_kernel(int* __restrict__ d, const int* __restrict__ s, int n)
{
    int i = blockIdx.x * blockDim.x + threadIdx.x;
    if (i < n) d[i] = s[i];
}
__global__ void fill_kernel(const int* __restrict__ src, const int* __restrict__ dst,
                            int* __restrict__ pos, int* __restrict__ perm,
                            int* __restrict__ csrc, int E)
{
    int i = blockIdx.x * blockDim.x + threadIdx.x;
    if (i >= E) return;
    int slot = atomicAdd(&pos[dst[i]], 1);
    perm[i] = slot;
    csrc[slot] = src[i];
}

// ---------------- edge alpha, both lists in one kernel ----------------
__global__ void alpha_both_kernel(const int* __restrict__ src1, const int* __restrict__ dst1,
                                  const int* __restrict__ src2, const int* __restrict__ dst2,
                                  const float* __restrict__ as_, const float* __restrict__ ad_,
                                  const int* __restrict__ perm, float* __restrict__ cw,
                                  float* __restrict__ s, int E)
{
    int i = blockIdx.x * blockDim.x + threadIdx.x;
    if (i >= 2 * E) return;
    int l = (i >= E) ? 1 : 0;
    int j = i - l * E;
    const int* sp = l ? src2 : src1;
    const int* dp = l ? dst2 : dst1;
    int sn = sp[j], dn = dp[j];
    float v = as_[sn] + ad_[dn];
    v = v > 0.f ? v : 0.2f * v;          // leaky_relu, slope 0.2
    float ex = expf(v);
    cw[(size_t)l * EE + perm[(size_t)l * EE + j]] = ex;
    atomicAdd(&s[(size_t)l * NN + dn], ex);
}

// ---------------- per-node CSR aggregation (both lists), out = 2*bias + sums ----------------
// Column-sliced: covers blockDim.x*4 columns starting at colOff (C = row stride).
template<int C>
__global__ void agg_kernel(const int* __restrict__ rp1, const int* __restrict__ cs1,
                           const float* __restrict__ cw1, const float* __restrict__ s1,
                           const int* __restrict__ rp2, const int* __restrict__ cs2,
                           const float* __restrict__ cw2, const float* __restrict__ s2,
                           const float* __restrict__ h, const float* __restrict__ bias,
                           float* __restrict__ out, int colOff)
{
    int n = blockIdx.x;
    int c = colOff + threadIdx.x * 4;
    float4 b4 = *(const float4*)(bias + c);
    float4 acc = make_float4(2.f * b4.x, 2.f * b4.y, 2.f * b4.z, 2.f * b4.w);

    #pragma unroll
    for (int li = 0; li < 2; li++) {
        const int* rp = li ? rp2 : rp1;
        const int* cs = li ? cs2 : cs1;
        const float* cwp = li ? cw2 : cw1;
        const float* sp = li ? s2 : s1;

        int st = rp[n], en = rp[n + 1];
        float inv = 1.f / (sp[n] + 1e-16f);
        int j = st;
        for (; j + 4 <= en; j += 4) {
            int i0 = cs[j], i1 = cs[j + 1], i2 = cs[j + 2], i3 = cs[j + 3];
            float w0 = cwp[j] * inv, w1 = cwp[j + 1] * inv;
            float w2 = cwp[j + 2] * inv, w3 = cwp[j + 3] * inv;
            float4 h0 = *(const float4*)(h + (size_t)i0 * C + c);
            float4 h1 = *(const float4*)(h + (size_t)i1 * C + c);
            float4 h2 = *(const float4*)(h + (size_t)i2 * C + c);
            float4 h3 = *(const float4*)(h + (size_t)i3 * C + c);
            acc.x += w0 * h0.x + w1 * h1.x + w2 * h2.x + w3 * h3.x;
            acc.y += w0 * h0.y + w1 * h1.y + w2 * h2.y + w3 * h3.y;
            acc.z += w0 * h0.z + w1 * h1.z + w2 * h2.z + w3 * h3.z;
            acc.w += w0 * h0.w + w1 * h1.w + w2 * h2.w + w3 * h3.w;
        }
        for (; j < en; j++) {
            float wv = cwp[j] * inv;
            float4 hv = *(const float4*)(h + (size_t)cs[j] * C + c);
            acc.x += wv * hv.x; acc.y += wv * hv.y;
            acc.z += wv * hv.z; acc.w += wv * hv.w;
        }
    }
    *(float4*)(out + (size_t)n * C + c) = acc;
}

// ---------------- host orchestration ----------------
static void* symaddr(const void* s)
{
    void* p = nullptr;
    cudaGetSymbolAddress(&p, s);
    return p;
}

extern "C" void kernel_launch(void* const* d_in, const int* in_sizes, int n_in,
                              void* d_out, int out_size)
{
    (void)n_in; (void)out_size;
    const float* x   = (const float*)d_in[0];
    const int*   ei1 = (const int*)d_in[1];
    const int*   ei2 = (const int*)d_in[2];
    const float* W1s = (const float*)d_in[3];
    const float* W1d = (const float*)d_in[4];
    const float* a1s = (const float*)d_in[5];
    const float* a1d = (const float*)d_in[6];
    const float* b1  = (const float*)d_in[7];
    const float* Wl1 = (const float*)d_in[8];
    const float* bl1 = (const float*)d_in[9];
    const float* W2s = (const float*)d_in[10];
    const float* W2d = (const float*)d_in[11];
    const float* a2s = (const float*)d_in[12];
    const float* a2d = (const float*)d_in[13];
    const float* b2  = (const float*)d_in[14];
    const float* Wl2 = (const float*)d_in[15];
    const float* bl2 = (const float*)d_in[16];
    float* out = (float*)d_out;

    const int N = in_sizes[0] / DD;       // 50000
    const int E = in_sizes[1] / 2;        // 150000

    float* hsrc = (float*)symaddr(g_hsrc);
    float* agg  = (float*)symaddr(g_agg);
    float* hmid = (float*)symaddr(g_hmid);
    float* asrc = (float*)symaddr(g_asrc);
    float* adst = (float*)symaddr(g_adst);
    float* sbuf = (float*)symaddr(g_s);          // [4][NN]
    float* wa   = (float*)symaddr(g_wa);         // [2][DD]
    float* wb   = (float*)symaddr(g_wb);         // [2][DD]
    int* rowptr = (int*)symaddr(g_rowptr);
    int* pos    = (int*)symaddr(g_pos);
    int* perm   = (int*)symaddr(g_perm);
    int* csrc   = (int*)symaddr(g_csrc);
    float* cw   = (float*)symaddr(g_cw);
    int* bsum   = (int*)symaddr(g_bsum);
    int* boff   = (int*)symaddr(g_boff);
    __nv_bfloat16* whi = (__nv_bfloat16*)symaddr(g_whi);
    __nv_bfloat16* wlo = (__nv_bfloat16*)symaddr(g_wlo);

    const int NB = (NN + 511) / 512;
    const int* srcp1 = ei1;            const int* dstp1 = ei1 + E;
    const int* srcp2 = ei2;            const int* dstp2 = ei2 + E;

    static cudaStream_t sB = nullptr, sC = nullptr;
    static cudaEvent_t ev0, evB, evA1, evCa, ev1, evA2, evCb, evG1a, evG2a;
    if (!sB) {
        cudaStreamCreateWithFlags(&sB, cudaStreamNonBlocking);
        cudaStreamCreateWithFlags(&sC, cudaStreamNonBlocking);
        cudaEventCreateWithFlags(&ev0, cudaEventDisableTiming);
        cudaEventCreateWithFlags(&evB, cudaEventDisableTiming);
        cudaEventCreateWithFlags(&evA1, cudaEventDisableTiming);
        cudaEventCreateWithFlags(&evCa, cudaEventDisableTiming);
        cudaEventCreateWithFlags(&ev1, cudaEventDisableTiming);
        cudaEventCreateWithFlags(&evA2, cudaEventDisableTiming);
        cudaEventCreateWithFlags(&evCb, cudaEventDisableTiming);
        cudaEventCreateWithFlags(&evG1a, cudaEventDisableTiming);
        cudaEventCreateWithFlags(&evG2a, cudaEventDisableTiming);
        cudaFuncSetAttribute(mma_gemm_kernel<false, false>,
                             cudaFuncAttributeMaxDynamicSharedMemorySize, GDSM);
        cudaFuncSetAttribute(mma_gemm_kernel<true, true>,
                             cudaFuncAttributeMaxDynamicSharedMemorySize, GDSM);
        cudaFuncSetAttribute(mma_gemm_kernel<true, false>,
                             cudaFuncAttributeMaxDynamicSharedMemorySize, GDSM);
    }

    dim3 gH2(2, (N + 127) / 128);             // 256-col half (512-col GEMM)
    dim3 gH(HH / 128, (N + 127) / 128);       // full 512 cols
    dim3 gO1(1, (N + 127) / 128);             // 128-col half (256-col GEMM)

    // ===== fork =====
    cudaEventRecord(ev0, 0);
    cudaStreamWaitEvent(sB, ev0, 0);
    cudaStreamWaitEvent(sC, ev0, 0);

    // Submissions 1-3, then GEMM1a as the 4th launch (ncu profile targeting).
    wsplit_kernel<<<(DD * HH / 4 + 255) / 256, 256>>>(W1s, whi + WO1, wlo + WO1, DD * HH / 4);
    wsplit_kernel<<<(HH * HH / 4 + 255) / 256, 256, 0, sB>>>(Wl1, whi + WO2, wlo + WO2, HH * HH / 4);
    wsplit_kernel<<<(HH * OC / 4 + 255) / 256, 256, 0, sB>>>(W2s, whi + WO3, wlo + WO3, HH * OC / 4);
    // GEMM1a: cols [0,256)
    mma_gemm_kernel<false, false><<<gH2, 256, GDSM>>>(x, whi + WO1, wlo + WO1, nullptr, hsrc, N, HH, DD);
    cudaEventRecord(evG1a, 0);
    // GEMM1b: cols [256,512)
    mma_gemm_kernel<false, false><<<gH2, 256, GDSM>>>(x, whi + WO1 + 256, wlo + WO1 + 256, nullptr,
                                                      hsrc + 256, N, HH, DD);

    // ----- stream B: remaining setup (CSR build etc.) -----
    wsplit_kernel<<<(OC * OC / 4 + 255) / 256, 256, 0, sB>>>(Wl2, whi + WO4, wlo + WO4, OC * OC / 4);
    gemv_kernel<<<(HH + 7) / 8, 256, 0, sB>>>(W2s, a2s, wa + DD, HH, OC);
    gemv_kernel<<<(HH + 7) / 8, 256, 0, sB>>>(W2d, a2d, wb + DD, HH, OC);
    zero_f_kernel<<<(4 * NN + 255) / 256, 256, 0, sB>>>(sbuf, 4 * NN);
    zero_int_kernel<<<(2 * NN + 255) / 256, 256, 0, sB>>>(pos, 2 * NN);
    for (int l = 0; l < 2; l++) {
        const int* dstp = l ? dstp2 : dstp1;
        const int* srcp = l ? srcp2 : srcp1;
        int* cnt_l = pos + l * NN;
        int* rp_l  = rowptr + l * (NN + 1);
        hist_kernel<<<(E + 255) / 256, 256, 0, sB>>>(dstp, cnt_l, E);
        scan1_kernel<<<NB, 512, 0, sB>>>(cnt_l, rp_l, bsum + l * 128, N);
        scan2_kernel<<<1, 128, 0, sB>>>(bsum + l * 128, boff + l * 128, NB);
        scan3_kernel<<<NB, 512, 0, sB>>>(rp_l, boff + l * 128, N);
        copy_int_kernel<<<(NN + 255) / 256, 256, 0, sB>>>(cnt_l, rp_l, N);
        fill_kernel<<<(E + 255) / 256, 256, 0, sB>>>(srcp, dstp, cnt_l, perm + l * EE, csrc + l * EE, E);
    }
    cudaEventRecord(evB, sB);

    // ----- stream C: L1 weight gemvs + node alphas + L1 edge alphas + agg1a -----
    gemv_kernel<<<(DD + 7) / 8, 256, 0, sC>>>(W1s, a1s, wa, DD, HH);
    gemv_kernel<<<(DD + 7) / 8, 256, 0, sC>>>(W1d, a1d, wb, DD, HH);
    gemv2_kernel<<<(N + 7) / 8, 256, 0, sC>>>(x, wa, wb, asrc, adst, N, DD);
    cudaStreamWaitEvent(sC, evB, 0);
    alpha_both_kernel<<<(2 * E + 255) / 256, 256, 0, sC>>>(srcp1, dstp1, srcp2, dstp2,
                                                           asrc, adst, perm, cw, sbuf, E);
    cudaEventRecord(evA1, sC);                 // alpha1 done
    // agg1a (cols 0-255) overlaps GEMM1b on default
    cudaStreamWaitEvent(sC, evG1a, 0);
    agg_kernel<HH><<<N, 64, 0, sC>>>(rowptr, csrc, cw, sbuf,
                                     rowptr + (NN + 1), csrc + EE, cw + EE, sbuf + NN,
                                     hsrc, b1, agg, 0);
    cudaEventRecord(evCa, sC);

    // ----- default stream: critical chain -----
    cudaStreamWaitEvent(0, evA1, 0);           // agg1b needs alpha1 (GEMM1b by stream order)
    agg_kernel<HH><<<N, 64>>>(rowptr, csrc, cw, sbuf,
                              rowptr + (NN + 1), csrc + EE, cw + EE, sbuf + NN,
                              hsrc, b1, agg, 256);
    cudaStreamWaitEvent(0, evCa, 0);           // lin1 needs agg1a too
    mma_gemm_kernel<true, true><<<gH, 256, GDSM>>>(agg, whi + WO2, wlo + WO2, bl1, hmid, N, HH, HH);

    // fork: layer-2 node/edge alphas overlap GEMM2
    cudaEventRecord(ev1, 0);
    cudaStreamWaitEvent(sC, ev1, 0);
    gemv2_kernel<<<(N + 7) / 8, 256, 0, sC>>>(hmid, wa + DD, wb + DD, asrc, adst, N, HH);
    alpha_both_kernel<<<(2 * E + 255) / 256, 256, 0, sC>>>(srcp1, dstp1, srcp2, dstp2,
                                                           asrc, adst, perm, cw, sbuf + 2 * NN, E);
    cudaEventRecord(evA2, sC);                 // alpha2 done

    // GEMM2a: cols [0,128)
    mma_gemm_kernel<false, false><<<gO1, 256, GDSM>>>(hmid, whi + WO3, wlo + WO3, nullptr, hsrc, N, OC, HH);
    cudaEventRecord(evG2a, 0);
    // GEMM2b: cols [128,256)
    mma_gemm_kernel<false, false><<<gO1, 256, GDSM>>>(hmid, whi + WO3 + 128, wlo + WO3 + 128, nullptr,
                                                      hsrc + 128, N, OC, HH);

    // agg2a (cols 0-127) on stream C overlaps GEMM2b (alpha2 precedes in stream order)
    cudaStreamWaitEvent(sC, evG2a, 0);
    agg_kernel<OC><<<N, 32, 0, sC>>>(rowptr, csrc, cw, sbuf + 2 * NN,
                                     rowptr + (NN + 1), csrc + EE, cw + EE, sbuf + 3 * NN,
                                     hsrc, b2, agg, 0);
    cudaEventRecord(evCb, sC);

    // agg2b (cols 128-255) on default after GEMM2b + alpha2
    cudaStreamWaitEvent(0, evA2, 0);
    agg_kernel<OC><<<N, 32>>>(rowptr, csrc, cw, sbuf + 2 * NN,
                              rowptr + (NN + 1), csrc + EE, cw + EE, sbuf + 3 * NN,
                              hsrc, b2, agg, 128);
    cudaStreamWaitEvent(0, evCb, 0);
    // lin2 (full 256 cols, two 128-col halves back to back on default)
    mma_gemm_kernel<true, false><<<gO1, 256, GDSM>>>(agg, whi + WO4, wlo + WO4, bl2, out, N, OC, OC);
    mma_gemm_kernel<true, false><<<gO1, 256, GDSM>>>(agg, whi + WO4 + 128, wlo + WO4 + 128, bl2 + 128,
                                                     out + 128, N, OC, OC);
}

// round 17
// speedup vs baseline: 1.9181x; 1.0074x over previous
#include <cuda_runtime.h>
#include <cuda_bf16.h>
#include <math_constants.h>
#include <cstdint>

// Problem constants (fixed by the reference setup)
#define NN  50000
#define DD  512
#define HH  512
#define OC  256
#define EE  150000

// ---------------- scratch (no allocation allowed -> __device__ globals) ----------------
__device__ float g_hsrc[(size_t)NN * HH];   // layer1: [N,512]; layer2 reuse: [N,256]
__device__ float g_agg [(size_t)NN * HH];   // conv accumulator
__device__ float g_hmid[(size_t)NN * HH];   // after lin1
__device__ float g_asrc[NN];
__device__ float g_adst[NN];
__device__ float g_s[4][NN];                // per-layer, per-list softmax sums
__device__ float g_wa[2][DD];
__device__ float g_wb[2][DD];

// CSR structures (built once per launch; shared by both layers)
__device__ int   g_rowptr[2][NN + 1];
__device__ int   g_pos[2][NN];              // histogram, then fill cursor
__device__ int   g_perm[2][EE];             // edge -> csr slot
__device__ int   g_csrc[2][EE];             // csr: source node per slot
__device__ float g_cw[2][EE];               // csr: exp(e) per slot (per layer)
__device__ int   g_bsum[2][128];
__device__ int   g_boff[2][128];

// pre-split weights, [K,N] fp32 layout -> bf16 hi/lo (same layout)
#define WO1 0
#define WO2 262144
#define WO3 524288
#define WO4 655360
#define WTOT 720896
__device__ __nv_bfloat16 g_whi[WTOT];
__device__ __nv_bfloat16 g_wlo[WTOT];

// ==================== weight bf16 hi/lo split (elementwise, float4) ====================
__global__ void wsplit_kernel(const float* __restrict__ W,
                              __nv_bfloat16* __restrict__ hi, __nv_bfloat16* __restrict__ lo,
                              int total4)
{
    int i = blockIdx.x * blockDim.x + threadIdx.x;
    if (i >= total4) return;
    float4 v = ((const float4*)W)[i];
    __nv_bfloat162 h0 = __floats2bfloat162_rn(v.x, v.y);
    float2 f0 = __bfloat1622float2(h0);
    __nv_bfloat162 l0 = __floats2bfloat162_rn(v.x - f0.x, v.y - f0.y);
    __nv_bfloat162 h1 = __floats2bfloat162_rn(v.z, v.w);
    float2 f1 = __bfloat1622float2(h1);
    __nv_bfloat162 l1 = __floats2bfloat162_rn(v.z - f1.x, v.w - f1.y);
    uint2 hh, ll;
    hh.x = reinterpret_cast<uint32_t&>(h0); hh.y = reinterpret_cast<uint32_t&>(h1);
    ll.x = reinterpret_cast<uint32_t&>(l0); ll.y = reinterpret_cast<uint32_t&>(l1);
    ((uint2*)hi)[i] = hh;
    ((uint2*)lo)[i] = ll;
}

// ==================== tensor-core GEMM (mma.sync, 3-term bf16 split) ====================
#define LDM4(r0,r1,r2,r3,addr) \
    asm volatile("ldmatrix.sync.aligned.m8n8.x4.shared.b16 {%0,%1,%2,%3}, [%4];" \
                 : "=r"(r0),"=r"(r1),"=r"(r2),"=r"(r3) : "r"(addr))
#define LDM4T(r0,r1,r2,r3,addr) \
    asm volatile("ldmatrix.sync.aligned.m8n8.x4.trans.shared.b16 {%0,%1,%2,%3}, [%4];" \
                 : "=r"(r0),"=r"(r1),"=r"(r2),"=r"(r3) : "r"(addr))
#define MMA16816(d, a, b) \
    asm volatile("mma.sync.aligned.m16n8k16.row.col.f32.bf16.bf16.f32 " \
                 "{%0,%1,%2,%3},{%4,%5,%6,%7},{%8,%9},{%0,%1,%2,%3};" \
                 : "+f"(d[0]),"+f"(d[1]),"+f"(d[2]),"+f"(d[3]) \
                 : "r"(a[0]),"r"(a[1]),"r"(a[2]),"r"(a[3]),"r"(b[0]),"r"(b[1]))
#define CP_ASYNC16(dst, src) \
    asm volatile("cp.async.ca.shared.global [%0], [%1], 16;" :: "r"(dst), "l"(src) : "memory")
#define CP_COMMIT()  asm volatile("cp.async.commit_group;" ::: "memory")
#define CP_WAIT0()   asm volatile("cp.async.wait_group 0;" ::: "memory")

__device__ __forceinline__ uint32_t smem_u32(const void* p)
{
    return (uint32_t)__cvta_generic_to_shared(p);
}

__device__ __forceinline__ void split2(__nv_bfloat16* hp, __nv_bfloat16* lp, float x, float y)
{
    __nv_bfloat162 h = __floats2bfloat162_rn(x, y);
    float2 hf = __bfloat1622float2(h);
    __nv_bfloat162 l = __floats2bfloat162_rn(x - hf.x, y - hf.y);
    *(__nv_bfloat162*)hp = h;
    *(__nv_bfloat162*)lp = l;
}

// dynamic-smem stage layout (bytes)
#define GA_HI 0
#define GA_LO 10240
#define GB_HI 20480
#define GB_LO 29184
#define GSTAGE 37888
#define GDSM (2 * GSTAGE)

// C = A[MxK](fp32, split on the fly) @ B[KxN](pre-split bf16 hi/lo) (+bias)(+relu)
// Double-buffered SMEM: B via cp.async, A via register prefetch; 1 sync per K-tile.
// N is the row stride of B and C; kernel covers gridDim.x*128 cols at the given
// (possibly offset) pointers -> enables column- and row-split launches.
template<bool BIAS, bool RELU>
__global__ __launch_bounds__(256, 2)
void mma_gemm_kernel(const float* __restrict__ A,
                     const __nv_bfloat16* __restrict__ Bhi,
                     const __nv_bfloat16* __restrict__ Blo,
                     const float* __restrict__ bias, float* __restrict__ C,
                     int M, int N, int K)
{
    const int BM = 128, BN = 128, BK = 32;
    const int ASTR = 40;      // A row stride (elements): BK + 8 pad
    const int BSTR = 136;     // B row stride (elements): BN + 8 pad
    extern __shared__ __align__(16) char dsm[];

    int tid = threadIdx.x;
    int lane = tid & 31;
    int w = tid >> 5;
    int wm = w & 3;
    int wn = w >> 2;

    int blockM = blockIdx.y * BM;
    int blockN = blockIdx.x * BN;

    int aRow0 = tid >> 3;          // + 32*i
    int aCol  = (tid & 7) * 4;
    // B tile: 32 rows x 128 cols = 512 uint4-groups of 8 bf16; 2 groups per thread
    int bR[2], bC[2];
    #pragma unroll
    for (int i = 0; i < 2; i++) {
        int g = tid + 256 * i;
        bR[i] = g >> 4;            // 0..31
        bC[i] = (g & 15) * 8;      // 0..120
    }

    const float4 z4 = make_float4(0.f, 0.f, 0.f, 0.f);
    float4 pa[4];

    float acc[2][8][4];
    #pragma unroll
    for (int mt = 0; mt < 2; mt++)
        #pragma unroll
        for (int nt = 0; nt < 8; nt++)
            #pragma unroll
            for (int q = 0; q < 4; q++) acc[mt][nt][q] = 0.f;

    const uint32_t smBase = smem_u32(dsm);

    // ---- prologue: tile 0 into stage 0 ----
    #pragma unroll
    for (int i = 0; i < 2; i++) {
        uint32_t so = (uint32_t)(bR[i] * BSTR + bC[i]) * 2u;
        size_t go = (size_t)bR[i] * N + blockN + bC[i];
        CP_ASYNC16(smBase + GB_HI + so, Bhi + go);
        CP_ASYNC16(smBase + GB_LO + so, Blo + go);
    }
    CP_COMMIT();
    #pragma unroll
    for (int i = 0; i < 4; i++) {
        int r = blockM + aRow0 + 32 * i;
        pa[i] = (r < M) ? *(const float4*)(A + (size_t)r * K + aCol) : z4;
    }
    #pragma unroll
    for (int i = 0; i < 4; i++) {
        int r = aRow0 + 32 * i;
        __nv_bfloat16* hp = (__nv_bfloat16*)(dsm + GA_HI + (r * ASTR + aCol) * 2);
        __nv_bfloat16* lp = (__nv_bfloat16*)(dsm + GA_LO + (r * ASTR + aCol) * 2);
        split2(hp,     lp,     pa[i].x, pa[i].y);
        split2(hp + 2, lp + 2, pa[i].z, pa[i].w);
    }
    CP_WAIT0();
    __syncthreads();

    int nT = K / BK;
    for (int kt = 0; kt < nT; kt++) {
        uint32_t cur = (uint32_t)(kt & 1) * GSTAGE;
        uint32_t nxt = cur ^ GSTAGE;

        // prefetch next tile: B via cp.async into nxt, A into registers
        if (kt + 1 < nT) {
            #pragma unroll
            for (int i = 0; i < 2; i++) {
                uint32_t so = (uint32_t)(bR[i] * BSTR + bC[i]) * 2u;
                size_t go = (size_t)((kt + 1) * BK + bR[i]) * N + blockN + bC[i];
                CP_ASYNC16(smBase + nxt + GB_HI + so, Bhi + go);
                CP_ASYNC16(smBase + nxt + GB_LO + so, Blo + go);
            }
            CP_COMMIT();
            #pragma unroll
            for (int i = 0; i < 4; i++) {
                int r = blockM + aRow0 + 32 * i;
                pa[i] = (r < M) ? *(const float4*)(A + (size_t)r * K + (kt + 1) * BK + aCol) : z4;
            }
        }

        // compute on cur
        #pragma unroll
        for (int ks = 0; ks < 2; ks++) {
            uint32_t ah[2][4], al[2][4];
            #pragma unroll
            for (int mt = 0; mt < 2; mt++) {
                uint32_t off = (uint32_t)((wm * 32 + mt * 16 + (lane & 15)) * ASTR
                                          + (lane >> 4) * 8 + ks * 16) * 2u;
                LDM4(ah[mt][0], ah[mt][1], ah[mt][2], ah[mt][3], smBase + cur + GA_HI + off);
                LDM4(al[mt][0], al[mt][1], al[mt][2], al[mt][3], smBase + cur + GA_LO + off);
            }
            uint32_t bh[8][2], bl[8][2];
            #pragma unroll
            for (int p = 0; p < 4; p++) {
                uint32_t off = (uint32_t)((ks * 16 + (lane & 15)) * BSTR
                                          + wn * 64 + p * 16 + ((lane & 16) >> 1)) * 2u;
                uint32_t r0, r1, r2, r3;
                LDM4T(r0, r1, r2, r3, smBase + cur + GB_HI + off);
                bh[2 * p][0] = r0; bh[2 * p][1] = r1;
                bh[2 * p + 1][0] = r2; bh[2 * p + 1][1] = r3;
                LDM4T(r0, r1, r2, r3, smBase + cur + GB_LO + off);
                bl[2 * p][0] = r0; bl[2 * p][1] = r1;
                bl[2 * p + 1][0] = r2; bl[2 * p + 1][1] = r3;
            }
            #pragma unroll
            for (int mt = 0; mt < 2; mt++)
                #pragma unroll
                for (int nt = 0; nt < 8; nt++) {
                    MMA16816(acc[mt][nt], ah[mt], bh[nt]);
                    MMA16816(acc[mt][nt], ah[mt], bl[nt]);
                    MMA16816(acc[mt][nt], al[mt], bh[nt]);
                }
        }

        if (kt + 1 < nT) {
            // split-store A into nxt, then drain cp.async before the sync
            #pragma unroll
            for (int i = 0; i < 4; i++) {
                int r = aRow0 + 32 * i;
                __nv_bfloat16* hp = (__nv_bfloat16*)(dsm + nxt + GA_HI + (r * ASTR + aCol) * 2);
                __nv_bfloat16* lp = (__nv_bfloat16*)(dsm + nxt + GA_LO + (r * ASTR + aCol) * 2);
                split2(hp,     lp,     pa[i].x, pa[i].y);
                split2(hp + 2, lp + 2, pa[i].z, pa[i].w);
            }
            CP_WAIT0();
        }
        __syncthreads();
    }

    // epilogue
    #pragma unroll
    for (int mt = 0; mt < 2; mt++) {
        #pragma unroll
        for (int nt = 0; nt < 8; nt++) {
            int row = blockM + wm * 32 + mt * 16 + (lane >> 2);
            int col = blockN + wn * 64 + nt * 8 + (lane & 3) * 2;
            float2 v0 = make_float2(acc[mt][nt][0], acc[mt][nt][1]);
            float2 v1 = make_float2(acc[mt][nt][2], acc[mt][nt][3]);
            if (BIAS) {
                float2 bv = *(const float2*)(bias + col);
                v0.x += bv.x; v0.y += bv.y;
                v1.x += bv.x; v1.y += bv.y;
            }
            if (RELU) {
                v0.x = fmaxf(v0.x, 0.f); v0.y = fmaxf(v0.y, 0.f);
                v1.x = fmaxf(v1.x, 0.f); v1.y = fmaxf(v1.y, 0.f);
            }
            if (row < M)     *(float2*)(C + (size_t)row * N + col) = v0;
            if (row + 8 < M) *(float2*)(C + (size_t)(row + 8) * N + col) = v1;
        }
    }
}

// ---------------- GEMV kernels ----------------
__global__ void gemv_kernel(const float* __restrict__ A, const float* __restrict__ v,
                            float* __restrict__ out, int M, int K)
{
    int row = blockIdx.x * (blockDim.x >> 5) + (threadIdx.x >> 5);
    int lane = threadIdx.x & 31;
    if (row >= M) return;
    const float4* a4 = (const float4*)(A + (size_t)row * K);
    const float4* v4 = (const float4*)v;
    int K4 = K >> 2;
    float sum = 0.f;
    for (int k = lane; k < K4; k += 32) {
        float4 a = a4[k], b = v4[k];
        sum += a.x * b.x + a.y * b.y + a.z * b.z + a.w * b.w;
    }
    #pragma unroll
    for (int o = 16; o; o >>= 1) sum += __shfl_down_sync(0xffffffffu, sum, o);
    if (lane == 0) out[row] = sum;
}

__global__ void gemv2_kernel(const float* __restrict__ A,
                             const float* __restrict__ va, const float* __restrict__ vb,
                             float* __restrict__ oa, float* __restrict__ ob, int M, int K)
{
    int row = blockIdx.x * (blockDim.x >> 5) + (threadIdx.x >> 5);
    int lane = threadIdx.x & 31;
    if (row >= M) return;
    const float4* a4 = (const float4*)(A + (size_t)row * K);
    const float4* va4 = (const float4*)va;
    const float4* vb4 = (const float4*)vb;
    int K4 = K >> 2;
    float sa = 0.f, sb = 0.f;
    for (int k = lane; k < K4; k += 32) {
        float4 a = a4[k], u = va4[k], t = vb4[k];
        sa += a.x * u.x + a.y * u.y + a.z * u.z + a.w * u.w;
        sb += a.x * t.x + a.y * t.y + a.z * t.z + a.w * t.w;
    }
    #pragma unroll
    for (int o = 16; o; o >>= 1) {
        sa += __shfl_down_sync(0xffffffffu, sa, o);
        sb += __shfl_down_sync(0xffffffffu, sb, o);
    }
    if (lane == 0) { oa[row] = sa; ob[row] = sb; }
}

// ---------------- CSR build kernels ----------------
__global__ void zero_int_kernel(int* __restrict__ p, int n)
{
    int i = blockIdx.x * blockDim.x + threadIdx.x;
    if (i < n) p[i] = 0;
}
__global__ void zero_f_kernel(float* __restrict__ p, int n)
{
    int i = blockIdx.x * blockDim.x + threadIdx.x;
    if (i < n) p[i] = 0.f;
}
__global__ void hist_kernel(const int* __restrict__ dst, int* __restrict__ cnt, int E)
{
    int i = blockIdx.x * blockDim.x + threadIdx.x;
    if (i < E) atomicAdd(&cnt[dst[i]], 1);
}
__global__ void scan1_kernel(const int* __restrict__ cnt, int* __restrict__ rowptr,
                             int* __restrict__ bsum, int n)
{
    __shared__ int sm[512];
    int t = threadIdx.x;
    int idx = blockIdx.x * 512 + t;
    int v = (idx < n) ? cnt[idx] : 0;
    sm[t] = v;
    __syncthreads();
    for (int o = 1; o < 512; o <<= 1) {
        int a = (t >= o) ? sm[t - o] : 0;
        __syncthreads();
        sm[t] += a;
        __syncthreads();
    }
    if (idx < n) rowptr[idx + 1] = sm[t];
    if (t == 511) bsum[blockIdx.x] = sm[511];
}
__global__ void scan2_kernel(const int* __restrict__ bsum, int* __restrict__ boff, int nb)
{
    __shared__ int sm[128];
    int t = threadIdx.x;
    int v = (t < nb) ? bsum[t] : 0;
    sm[t] = v;
    __syncthreads();
    for (int o = 1; o < 128; o <<= 1) {
        int a = (t >= o) ? sm[t - o] : 0;
        __syncthreads();
        sm[t] += a;
        __syncthreads();
    }
    boff[t] = sm[t] - v;     // exclusive
}
__global__ void scan3_kernel(int* __restrict__ rowptr, const int* __restrict__ boff, int n)
{
    int idx = blockIdx.x * 512 + threadIdx.x;
    if (idx < n) rowptr[idx + 1] += boff[blockIdx.x];
    if (idx == 0) rowptr[0] = 0;
}
__global__ void copy_int_kernel(int* __restrict__ d, const int* __restrict__ s, int n)
{
    int i = blockIdx.x * blockDim.x + threadIdx.x;
    if (i < n) d[i] = s[i];
}
__global__ void fill_kernel(const int* __restrict__ src, const int* __restrict__ dst,
                            int* __restrict__ pos, int* __restrict__ perm,
                            int* __restrict__ csrc, int E)
{
    int i = blockIdx.x * blockDim.x + threadIdx.x;
    if (i >= E) return;
    int slot = atomicAdd(&pos[dst[i]], 1);
    perm[i] = slot;
    csrc[slot] = src[i];
}

// ---------------- edge alpha, both lists in one kernel ----------------
__global__ void alpha_both_kernel(const int* __restrict__ src1, const int* __restrict__ dst1,
                                  const int* __restrict__ src2, const int* __restrict__ dst2,
                                  const float* __restrict__ as_, const float* __restrict__ ad_,
                                  const int* __restrict__ perm, float* __restrict__ cw,
                                  float* __restrict__ s, int E)
{
    int i = blockIdx.x * blockDim.x + threadIdx.x;
    if (i >= 2 * E) return;
    int l = (i >= E) ? 1 : 0;
    int j = i - l * E;
    const int* sp = l ? src2 : src1;
    const int* dp = l ? dst2 : dst1;
    int sn = sp[j], dn = dp[j];
    float v = as_[sn] + ad_[dn];
    v = v > 0.f ? v : 0.2f * v;          // leaky_relu, slope 0.2
    float ex = expf(v);
    cw[(size_t)l * EE + perm[(size_t)l * EE + j]] = ex;
    atomicAdd(&s[(size_t)l * NN + dn], ex);
}

// ---------------- per-node CSR aggregation (both lists), out = 2*bias + sums ----------------
// Column-sliced: covers blockDim.x*4 columns starting at colOff (C = row stride).
template<int C>
__global__ void agg_kernel(const int* __restrict__ rp1, const int* __restrict__ cs1,
                           const float* __restrict__ cw1, const float* __restrict__ s1,
                           const int* __restrict__ rp2, const int* __restrict__ cs2,
                           const float* __restrict__ cw2, const float* __restrict__ s2,
                           const float* __restrict__ h, const float* __restrict__ bias,
                           float* __restrict__ out, int colOff)
{
    int n = blockIdx.x;
    int c = colOff + threadIdx.x * 4;
    float4 b4 = *(const float4*)(bias + c);
    float4 acc = make_float4(2.f * b4.x, 2.f * b4.y, 2.f * b4.z, 2.f * b4.w);

    #pragma unroll
    for (int li = 0; li < 2; li++) {
        const int* rp = li ? rp2 : rp1;
        const int* cs = li ? cs2 : cs1;
        const float* cwp = li ? cw2 : cw1;
        const float* sp = li ? s2 : s1;

        int st = rp[n], en = rp[n + 1];
        float inv = 1.f / (sp[n] + 1e-16f);
        int j = st;
        for (; j + 4 <= en; j += 4) {
            int i0 = cs[j], i1 = cs[j + 1], i2 = cs[j + 2], i3 = cs[j + 3];
            float w0 = cwp[j] * inv, w1 = cwp[j + 1] * inv;
            float w2 = cwp[j + 2] * inv, w3 = cwp[j + 3] * inv;
            float4 h0 = *(const float4*)(h + (size_t)i0 * C + c);
            float4 h1 = *(const float4*)(h + (size_t)i1 * C + c);
            float4 h2 = *(const float4*)(h + (size_t)i2 * C + c);
            float4 h3 = *(const float4*)(h + (size_t)i3 * C + c);
            acc.x += w0 * h0.x + w1 * h1.x + w2 * h2.x + w3 * h3.x;
            acc.y += w0 * h0.y + w1 * h1.y + w2 * h2.y + w3 * h3.y;
            acc.z += w0 * h0.z + w1 * h1.z + w2 * h2.z + w3 * h3.z;
            acc.w += w0 * h0.w + w1 * h1.w + w2 * h2.w + w3 * h3.w;
        }
        for (; j < en; j++) {
            float wv = cwp[j] * inv;
            float4 hv = *(const float4*)(h + (size_t)cs[j] * C + c);
            acc.x += wv * hv.x; acc.y += wv * hv.y;
            acc.z += wv * hv.z; acc.w += wv * hv.w;
        }
    }
    *(float4*)(out + (size_t)n * C + c) = acc;
}

// ---------------- host orchestration ----------------
static void* symaddr(const void* s)
{
    void* p = nullptr;
    cudaGetSymbolAddress(&p, s);
    return p;
}

extern "C" void kernel_launch(void* const* d_in, const int* in_sizes, int n_in,
                              void* d_out, int out_size)
{
    (void)n_in; (void)out_size;
    const float* x   = (const float*)d_in[0];
    const int*   ei1 = (const int*)d_in[1];
    const int*   ei2 = (const int*)d_in[2];
    const float* W1s = (const float*)d_in[3];
    const float* W1d = (const float*)d_in[4];
    const float* a1s = (const float*)d_in[5];
    const float* a1d = (const float*)d_in[6];
    const float* b1  = (const float*)d_in[7];
    const float* Wl1 = (const float*)d_in[8];
    const float* bl1 = (const float*)d_in[9];
    const float* W2s = (const float*)d_in[10];
    const float* W2d = (const float*)d_in[11];
    const float* a2s = (const float*)d_in[12];
    const float* a2d = (const float*)d_in[13];
    const float* b2  = (const float*)d_in[14];
    const float* Wl2 = (const float*)d_in[15];
    const float* bl2 = (const float*)d_in[16];
    float* out = (float*)d_out;

    const int N = in_sizes[0] / DD;       // 50000
    const int E = in_sizes[1] / 2;        // 150000
    const int M0 = 25088;                 // row-split point (196 * 128)
    const int M1 = N - M0;                // 24912

    float* hsrc = (float*)symaddr(g_hsrc);
    float* agg  = (float*)symaddr(g_agg);
    float* hmid = (float*)symaddr(g_hmid);
    float* asrc = (float*)symaddr(g_asrc);
    float* adst = (float*)symaddr(g_adst);
    float* sbuf = (float*)symaddr(g_s);          // [4][NN]
    float* wa   = (float*)symaddr(g_wa);         // [2][DD]
    float* wb   = (float*)symaddr(g_wb);         // [2][DD]
    int* rowptr = (int*)symaddr(g_rowptr);
    int* pos    = (int*)symaddr(g_pos);
    int* perm   = (int*)symaddr(g_perm);
    int* csrc   = (int*)symaddr(g_csrc);
    float* cw   = (float*)symaddr(g_cw);
    int* bsum   = (int*)symaddr(g_bsum);
    int* boff   = (int*)symaddr(g_boff);
    __nv_bfloat16* whi = (__nv_bfloat16*)symaddr(g_whi);
    __nv_bfloat16* wlo = (__nv_bfloat16*)symaddr(g_wlo);

    const int NB = (NN + 511) / 512;
    const int* srcp1 = ei1;            const int* dstp1 = ei1 + E;
    const int* srcp2 = ei2;            const int* dstp2 = ei2 + E;

    static cudaStream_t sB = nullptr, sC = nullptr;
    static cudaEvent_t ev0, evB, evA1, evCa, evG1a, evL1a, evL1b, evG2A, evA2;
    if (!sB) {
        cudaStreamCreateWithFlags(&sB, cudaStreamNonBlocking);
        cudaStreamCreateWithFlags(&sC, cudaStreamNonBlocking);
        cudaEventCreateWithFlags(&ev0, cudaEventDisableTiming);
        cudaEventCreateWithFlags(&evB, cudaEventDisableTiming);
        cudaEventCreateWithFlags(&evA1, cudaEventDisableTiming);
        cudaEventCreateWithFlags(&evCa, cudaEventDisableTiming);
        cudaEventCreateWithFlags(&evG1a, cudaEventDisableTiming);
        cudaEventCreateWithFlags(&evL1a, cudaEventDisableTiming);
        cudaEventCreateWithFlags(&evL1b, cudaEventDisableTiming);
        cudaEventCreateWithFlags(&evG2A, cudaEventDisableTiming);
        cudaEventCreateWithFlags(&evA2, cudaEventDisableTiming);
        cudaFuncSetAttribute(mma_gemm_kernel<false, false>,
                             cudaFuncAttributeMaxDynamicSharedMemorySize, GDSM);
        cudaFuncSetAttribute(mma_gemm_kernel<true, true>,
                             cudaFuncAttributeMaxDynamicSharedMemorySize, GDSM);
        cudaFuncSetAttribute(mma_gemm_kernel<true, false>,
                             cudaFuncAttributeMaxDynamicSharedMemorySize, GDSM);
    }

    dim3 gH2(2, (N + 127) / 128);             // 256-col half (512-col GEMM), full rows
    dim3 gL1a(4, M0 / 128);                   // lin1 rows [0,M0)
    dim3 gL1b(4, (M1 + 127) / 128);           // lin1 rows [M0,N)
    dim3 gG2a(2, M0 / 128);                   // GEMM2 rows [0,M0), full 256 cols
    dim3 gG2b(2, (M1 + 127) / 128);           // GEMM2 rows [M0,N)
    dim3 gO(2, (N + 127) / 128);              // 256-col full-row GEMM

    // ===== fork =====
    cudaEventRecord(ev0, 0);
    cudaStreamWaitEvent(sB, ev0, 0);
    cudaStreamWaitEvent(sC, ev0, 0);

    // Submissions 1-3, then GEMM1a as the 4th launch (ncu profile targeting).
    wsplit_kernel<<<(DD * HH / 4 + 255) / 256, 256>>>(W1s, whi + WO1, wlo + WO1, DD * HH / 4);
    wsplit_kernel<<<(HH * HH / 4 + 255) / 256, 256, 0, sB>>>(Wl1, whi + WO2, wlo + WO2, HH * HH / 4);
    wsplit_kernel<<<(HH * OC / 4 + 255) / 256, 256, 0, sB>>>(W2s, whi + WO3, wlo + WO3, HH * OC / 4);
    // GEMM1a: cols [0,256)
    mma_gemm_kernel<false, false><<<gH2, 256, GDSM>>>(x, whi + WO1, wlo + WO1, nullptr, hsrc, N, HH, DD);
    cudaEventRecord(evG1a, 0);
    // GEMM1b: cols [256,512)
    mma_gemm_kernel<false, false><<<gH2, 256, GDSM>>>(x, whi + WO1 + 256, wlo + WO1 + 256, nullptr,
                                                      hsrc + 256, N, HH, DD);

    // ----- stream B: remaining setup (CSR build etc.) -----
    wsplit_kernel<<<(OC * OC / 4 + 255) / 256, 256, 0, sB>>>(Wl2, whi + WO4, wlo + WO4, OC * OC / 4);
    gemv_kernel<<<(HH + 7) / 8, 256, 0, sB>>>(W2s, a2s, wa + DD, HH, OC);
    gemv_kernel<<<(HH + 7) / 8, 256, 0, sB>>>(W2d, a2d, wb + DD, HH, OC);
    zero_f_kernel<<<(4 * NN + 255) / 256, 256, 0, sB>>>(sbuf, 4 * NN);
    zero_int_kernel<<<(2 * NN + 255) / 256, 256, 0, sB>>>(pos, 2 * NN);
    for (int l = 0; l < 2; l++) {
        const int* dstp = l ? dstp2 : dstp1;
        const int* srcp = l ? srcp2 : srcp1;
        int* cnt_l = pos + l * NN;
        int* rp_l  = rowptr + l * (NN + 1);
        hist_kernel<<<(E + 255) / 256, 256, 0, sB>>>(dstp, cnt_l, E);
        scan1_kernel<<<NB, 512, 0, sB>>>(cnt_l, rp_l, bsum + l * 128, N);
        scan2_kernel<<<1, 128, 0, sB>>>(bsum + l * 128, boff + l * 128, NB);
        scan3_kernel<<<NB, 512, 0, sB>>>(rp_l, boff + l * 128, N);
        copy_int_kernel<<<(NN + 255) / 256, 256, 0, sB>>>(cnt_l, rp_l, N);
        fill_kernel<<<(E + 255) / 256, 256, 0, sB>>>(srcp, dstp, cnt_l, perm + l * EE, csrc + l * EE, E);
    }
    cudaEventRecord(evB, sB);

    // ----- stream C: L1 weight gemvs + node alphas + L1 edge alphas + agg1a -----
    gemv_kernel<<<(DD + 7) / 8, 256, 0, sC>>>(W1s, a1s, wa, DD, HH);
    gemv_kernel<<<(DD + 7) / 8, 256, 0, sC>>>(W1d, a1d, wb, DD, HH);
    gemv2_kernel<<<(N + 7) / 8, 256, 0, sC>>>(x, wa, wb, asrc, adst, N, DD);
    cudaStreamWaitEvent(sC, evB, 0);
    alpha_both_kernel<<<(2 * E + 255) / 256, 256, 0, sC>>>(srcp1, dstp1, srcp2, dstp2,
                                                           asrc, adst, perm, cw, sbuf, E);
    cudaEventRecord(evA1, sC);
    // agg1a (cols 0-255) overlaps GEMM1b on default
    cudaStreamWaitEvent(sC, evG1a, 0);
    agg_kernel<HH><<<N, 64, 0, sC>>>(rowptr, csrc, cw, sbuf,
                                     rowptr + (NN + 1), csrc + EE, cw + EE, sbuf + NN,
                                     hsrc, b1, agg, 0);
    cudaEventRecord(evCa, sC);

    // ----- default stream: critical chain -----
    cudaStreamWaitEvent(0, evA1, 0);
    agg_kernel<HH><<<N, 64>>>(rowptr, csrc, cw, sbuf,
                              rowptr + (NN + 1), csrc + EE, cw + EE, sbuf + NN,
                              hsrc, b1, agg, 256);
    cudaStreamWaitEvent(0, evCa, 0);

    // lin1 row-split: half A then half B
    mma_gemm_kernel<true, true><<<gL1a, 256, GDSM>>>(agg, whi + WO2, wlo + WO2, bl1, hmid, M0, HH, HH);
    cudaEventRecord(evL1a, 0);
    mma_gemm_kernel<true, true><<<gL1b, 256, GDSM>>>(agg + (size_t)M0 * HH, whi + WO2, wlo + WO2, bl1,
                                                     hmid + (size_t)M0 * HH, M1, HH, HH);
    cudaEventRecord(evL1b, 0);

    // stream B: GEMM2a (rows 0..M0) overlaps lin1b on default
    cudaStreamWaitEvent(sB, evL1a, 0);
    mma_gemm_kernel<false, false><<<gG2a, 256, GDSM>>>(hmid, whi + WO3, wlo + WO3, nullptr,
                                                       hsrc, M0, OC, HH);
    cudaEventRecord(evG2A, sB);

    // stream C: layer-2 node alphas per row half, then edge alphas
    cudaStreamWaitEvent(sC, evL1a, 0);
    gemv2_kernel<<<(M0 + 7) / 8, 256, 0, sC>>>(hmid, wa + DD, wb + DD, asrc, adst, M0, HH);
    cudaStreamWaitEvent(sC, evL1b, 0);
    gemv2_kernel<<<(M1 + 7) / 8, 256, 0, sC>>>(hmid + (size_t)M0 * HH, wa + DD, wb + DD,
                                               asrc + M0, adst + M0, M1, HH);
    alpha_both_kernel<<<(2 * E + 255) / 256, 256, 0, sC>>>(srcp1, dstp1, srcp2, dstp2,
                                                           asrc, adst, perm, cw, sbuf + 2 * NN, E);
    cudaEventRecord(evA2, sC);

    // default: GEMM2b (rows M0..N)
    mma_gemm_kernel<false, false><<<gG2b, 256, GDSM>>>(hmid + (size_t)M0 * HH, whi + WO3, wlo + WO3,
                                                       nullptr, hsrc + (size_t)M0 * OC, M1, OC, HH);

    // join: agg2 needs full hsrc (GEMM2a + GEMM2b) and alpha2
    cudaStreamWaitEvent(0, evG2A, 0);
    cudaStreamWaitEvent(0, evA2, 0);
    agg_kernel<OC><<<N, 64>>>(rowptr, csrc, cw, sbuf + 2 * NN,
                              rowptr + (NN + 1), csrc + EE, cw + EE, sbuf + 3 * NN,
                              hsrc, b2, agg, 0);
    // lin2 full
    mma_gemm_kernel<true, false><<<gO, 256, GDSM>>>(agg, whi + WO4, wlo + WO4, bl2, out, N, OC, OC);
}